// round 6
// baseline (speedup 1.0000x reference)
#include <cuda_runtime.h>
#include <cstdint>

#define NB 4
#define NT 2048
#define NC 1024
#define NH 16
#define ND 64

// Scratch. g_q, g_k: [B,H,T,D]. g_v: TRANSPOSED [B,H,D,T]. All tf32-pre-rounded.
__device__ float g_q[NB*NH*NT*ND];
__device__ float g_k[NB*NH*NT*ND];
__device__ float g_v[NB*NH*NT*ND];

__device__ __forceinline__ float tf32r(float x) {
    uint32_t u;
    asm("cvt.rna.tf32.f32 %0, %1;" : "=r"(u) : "f"(x));
    return __uint_as_float(u);
}
__device__ __forceinline__ uint32_t fau(float x) { return __float_as_uint(x); }

__device__ __forceinline__ void mma_tf32(float d[4], const uint32_t a[4],
                                         const uint32_t b[2]) {
    asm volatile(
        "mma.sync.aligned.m16n8k8.row.col.f32.tf32.tf32.f32 "
        "{%0,%1,%2,%3}, {%4,%5,%6,%7}, {%8,%9}, {%0,%1,%2,%3};"
        : "+f"(d[0]), "+f"(d[1]), "+f"(d[2]), "+f"(d[3])
        : "r"(a[0]), "r"(a[1]), "r"(a[2]), "r"(a[3]), "r"(b[0]), "r"(b[1]));
}

// ---------------------------------------------------------------------------
// QKV projection, tf32 mma, split-activation compensation.
// R6: pair-column smem layout (cols [0,4,1,5,2,6,3,7] per 8-group) ->
// all fragment loads are LDS.64. Epilogue pre-rounds to tf32; V transposed.
// grid = (NC/128, (NB*NT)/128, 3), block = 256 (2 m-warp x 4 n-warp).
// ---------------------------------------------------------------------------
#define AST 40   // row stride: frag LDS.64 banks (8g+2c) -> conflict-free

__global__ __launch_bounds__(256, 2) void qkv_mma(
    const float* __restrict__ x,
    const float* __restrict__ Wq, const float* __restrict__ bq,
    const float* __restrict__ Wk, const float* __restrict__ bk,
    const float* __restrict__ Wv, const float* __restrict__ bv)
{
    extern __shared__ float smq[];
    float* Ah = smq;               // [128][AST] x_hi (pair-column)
    float* Al = smq + 128*AST;     // [128][AST] x_lo
    float* Bs = smq + 2*128*AST;   // [128][AST] W

    const int z = blockIdx.z;
    const float* __restrict__ W    = (z == 0) ? Wq : ((z == 1) ? Wk : Wv);
    const float* __restrict__ bias = (z == 0) ? bq : ((z == 1) ? bk : bv);
    float* __restrict__ dst        = (z == 0) ? g_q : ((z == 1) ? g_k : g_v);
    const float scale = (z == 0) ? 0.125f : 1.0f;

    const int tid  = threadIdx.x;
    const int warp = tid >> 5;
    const int lane = tid & 31;
    const int g    = lane >> 2;
    const int c    = lane & 3;
    const int mw   = (warp & 1) * 64;
    const int nw   = (warp >> 1) * 32;

    const int m0 = blockIdx.y * 128;
    const int n0 = blockIdx.x * 128;

    // staging: 128 rows x 4 col-groups(8); 64 rows per pass, 2 passes
    const int srow = tid >> 2;          // 0..63
    const int sgb  = (tid & 3) * 8;     // col-group base

    float acc[4][4][4] = {};

    for (int k0 = 0; k0 < NC; k0 += 32) {
        float4 xa[2][2], wa[2][2];
        #pragma unroll
        for (int i = 0; i < 2; i++) {
            const int r = srow + 64*i;
            xa[i][0] = *(const float4*)&x[(m0 + r)*NC + k0 + sgb];
            xa[i][1] = *(const float4*)&x[(m0 + r)*NC + k0 + sgb + 4];
            wa[i][0] = *(const float4*)&W[(n0 + r)*NC + k0 + sgb];
            wa[i][1] = *(const float4*)&W[(n0 + r)*NC + k0 + sgb + 4];
        }
        __syncthreads();
        #pragma unroll
        for (int i = 0; i < 2; i++) {
            const int r = srow + 64*i;
            float h[8], l[8];
            const float xv[8] = {xa[i][0].x, xa[i][0].y, xa[i][0].z, xa[i][0].w,
                                 xa[i][1].x, xa[i][1].y, xa[i][1].z, xa[i][1].w};
            #pragma unroll
            for (int j = 0; j < 8; j++) {
                h[j] = tf32r(xv[j]);
                l[j] = tf32r(xv[j] - h[j]);
            }
            // pair-column interleave: mem order <- cols [0,4,1,5,2,6,3,7]
            *(float4*)&Ah[r*AST + sgb]     = make_float4(h[0], h[4], h[1], h[5]);
            *(float4*)&Ah[r*AST + sgb + 4] = make_float4(h[2], h[6], h[3], h[7]);
            *(float4*)&Al[r*AST + sgb]     = make_float4(l[0], l[4], l[1], l[5]);
            *(float4*)&Al[r*AST + sgb + 4] = make_float4(l[2], l[6], l[3], l[7]);
            const float wv2[8] = {wa[i][0].x, wa[i][0].y, wa[i][0].z, wa[i][0].w,
                                  wa[i][1].x, wa[i][1].y, wa[i][1].z, wa[i][1].w};
            float wt[8];
            #pragma unroll
            for (int j = 0; j < 8; j++) wt[j] = tf32r(wv2[j]);
            *(float4*)&Bs[r*AST + sgb]     = make_float4(wt[0], wt[4], wt[1], wt[5]);
            *(float4*)&Bs[r*AST + sgb + 4] = make_float4(wt[2], wt[6], wt[3], wt[7]);
        }
        __syncthreads();

        #pragma unroll
        for (int kc = 0; kc < 4; kc++) {
            const int k = kc * 8;
            float2 bf[4];
            #pragma unroll
            for (int nt = 0; nt < 4; nt++)
                bf[nt] = *(const float2*)&Bs[(nw + nt*8 + g)*AST + k + 2*c];
            #pragma unroll
            for (int mt = 0; mt < 4; mt++) {
                float2 h0 = *(const float2*)&Ah[(mw + mt*16 + g    )*AST + k + 2*c];
                float2 h1 = *(const float2*)&Ah[(mw + mt*16 + g + 8)*AST + k + 2*c];
                float2 l0 = *(const float2*)&Al[(mw + mt*16 + g    )*AST + k + 2*c];
                float2 l1 = *(const float2*)&Al[(mw + mt*16 + g + 8)*AST + k + 2*c];
                uint32_t ah[4] = {fau(h0.x), fau(h1.x), fau(h0.y), fau(h1.y)};
                uint32_t al[4] = {fau(l0.x), fau(l1.x), fau(l0.y), fau(l1.y)};
                #pragma unroll
                for (int nt = 0; nt < 4; nt++) {
                    uint32_t bb[2] = {fau(bf[nt].x), fau(bf[nt].y)};
                    mma_tf32(acc[mt][nt], ah, bb);
                    mma_tf32(acc[mt][nt], al, bb);
                }
            }
        }
    }

    // Epilogue: bias + scale, tf32 pre-round, scatter.
    // z<2: [B,H,T,D] float2; z==2 (V): transposed [B,H,D,T] scalar stores.
    #pragma unroll
    for (int nt = 0; nt < 4; nt++) {
        const int col = n0 + nw + nt*8 + 2*c;
        float2 b2 = *(const float2*)&bias[col];
        const int h  = col >> 6;
        const int cc = col & 63;
        #pragma unroll
        for (int mt = 0; mt < 4; mt++) {
            #pragma unroll
            for (int rh = 0; rh < 2; rh++) {
                const int m = m0 + mw + mt*16 + g + rh*8;
                const int b = m >> 11;
                const int t = m & (NT - 1);
                const float vx = tf32r((acc[mt][nt][rh*2 + 0] + b2.x) * scale);
                const float vy = tf32r((acc[mt][nt][rh*2 + 1] + b2.y) * scale);
                if (z == 2) {
                    dst[((b*NH + h)*ND + cc    )*NT + t] = vx;
                    dst[((b*NH + h)*ND + cc + 1)*NT + t] = vy;
                } else {
                    *(float2*)&dst[((b*NH + h)*NT + t)*ND + cc] =
                        make_float2(vx, vy);
                }
            }
        }
    }
}

// ---------------------------------------------------------------------------
// Flash attention, tf32 mma. 4 warps x 32 q-rows; pair-column Qs/Ks/Vt
// (all S and PV b/a loads vectorized LDS.64 except P a-frags).
// grid = (NT/128, NB*NH), block = 128.
// ---------------------------------------------------------------------------
#define S72 72   // Qs/Ks/Vt/Ps stride: frag banks (8g+2c)/(8g+c) conflict-free

__global__ __launch_bounds__(128) void attn_kernel(
    const int* __restrict__ mask, float* __restrict__ out)
{
    extern __shared__ float sm[];
    float* Qs    = sm;                    // [128][72] pair-column  9216
    float* Ps    = sm + 9216;             // [128][72] natural      9216
    float* Ks    = sm + 18432;            // [64][72]  pair-column  4608
    float* Vt    = sm + 23040;            // [64 d][72 key-paircol] 4608
    float* maskf = sm + 27648;            // [64]
    // total 27712 floats = 110848 B

    const int tid  = threadIdx.x;
    const int warp = tid >> 5;
    const int lane = tid & 31;
    const int g    = lane >> 2;
    const int c    = lane & 3;
    const int wr   = warp * 32;

    const int bh = blockIdx.y;
    const int b  = bh >> 4;
    const int h  = bh & 15;
    const int q0 = blockIdx.x * 128;

    const float* __restrict__ qb  = g_q + (bh*NT + q0) * ND;
    const float* __restrict__ kb  = g_k + bh*NT*ND;
    const float* __restrict__ vbT = g_v + bh*ND*NT;   // [D][T]
    const int*   __restrict__ mb  = mask + b*NT;

    // Stage Q once, pair-column (values already tf32)
    #pragma unroll
    for (int i = 0; i < 8; i++) {
        const int slot = tid + 128*i;
        const int r = slot >> 3, gb = (slot & 7) * 8;
        float4 va = *(const float4*)&qb[r*ND + gb];
        float4 vb = *(const float4*)&qb[r*ND + gb + 4];
        *(float4*)&Qs[r*S72 + gb]     = make_float4(va.x, vb.x, va.y, vb.y);
        *(float4*)&Qs[r*S72 + gb + 4] = make_float4(va.z, vb.z, va.w, vb.w);
    }

    float o[2][8][4] = {};
    float m_run[2][2] = {{-1e30f,-1e30f},{-1e30f,-1e30f}};
    float l_run[2][2] = {{0.f,0.f},{0.f,0.f}};

    for (int k0 = 0; k0 < NT; k0 += 64) {
        // prefetch K to registers (latency overlapped with prior compute)
        float4 ka[4][2];
        #pragma unroll
        for (int i = 0; i < 4; i++) {
            const int slot = tid + 128*i;
            const int r = slot >> 3, gb = (slot & 7) * 8;
            ka[i][0] = *(const float4*)&kb[(k0 + r)*ND + gb];
            ka[i][1] = *(const float4*)&kb[(k0 + r)*ND + gb + 4];
        }
        __syncthreads();   // prior chunk's smem reads complete
        #pragma unroll
        for (int i = 0; i < 4; i++) {
            const int slot = tid + 128*i;
            const int r = slot >> 3, gb = (slot & 7) * 8;
            *(float4*)&Ks[r*S72 + gb] =
                make_float4(ka[i][0].x, ka[i][1].x, ka[i][0].y, ka[i][1].y);
            *(float4*)&Ks[r*S72 + gb + 4] =
                make_float4(ka[i][0].z, ka[i][1].z, ka[i][0].w, ka[i][1].w);
            // V from transposed gmem: row r = d, cols = keys (pair-column)
            float4 u0 = *(const float4*)&vbT[r*NT + k0 + gb];
            float4 u1 = *(const float4*)&vbT[r*NT + k0 + gb + 4];
            *(float4*)&Vt[r*S72 + gb] =
                make_float4(u0.x, u1.x, u0.y, u1.y);
            *(float4*)&Vt[r*S72 + gb + 4] =
                make_float4(u0.z, u1.z, u0.w, u1.w);
        }
        if (tid < 64) maskf[tid] = (mb[k0 + tid] > 0) ? 0.0f : -1e30f;
        __syncthreads();

        // ---- S = Q @ K^T ----
        float s[2][8][4] = {};
        #pragma unroll
        for (int kt = 0; kt < 8; kt++) {
            const int k = kt*8;
            uint32_t a[2][4];
            #pragma unroll
            for (int mt = 0; mt < 2; mt++) {
                float2 q0f = *(const float2*)&Qs[(wr + mt*16 + g    )*S72 + k + 2*c];
                float2 q1f = *(const float2*)&Qs[(wr + mt*16 + g + 8)*S72 + k + 2*c];
                a[mt][0] = fau(q0f.x); a[mt][1] = fau(q1f.x);
                a[mt][2] = fau(q0f.y); a[mt][3] = fau(q1f.y);
            }
            #pragma unroll
            for (int nt = 0; nt < 8; nt++) {
                float2 kf = *(const float2*)&Ks[(nt*8 + g)*S72 + k + 2*c];
                uint32_t bb[2] = {fau(kf.x), fau(kf.y)};
                mma_tf32(s[0][nt], a[0], bb);
                mma_tf32(s[1][nt], a[1], bb);
            }
        }

        // additive mask
        #pragma unroll
        for (int nt = 0; nt < 8; nt++) {
            float2 mf = *(const float2*)&maskf[nt*8 + 2*c];
            #pragma unroll
            for (int mt = 0; mt < 2; mt++) {
                s[mt][nt][0] += mf.x; s[mt][nt][1] += mf.y;
                s[mt][nt][2] += mf.x; s[mt][nt][3] += mf.y;
            }
        }

        // ---- online softmax ----
        #pragma unroll
        for (int mt = 0; mt < 2; mt++) {
            float alpha[2];
            #pragma unroll
            for (int rh = 0; rh < 2; rh++) {
                float rm = -1e30f;
                #pragma unroll
                for (int nt = 0; nt < 8; nt++)
                    rm = fmaxf(rm, fmaxf(s[mt][nt][rh*2], s[mt][nt][rh*2+1]));
                rm = fmaxf(rm, __shfl_xor_sync(0xffffffffu, rm, 1));
                rm = fmaxf(rm, __shfl_xor_sync(0xffffffffu, rm, 2));
                float mnew = fmaxf(m_run[mt][rh], rm);
                alpha[rh] = __expf(m_run[mt][rh] - mnew);
                m_run[mt][rh] = mnew;
                float rs = 0.f;
                #pragma unroll
                for (int nt = 0; nt < 8; nt++) {
                    float p0 = __expf(s[mt][nt][rh*2]   - mnew);
                    float p1 = __expf(s[mt][nt][rh*2+1] - mnew);
                    s[mt][nt][rh*2] = p0; s[mt][nt][rh*2+1] = p1;
                    rs += p0 + p1;
                }
                rs += __shfl_xor_sync(0xffffffffu, rs, 1);
                rs += __shfl_xor_sync(0xffffffffu, rs, 2);
                l_run[mt][rh] = l_run[mt][rh]*alpha[rh] + rs;
            }
            #pragma unroll
            for (int nt = 0; nt < 8; nt++) {
                o[mt][nt][0] *= alpha[0]; o[mt][nt][1] *= alpha[0];
                o[mt][nt][2] *= alpha[1]; o[mt][nt][3] *= alpha[1];
            }
            #pragma unroll
            for (int nt = 0; nt < 8; nt++) {
                float2 lo = make_float2(tf32r(s[mt][nt][0]), tf32r(s[mt][nt][1]));
                float2 hi = make_float2(tf32r(s[mt][nt][2]), tf32r(s[mt][nt][3]));
                *(float2*)&Ps[(wr + mt*16 + g    )*S72 + nt*8 + 2*c] = lo;
                *(float2*)&Ps[(wr + mt*16 + g + 8)*S72 + nt*8 + 2*c] = hi;
            }
        }
        __syncwarp();

        // ---- O += P @ V ----
        #pragma unroll
        for (int kt = 0; kt < 8; kt++) {
            const int k = kt*8;
            uint32_t a[2][4];
            #pragma unroll
            for (int mt = 0; mt < 2; mt++) {
                const float* pr = &Ps[(wr + mt*16 + g)*S72 + k];
                a[mt][0] = fau(pr[c]);       a[mt][1] = fau(pr[8*S72 + c]);
                a[mt][2] = fau(pr[c + 4]);   a[mt][3] = fau(pr[8*S72 + c + 4]);
            }
            #pragma unroll
            for (int nt = 0; nt < 8; nt++) {
                float2 vf = *(const float2*)&Vt[(nt*8 + g)*S72 + k + 2*c];
                uint32_t bb[2] = {fau(vf.x), fau(vf.y)};
                mma_tf32(o[0][nt], a[0], bb);
                mma_tf32(o[1][nt], a[1], bb);
            }
        }
    }

    // epilogue
    #pragma unroll
    for (int mt = 0; mt < 2; mt++) {
        const float inv0 = 1.0f / l_run[mt][0];
        const float inv1 = 1.0f / l_run[mt][1];
        const int t0 = q0 + wr + mt*16 + g;
        float* ob0 = out + (b*NT + t0    )*NC + h*ND;
        float* ob1 = out + (b*NT + t0 + 8)*NC + h*ND;
        #pragma unroll
        for (int nt = 0; nt < 8; nt++) {
            *(float2*)&ob0[nt*8 + 2*c] =
                make_float2(o[mt][nt][0]*inv0, o[mt][nt][1]*inv0);
            *(float2*)&ob1[nt*8 + 2*c] =
                make_float2(o[mt][nt][2]*inv1, o[mt][nt][3]*inv1);
        }
    }
}

// ---------------------------------------------------------------------------
extern "C" void kernel_launch(void* const* d_in, const int* in_sizes, int n_in,
                              void* d_out, int out_size)
{
    const float* x  = (const float*)d_in[0];
    const int* mask = (const int*)  d_in[1];
    const float* Wq = (const float*)d_in[2];
    const float* bq = (const float*)d_in[3];
    const float* Wk = (const float*)d_in[4];
    const float* bk = (const float*)d_in[5];
    const float* Wv = (const float*)d_in[6];
    const float* bv = (const float*)d_in[7];
    float* out = (float*)d_out;

    const int qkv_smem = 3 * 128 * AST * 4;   // 61440
    cudaFuncSetAttribute(qkv_mma,
                         cudaFuncAttributeMaxDynamicSharedMemorySize, qkv_smem);
    qkv_mma<<<dim3(NC/128, (NB*NT)/128, 3), 256, qkv_smem>>>(
        x, Wq, bq, Wk, bk, Wv, bv);

    const int attn_smem = 27712 * 4;          // 110848
    cudaFuncSetAttribute(attn_kernel,
                         cudaFuncAttributeMaxDynamicSharedMemorySize, attn_smem);
    attn_kernel<<<dim3(NT/128, NB*NH), 128, attn_smem>>>(mask, out);
}

// round 7
// speedup vs baseline: 1.4799x; 1.4799x over previous
#include <cuda_runtime.h>
#include <cuda_fp16.h>
#include <cstdint>

#define NB 4
#define NT 2048
#define NC 1024
#define NH 16
#define ND 64

// Scratch: Q,K,V in [B,H,T,D] layout, fp16 (rounded once in qkv epilogue).
__device__ __half g_q[NB*NH*NT*ND];
__device__ __half g_k[NB*NH*NT*ND];
__device__ __half g_v[NB*NH*NT*ND];

__device__ __forceinline__ float tf32r(float x) {
    uint32_t u;
    asm("cvt.rna.tf32.f32 %0, %1;" : "=r"(u) : "f"(x));
    return __uint_as_float(u);
}
__device__ __forceinline__ uint32_t fau(float x) { return __float_as_uint(x); }

__device__ __forceinline__ void mma_tf32(float d[4], const uint32_t a[4],
                                         const uint32_t b[2]) {
    asm volatile(
        "mma.sync.aligned.m16n8k8.row.col.f32.tf32.tf32.f32 "
        "{%0,%1,%2,%3}, {%4,%5,%6,%7}, {%8,%9}, {%0,%1,%2,%3};"
        : "+f"(d[0]), "+f"(d[1]), "+f"(d[2]), "+f"(d[3])
        : "r"(a[0]), "r"(a[1]), "r"(a[2]), "r"(a[3]), "r"(b[0]), "r"(b[1]));
}

__device__ __forceinline__ void mma_f16(float d[4], const uint32_t a[4],
                                        const uint32_t b[2]) {
    asm volatile(
        "mma.sync.aligned.m16n8k16.row.col.f32.f16.f16.f32 "
        "{%0,%1,%2,%3}, {%4,%5,%6,%7}, {%8,%9}, {%0,%1,%2,%3};"
        : "+f"(d[0]), "+f"(d[1]), "+f"(d[2]), "+f"(d[3])
        : "r"(a[0]), "r"(a[1]), "r"(a[2]), "r"(a[3]), "r"(b[0]), "r"(b[1]));
}

// ---------------------------------------------------------------------------
// QKV projection: tf32 mma + split-activation compensation (R5 mainloop,
// proven). Epilogue now emits fp16 (the only rounding of q/k/v).
// grid = (NC/128, (NB*NT)/128, 3), block = 256.
// ---------------------------------------------------------------------------
#define AST 36

__global__ __launch_bounds__(256) void qkv_mma(
    const float* __restrict__ x,
    const float* __restrict__ Wq, const float* __restrict__ bq,
    const float* __restrict__ Wk, const float* __restrict__ bk,
    const float* __restrict__ Wv, const float* __restrict__ bv)
{
    extern __shared__ float smq[];
    float* Ah = smq;
    float* Al = smq + 128*AST;
    float* Bs = smq + 2*128*AST;

    const int z = blockIdx.z;
    const float* __restrict__ W    = (z == 0) ? Wq : ((z == 1) ? Wk : Wv);
    const float* __restrict__ bias = (z == 0) ? bq : ((z == 1) ? bk : bv);
    __half* __restrict__ dst       = (z == 0) ? g_q : ((z == 1) ? g_k : g_v);
    const float scale = (z == 0) ? 0.125f : 1.0f;

    const int tid  = threadIdx.x;
    const int warp = tid >> 5;
    const int lane = tid & 31;
    const int g    = lane >> 2;
    const int c    = lane & 3;
    const int mw   = (warp & 1) * 64;
    const int nw   = (warp >> 1) * 32;

    const int m0 = blockIdx.y * 128;
    const int n0 = blockIdx.x * 128;

    const int srow = tid >> 3;
    const int sc4  = (tid & 7) * 4;

    float acc[4][4][4] = {};

    for (int k0 = 0; k0 < NC; k0 += 32) {
        float4 xv[4], wv[4];
        #pragma unroll
        for (int p = 0; p < 4; p++) {
            xv[p] = *(const float4*)&x[(m0 + srow + 32*p)*NC + k0 + sc4];
            wv[p] = *(const float4*)&W[(n0 + srow + 32*p)*NC + k0 + sc4];
        }
        __syncthreads();
        #pragma unroll
        for (int p = 0; p < 4; p++) {
            const int r = srow + 32*p;
            float4 hi = make_float4(tf32r(xv[p].x), tf32r(xv[p].y),
                                    tf32r(xv[p].z), tf32r(xv[p].w));
            float4 lo = make_float4(tf32r(xv[p].x - hi.x), tf32r(xv[p].y - hi.y),
                                    tf32r(xv[p].z - hi.z), tf32r(xv[p].w - hi.w));
            *(float4*)&Ah[r*AST + sc4] = hi;
            *(float4*)&Al[r*AST + sc4] = lo;
            *(float4*)&Bs[r*AST + sc4] =
                make_float4(tf32r(wv[p].x), tf32r(wv[p].y),
                            tf32r(wv[p].z), tf32r(wv[p].w));
        }
        __syncthreads();

        #pragma unroll
        for (int kc = 0; kc < 4; kc++) {
            const int k = kc * 8;
            uint32_t bf[4][2];
            #pragma unroll
            for (int nt = 0; nt < 4; nt++) {
                const float* br = &Bs[(nw + nt*8 + g)*AST + k];
                bf[nt][0] = fau(br[c]);
                bf[nt][1] = fau(br[c + 4]);
            }
            #pragma unroll
            for (int mt = 0; mt < 4; mt++) {
                const float* ar = &Ah[(mw + mt*16 + g)*AST + k];
                const float* lr = &Al[(mw + mt*16 + g)*AST + k];
                uint32_t ah[4] = {fau(ar[c]), fau(ar[8*AST + c]),
                                  fau(ar[c + 4]), fau(ar[8*AST + c + 4])};
                uint32_t al[4] = {fau(lr[c]), fau(lr[8*AST + c]),
                                  fau(lr[c + 4]), fau(lr[8*AST + c + 4])};
                #pragma unroll
                for (int nt = 0; nt < 4; nt++) {
                    mma_tf32(acc[mt][nt], ah, bf[nt]);
                    mma_tf32(acc[mt][nt], al, bf[nt]);
                }
            }
        }
    }

    // Epilogue: bias + scale, round to fp16, scatter to [B,H,T,D]
    #pragma unroll
    for (int nt = 0; nt < 4; nt++) {
        const int col = n0 + nw + nt*8 + 2*c;
        float2 b2 = *(const float2*)&bias[col];
        const int h  = col >> 6;
        const int cc = col & 63;
        #pragma unroll
        for (int mt = 0; mt < 4; mt++) {
            #pragma unroll
            for (int rh = 0; rh < 2; rh++) {
                const int m = m0 + mw + mt*16 + g + rh*8;
                const int b = m >> 11;
                const int t = m & (NT - 1);
                const float vx = (acc[mt][nt][rh*2 + 0] + b2.x) * scale;
                const float vy = (acc[mt][nt][rh*2 + 1] + b2.y) * scale;
                *(__half2*)&dst[((b*NH + h)*NT + t)*ND + cc] =
                    __floats2half2_rn(vx, vy);
            }
        }
    }
}

// ---------------------------------------------------------------------------
// Flash attention on fp16 tensor cores (m16n8k16, fp32 accum).
// 4 warps x 32 q-rows. Q/K/P a,b frags via half2 LDS; V b-frags via
// ldmatrix.x4.trans (HW transpose). grid = (NT/128, NB*NH), block = 128.
// ---------------------------------------------------------------------------
#define RS 72   // row stride in halves (36 words): frag banks 4g+c conflict-free

__global__ __launch_bounds__(128) void attn_kernel(
    const int* __restrict__ mask, float* __restrict__ out)
{
    extern __shared__ __align__(16) char smraw[];
    __half* Qsh = (__half*)smraw;          // [128][RS]
    __half* Psh = Qsh + 128*RS;            // [128][RS]
    __half* Ksh = Psh + 128*RS;            // [64][RS]
    __half* Vsh = Ksh + 64*RS;             // [64][RS]
    float*  maskf = (float*)(Vsh + 64*RS); // [64]
    // total 27648 halves + 64 floats = 55552 B

    const int tid  = threadIdx.x;
    const int warp = tid >> 5;
    const int lane = tid & 31;
    const int g    = lane >> 2;
    const int c    = lane & 3;
    const int wr   = warp * 32;

    const int bh = blockIdx.y;
    const int b  = bh >> 4;
    const int h  = bh & 15;
    const int q0 = blockIdx.x * 128;

    const __half* __restrict__ qb = g_q + (bh*NT + q0) * ND;
    const __half* __restrict__ kb = g_k + bh*NT*ND;
    const __half* __restrict__ vb = g_v + bh*NT*ND;
    const int*    __restrict__ mb = mask + b*NT;

    // Stage Q once: 128 rows x 64 halves, uint4 = 8 halves
    #pragma unroll
    for (int i = 0; i < 8; i++) {
        const int slot = tid + 128*i;
        const int r = slot >> 3, c8 = (slot & 7) * 8;
        *(uint4*)&Qsh[r*RS + c8] = *(const uint4*)&qb[r*ND + c8];
    }

    // ldmatrix lane-constant base into Vsh
    const int lrow = ((lane >> 3) & 1) * 8 + (lane & 7);
    const int lcol = (lane >> 4) * 8;
    const uint32_t vbase =
        (uint32_t)__cvta_generic_to_shared(&Vsh[lrow*RS + lcol]);

    float o[2][8][4] = {};
    float m_run[2][2] = {{-1e30f,-1e30f},{-1e30f,-1e30f}};
    float l_run[2][2] = {{0.f,0.f},{0.f,0.f}};

    for (int k0 = 0; k0 < NT; k0 += 64) {
        // prefetch K/V chunk to regs, then barrier, then store
        uint4 ka[4], va[4];
        #pragma unroll
        for (int i = 0; i < 4; i++) {
            const int slot = tid + 128*i;
            const int r = slot >> 3, c8 = (slot & 7) * 8;
            ka[i] = *(const uint4*)&kb[(k0 + r)*ND + c8];
            va[i] = *(const uint4*)&vb[(k0 + r)*ND + c8];
        }
        __syncthreads();   // prior chunk's smem reads complete
        #pragma unroll
        for (int i = 0; i < 4; i++) {
            const int slot = tid + 128*i;
            const int r = slot >> 3, c8 = (slot & 7) * 8;
            *(uint4*)&Ksh[r*RS + c8] = ka[i];
            *(uint4*)&Vsh[r*RS + c8] = va[i];
        }
        if (tid < 64) maskf[tid] = (mb[k0 + tid] > 0) ? 0.0f : -1e30f;
        __syncthreads();

        // ---- S = Q @ K^T  (4 k16-steps x 8 key-tiles x 2 m-tiles) ----
        float s[2][8][4] = {};
        #pragma unroll
        for (int kt = 0; kt < 4; kt++) {
            const int k = kt*16;
            uint32_t a[2][4];
            #pragma unroll
            for (int mt = 0; mt < 2; mt++) {
                const __half* qr = &Qsh[(wr + mt*16 + g)*RS + k + 2*c];
                a[mt][0] = *(const uint32_t*)qr;
                a[mt][1] = *(const uint32_t*)(qr + 8*RS);
                a[mt][2] = *(const uint32_t*)(qr + 8);
                a[mt][3] = *(const uint32_t*)(qr + 8*RS + 8);
            }
            #pragma unroll
            for (int nt = 0; nt < 8; nt++) {
                const __half* kr = &Ksh[(nt*8 + g)*RS + k + 2*c];
                uint32_t bb[2] = {*(const uint32_t*)kr,
                                  *(const uint32_t*)(kr + 8)};
                mma_f16(s[0][nt], a[0], bb);
                mma_f16(s[1][nt], a[1], bb);
            }
        }

        // additive mask (reference semantics: masked -> -1e30)
        #pragma unroll
        for (int nt = 0; nt < 8; nt++) {
            float2 mf = *(const float2*)&maskf[nt*8 + 2*c];
            #pragma unroll
            for (int mt = 0; mt < 2; mt++) {
                s[mt][nt][0] += mf.x; s[mt][nt][1] += mf.y;
                s[mt][nt][2] += mf.x; s[mt][nt][3] += mf.y;
            }
        }

        // ---- online softmax (accumulator layout; quad shuffles) ----
        #pragma unroll
        for (int mt = 0; mt < 2; mt++) {
            float alpha[2];
            #pragma unroll
            for (int rh = 0; rh < 2; rh++) {
                float rm = -1e30f;
                #pragma unroll
                for (int nt = 0; nt < 8; nt++)
                    rm = fmaxf(rm, fmaxf(s[mt][nt][rh*2], s[mt][nt][rh*2+1]));
                rm = fmaxf(rm, __shfl_xor_sync(0xffffffffu, rm, 1));
                rm = fmaxf(rm, __shfl_xor_sync(0xffffffffu, rm, 2));
                float mnew = fmaxf(m_run[mt][rh], rm);
                alpha[rh] = __expf(m_run[mt][rh] - mnew);
                m_run[mt][rh] = mnew;
                float rs = 0.f;
                #pragma unroll
                for (int nt = 0; nt < 8; nt++) {
                    float p0 = __expf(s[mt][nt][rh*2]   - mnew);
                    float p1 = __expf(s[mt][nt][rh*2+1] - mnew);
                    s[mt][nt][rh*2] = p0; s[mt][nt][rh*2+1] = p1;
                    rs += p0 + p1;
                }
                rs += __shfl_xor_sync(0xffffffffu, rs, 1);
                rs += __shfl_xor_sync(0xffffffffu, rs, 2);
                l_run[mt][rh] = l_run[mt][rh]*alpha[rh] + rs;
            }
            #pragma unroll
            for (int nt = 0; nt < 8; nt++) {
                o[mt][nt][0] *= alpha[0]; o[mt][nt][1] *= alpha[0];
                o[mt][nt][2] *= alpha[1]; o[mt][nt][3] *= alpha[1];
            }
            // P -> smem as fp16 (RN)
            #pragma unroll
            for (int nt = 0; nt < 8; nt++) {
                *(__half2*)&Psh[(wr + mt*16 + g    )*RS + nt*8 + 2*c] =
                    __floats2half2_rn(s[mt][nt][0], s[mt][nt][1]);
                *(__half2*)&Psh[(wr + mt*16 + g + 8)*RS + nt*8 + 2*c] =
                    __floats2half2_rn(s[mt][nt][2], s[mt][nt][3]);
            }
        }
        __syncwarp();

        // ---- O += P @ V  (V b-frags via ldmatrix.x4.trans) ----
        #pragma unroll
        for (int kt = 0; kt < 4; kt++) {
            const int k = kt*16;
            uint32_t a[2][4];
            #pragma unroll
            for (int mt = 0; mt < 2; mt++) {
                const __half* pr = &Psh[(wr + mt*16 + g)*RS + k + 2*c];
                a[mt][0] = *(const uint32_t*)pr;
                a[mt][1] = *(const uint32_t*)(pr + 8*RS);
                a[mt][2] = *(const uint32_t*)(pr + 8);
                a[mt][3] = *(const uint32_t*)(pr + 8*RS + 8);
            }
            #pragma unroll
            for (int nt2 = 0; nt2 < 4; nt2++) {
                uint32_t r0, r1, r2, r3;
                const uint32_t addr = vbase + (uint32_t)((kt*16*RS + nt2*16) * 2);
                asm volatile(
                    "ldmatrix.sync.aligned.m8n8.x4.trans.shared.b16 "
                    "{%0,%1,%2,%3}, [%4];"
                    : "=r"(r0), "=r"(r1), "=r"(r2), "=r"(r3) : "r"(addr));
                uint32_t b0[2] = {r0, r1};
                uint32_t b1[2] = {r2, r3};
                mma_f16(o[0][nt2*2    ], a[0], b0);
                mma_f16(o[1][nt2*2    ], a[1], b0);
                mma_f16(o[0][nt2*2 + 1], a[0], b1);
                mma_f16(o[1][nt2*2 + 1], a[1], b1);
            }
        }
    }

    // epilogue: normalize, store fp32
    #pragma unroll
    for (int mt = 0; mt < 2; mt++) {
        const float inv0 = 1.0f / l_run[mt][0];
        const float inv1 = 1.0f / l_run[mt][1];
        const int t0 = q0 + wr + mt*16 + g;
        float* ob0 = out + (b*NT + t0    )*NC + h*ND;
        float* ob1 = out + (b*NT + t0 + 8)*NC + h*ND;
        #pragma unroll
        for (int nt = 0; nt < 8; nt++) {
            *(float2*)&ob0[nt*8 + 2*c] =
                make_float2(o[mt][nt][0]*inv0, o[mt][nt][1]*inv0);
            *(float2*)&ob1[nt*8 + 2*c] =
                make_float2(o[mt][nt][2]*inv1, o[mt][nt][3]*inv1);
        }
    }
}

// ---------------------------------------------------------------------------
extern "C" void kernel_launch(void* const* d_in, const int* in_sizes, int n_in,
                              void* d_out, int out_size)
{
    const float* x  = (const float*)d_in[0];
    const int* mask = (const int*)  d_in[1];
    const float* Wq = (const float*)d_in[2];
    const float* bq = (const float*)d_in[3];
    const float* Wk = (const float*)d_in[4];
    const float* bk = (const float*)d_in[5];
    const float* Wv = (const float*)d_in[6];
    const float* bv = (const float*)d_in[7];
    float* out = (float*)d_out;

    const int qkv_smem = 3 * 128 * AST * 4;   // 55296
    cudaFuncSetAttribute(qkv_mma,
                         cudaFuncAttributeMaxDynamicSharedMemorySize, qkv_smem);
    qkv_mma<<<dim3(NC/128, (NB*NT)/128, 3), 256, qkv_smem>>>(
        x, Wq, bq, Wk, bk, Wv, bv);

    const int attn_smem = 27648 * 2 + 64 * 4; // 55552
    cudaFuncSetAttribute(attn_kernel,
                         cudaFuncAttributeMaxDynamicSharedMemorySize, attn_smem);
    attn_kernel<<<dim3(NT/128, NB*NH), 128, attn_smem>>>(mask, out);
}

// round 8
// speedup vs baseline: 1.5926x; 1.0762x over previous
#include <cuda_runtime.h>
#include <cuda_fp16.h>
#include <cstdint>

#define NB 4
#define NT 2048
#define NC 1024
#define NH 16
#define ND 64

// Scratch: Q,K,V in [B,H,T,D] layout, fp16 (rounded once in qkv epilogue).
__device__ __half g_q[NB*NH*NT*ND];
__device__ __half g_k[NB*NH*NT*ND];
__device__ __half g_v[NB*NH*NT*ND];

__device__ __forceinline__ void mma_f16(float d[4], const uint32_t a[4],
                                        const uint32_t b[2]) {
    asm volatile(
        "mma.sync.aligned.m16n8k16.row.col.f32.f16.f16.f32 "
        "{%0,%1,%2,%3}, {%4,%5,%6,%7}, {%8,%9}, {%0,%1,%2,%3};"
        : "+f"(d[0]), "+f"(d[1]), "+f"(d[2]), "+f"(d[3])
        : "r"(a[0]), "r"(a[1]), "r"(a[2]), "r"(a[3]), "r"(b[0]), "r"(b[1]));
}

// ---------------------------------------------------------------------------
// QKV projection on fp16 tensor cores with split-activation compensation:
//   x = x_hi + x_lo (both fp16); acc += x_hi*W + x_lo*W  (W single fp16 round)
// grid = (NC/128, (NB*NT)/128, 3), block = 256 (2 m-warp x 4 n-warp).
// Block tile 128x128, BK=32 (2 k16-steps).
// ---------------------------------------------------------------------------
#define QKST 40  // halves per row (20 words): frag banks g*20+c distinct mod 32

__global__ __launch_bounds__(256) void qkv_mma(
    const float* __restrict__ x,
    const float* __restrict__ Wq, const float* __restrict__ bq,
    const float* __restrict__ Wk, const float* __restrict__ bk,
    const float* __restrict__ Wv, const float* __restrict__ bv)
{
    extern __shared__ __align__(16) char smraw[];
    __half* Ah = (__half*)smraw;       // [128][QKST] x_hi
    __half* Al = Ah + 128*QKST;        // [128][QKST] x_lo
    __half* Bs = Al + 128*QKST;        // [128][QKST] W
    // 3 * 128 * 40 * 2 = 30720 B

    const int z = blockIdx.z;
    const float* __restrict__ W    = (z == 0) ? Wq : ((z == 1) ? Wk : Wv);
    const float* __restrict__ bias = (z == 0) ? bq : ((z == 1) ? bk : bv);
    __half* __restrict__ dst       = (z == 0) ? g_q : ((z == 1) ? g_k : g_v);
    const float scale = (z == 0) ? 0.125f : 1.0f;   // q pre-scaled by 1/sqrt(D)

    const int tid  = threadIdx.x;
    const int warp = tid >> 5;
    const int lane = tid & 31;
    const int g    = lane >> 2;
    const int c    = lane & 3;
    const int mw   = (warp & 1) * 64;
    const int nw   = (warp >> 1) * 32;

    const int m0 = blockIdx.y * 128;
    const int n0 = blockIdx.x * 128;

    // staging: each thread owns one row (tid>>1) and 16 of the 32 k-columns
    const int srow = tid >> 1;
    const int scg  = (tid & 1) * 16;

    float acc[4][4][4] = {};

    for (int k0 = 0; k0 < NC; k0 += 32) {
        float4 xv[4], wv[4];
        #pragma unroll
        for (int p = 0; p < 4; p++) {
            xv[p] = *(const float4*)&x[(m0 + srow)*NC + k0 + scg + 4*p];
            wv[p] = *(const float4*)&W[(n0 + srow)*NC + k0 + scg + 4*p];
        }
        __syncthreads();

        __half2 xh[8], xl[8], wh[8];
        #pragma unroll
        for (int p = 0; p < 4; p++) {
            const float vx[4] = {xv[p].x, xv[p].y, xv[p].z, xv[p].w};
            __half hq[4]; float lq[4];
            #pragma unroll
            for (int j = 0; j < 4; j++) {
                hq[j] = __float2half_rn(vx[j]);
                lq[j] = vx[j] - __half2float(hq[j]);
            }
            xh[2*p]   = __halves2half2(hq[0], hq[1]);
            xh[2*p+1] = __halves2half2(hq[2], hq[3]);
            xl[2*p]   = __floats2half2_rn(lq[0], lq[1]);
            xl[2*p+1] = __floats2half2_rn(lq[2], lq[3]);
            wh[2*p]   = __floats2half2_rn(wv[p].x, wv[p].y);
            wh[2*p+1] = __floats2half2_rn(wv[p].z, wv[p].w);
        }
        *(uint4*)&Ah[srow*QKST + scg    ] = ((const uint4*)xh)[0];
        *(uint4*)&Ah[srow*QKST + scg + 8] = ((const uint4*)xh)[1];
        *(uint4*)&Al[srow*QKST + scg    ] = ((const uint4*)xl)[0];
        *(uint4*)&Al[srow*QKST + scg + 8] = ((const uint4*)xl)[1];
        *(uint4*)&Bs[srow*QKST + scg    ] = ((const uint4*)wh)[0];
        *(uint4*)&Bs[srow*QKST + scg + 8] = ((const uint4*)wh)[1];
        __syncthreads();

        #pragma unroll
        for (int kc = 0; kc < 2; kc++) {
            const int k = kc * 16;
            uint32_t bf[4][2];
            #pragma unroll
            for (int nt = 0; nt < 4; nt++) {
                const __half* br = &Bs[(nw + nt*8 + g)*QKST + k + 2*c];
                bf[nt][0] = *(const uint32_t*)br;
                bf[nt][1] = *(const uint32_t*)(br + 8);
            }
            #pragma unroll
            for (int mt = 0; mt < 4; mt++) {
                const __half* ar = &Ah[(mw + mt*16 + g)*QKST + k + 2*c];
                const __half* lr = &Al[(mw + mt*16 + g)*QKST + k + 2*c];
                uint32_t ah[4] = {*(const uint32_t*)ar,
                                  *(const uint32_t*)(ar + 8*QKST),
                                  *(const uint32_t*)(ar + 8),
                                  *(const uint32_t*)(ar + 8*QKST + 8)};
                uint32_t al[4] = {*(const uint32_t*)lr,
                                  *(const uint32_t*)(lr + 8*QKST),
                                  *(const uint32_t*)(lr + 8),
                                  *(const uint32_t*)(lr + 8*QKST + 8)};
                #pragma unroll
                for (int nt = 0; nt < 4; nt++) {
                    mma_f16(acc[mt][nt], ah, bf[nt]);
                    mma_f16(acc[mt][nt], al, bf[nt]);
                }
            }
        }
    }

    // Epilogue: bias + scale (fp32), round to fp16, scatter to [B,H,T,D]
    #pragma unroll
    for (int nt = 0; nt < 4; nt++) {
        const int col = n0 + nw + nt*8 + 2*c;
        float2 b2 = *(const float2*)&bias[col];
        const int h  = col >> 6;
        const int cc = col & 63;
        #pragma unroll
        for (int mt = 0; mt < 4; mt++) {
            #pragma unroll
            for (int rh = 0; rh < 2; rh++) {
                const int m = m0 + mw + mt*16 + g + rh*8;
                const int b = m >> 11;
                const int t = m & (NT - 1);
                const float vx = (acc[mt][nt][rh*2 + 0] + b2.x) * scale;
                const float vy = (acc[mt][nt][rh*2 + 1] + b2.y) * scale;
                *(__half2*)&dst[((b*NH + h)*NT + t)*ND + cc] =
                    __floats2half2_rn(vx, vy);
            }
        }
    }
}

// ---------------------------------------------------------------------------
// Flash attention on fp16 tensor cores (m16n8k16, fp32 accum) — unchanged R7.
// grid = (NT/128, NB*NH), block = 128.
// ---------------------------------------------------------------------------
#define RS 72

__global__ __launch_bounds__(128) void attn_kernel(
    const int* __restrict__ mask, float* __restrict__ out)
{
    extern __shared__ __align__(16) char smraw[];
    __half* Qsh = (__half*)smraw;          // [128][RS]
    __half* Psh = Qsh + 128*RS;            // [128][RS]
    __half* Ksh = Psh + 128*RS;            // [64][RS]
    __half* Vsh = Ksh + 64*RS;             // [64][RS]
    float*  maskf = (float*)(Vsh + 64*RS); // [64]

    const int tid  = threadIdx.x;
    const int warp = tid >> 5;
    const int lane = tid & 31;
    const int g    = lane >> 2;
    const int c    = lane & 3;
    const int wr   = warp * 32;

    const int bh = blockIdx.y;
    const int b  = bh >> 4;
    const int h  = bh & 15;
    const int q0 = blockIdx.x * 128;

    const __half* __restrict__ qb = g_q + (bh*NT + q0) * ND;
    const __half* __restrict__ kb = g_k + bh*NT*ND;
    const __half* __restrict__ vb = g_v + bh*NT*ND;
    const int*    __restrict__ mb = mask + b*NT;

    #pragma unroll
    for (int i = 0; i < 8; i++) {
        const int slot = tid + 128*i;
        const int r = slot >> 3, c8 = (slot & 7) * 8;
        *(uint4*)&Qsh[r*RS + c8] = *(const uint4*)&qb[r*ND + c8];
    }

    const int lrow = ((lane >> 3) & 1) * 8 + (lane & 7);
    const int lcol = (lane >> 4) * 8;
    const uint32_t vbase =
        (uint32_t)__cvta_generic_to_shared(&Vsh[lrow*RS + lcol]);

    float o[2][8][4] = {};
    float m_run[2][2] = {{-1e30f,-1e30f},{-1e30f,-1e30f}};
    float l_run[2][2] = {{0.f,0.f},{0.f,0.f}};

    for (int k0 = 0; k0 < NT; k0 += 64) {
        uint4 ka[4], va[4];
        #pragma unroll
        for (int i = 0; i < 4; i++) {
            const int slot = tid + 128*i;
            const int r = slot >> 3, c8 = (slot & 7) * 8;
            ka[i] = *(const uint4*)&kb[(k0 + r)*ND + c8];
            va[i] = *(const uint4*)&vb[(k0 + r)*ND + c8];
        }
        __syncthreads();
        #pragma unroll
        for (int i = 0; i < 4; i++) {
            const int slot = tid + 128*i;
            const int r = slot >> 3, c8 = (slot & 7) * 8;
            *(uint4*)&Ksh[r*RS + c8] = ka[i];
            *(uint4*)&Vsh[r*RS + c8] = va[i];
        }
        if (tid < 64) maskf[tid] = (mb[k0 + tid] > 0) ? 0.0f : -1e30f;
        __syncthreads();

        float s[2][8][4] = {};
        #pragma unroll
        for (int kt = 0; kt < 4; kt++) {
            const int k = kt*16;
            uint32_t a[2][4];
            #pragma unroll
            for (int mt = 0; mt < 2; mt++) {
                const __half* qr = &Qsh[(wr + mt*16 + g)*RS + k + 2*c];
                a[mt][0] = *(const uint32_t*)qr;
                a[mt][1] = *(const uint32_t*)(qr + 8*RS);
                a[mt][2] = *(const uint32_t*)(qr + 8);
                a[mt][3] = *(const uint32_t*)(qr + 8*RS + 8);
            }
            #pragma unroll
            for (int nt = 0; nt < 8; nt++) {
                const __half* kr = &Ksh[(nt*8 + g)*RS + k + 2*c];
                uint32_t bb[2] = {*(const uint32_t*)kr,
                                  *(const uint32_t*)(kr + 8)};
                mma_f16(s[0][nt], a[0], bb);
                mma_f16(s[1][nt], a[1], bb);
            }
        }

        #pragma unroll
        for (int nt = 0; nt < 8; nt++) {
            float2 mf = *(const float2*)&maskf[nt*8 + 2*c];
            #pragma unroll
            for (int mt = 0; mt < 2; mt++) {
                s[mt][nt][0] += mf.x; s[mt][nt][1] += mf.y;
                s[mt][nt][2] += mf.x; s[mt][nt][3] += mf.y;
            }
        }

        #pragma unroll
        for (int mt = 0; mt < 2; mt++) {
            float alpha[2];
            #pragma unroll
            for (int rh = 0; rh < 2; rh++) {
                float rm = -1e30f;
                #pragma unroll
                for (int nt = 0; nt < 8; nt++)
                    rm = fmaxf(rm, fmaxf(s[mt][nt][rh*2], s[mt][nt][rh*2+1]));
                rm = fmaxf(rm, __shfl_xor_sync(0xffffffffu, rm, 1));
                rm = fmaxf(rm, __shfl_xor_sync(0xffffffffu, rm, 2));
                float mnew = fmaxf(m_run[mt][rh], rm);
                alpha[rh] = __expf(m_run[mt][rh] - mnew);
                m_run[mt][rh] = mnew;
                float rs = 0.f;
                #pragma unroll
                for (int nt = 0; nt < 8; nt++) {
                    float p0 = __expf(s[mt][nt][rh*2]   - mnew);
                    float p1 = __expf(s[mt][nt][rh*2+1] - mnew);
                    s[mt][nt][rh*2] = p0; s[mt][nt][rh*2+1] = p1;
                    rs += p0 + p1;
                }
                rs += __shfl_xor_sync(0xffffffffu, rs, 1);
                rs += __shfl_xor_sync(0xffffffffu, rs, 2);
                l_run[mt][rh] = l_run[mt][rh]*alpha[rh] + rs;
            }
            #pragma unroll
            for (int nt = 0; nt < 8; nt++) {
                o[mt][nt][0] *= alpha[0]; o[mt][nt][1] *= alpha[0];
                o[mt][nt][2] *= alpha[1]; o[mt][nt][3] *= alpha[1];
            }
            #pragma unroll
            for (int nt = 0; nt < 8; nt++) {
                *(__half2*)&Psh[(wr + mt*16 + g    )*RS + nt*8 + 2*c] =
                    __floats2half2_rn(s[mt][nt][0], s[mt][nt][1]);
                *(__half2*)&Psh[(wr + mt*16 + g + 8)*RS + nt*8 + 2*c] =
                    __floats2half2_rn(s[mt][nt][2], s[mt][nt][3]);
            }
        }
        __syncwarp();

        #pragma unroll
        for (int kt = 0; kt < 4; kt++) {
            const int k = kt*16;
            uint32_t a[2][4];
            #pragma unroll
            for (int mt = 0; mt < 2; mt++) {
                const __half* pr = &Psh[(wr + mt*16 + g)*RS + k + 2*c];
                a[mt][0] = *(const uint32_t*)pr;
                a[mt][1] = *(const uint32_t*)(pr + 8*RS);
                a[mt][2] = *(const uint32_t*)(pr + 8);
                a[mt][3] = *(const uint32_t*)(pr + 8*RS + 8);
            }
            #pragma unroll
            for (int nt2 = 0; nt2 < 4; nt2++) {
                uint32_t r0, r1, r2, r3;
                const uint32_t addr = vbase + (uint32_t)((kt*16*RS + nt2*16) * 2);
                asm volatile(
                    "ldmatrix.sync.aligned.m8n8.x4.trans.shared.b16 "
                    "{%0,%1,%2,%3}, [%4];"
                    : "=r"(r0), "=r"(r1), "=r"(r2), "=r"(r3) : "r"(addr));
                uint32_t b0[2] = {r0, r1};
                uint32_t b1[2] = {r2, r3};
                mma_f16(o[0][nt2*2    ], a[0], b0);
                mma_f16(o[1][nt2*2    ], a[1], b0);
                mma_f16(o[0][nt2*2 + 1], a[0], b1);
                mma_f16(o[1][nt2*2 + 1], a[1], b1);
            }
        }
    }

    #pragma unroll
    for (int mt = 0; mt < 2; mt++) {
        const float inv0 = 1.0f / l_run[mt][0];
        const float inv1 = 1.0f / l_run[mt][1];
        const int t0 = q0 + wr + mt*16 + g;
        float* ob0 = out + (b*NT + t0    )*NC + h*ND;
        float* ob1 = out + (b*NT + t0 + 8)*NC + h*ND;
        #pragma unroll
        for (int nt = 0; nt < 8; nt++) {
            *(float2*)&ob0[nt*8 + 2*c] =
                make_float2(o[mt][nt][0]*inv0, o[mt][nt][1]*inv0);
            *(float2*)&ob1[nt*8 + 2*c] =
                make_float2(o[mt][nt][2]*inv1, o[mt][nt][3]*inv1);
        }
    }
}

// ---------------------------------------------------------------------------
extern "C" void kernel_launch(void* const* d_in, const int* in_sizes, int n_in,
                              void* d_out, int out_size)
{
    const float* x  = (const float*)d_in[0];
    const int* mask = (const int*)  d_in[1];
    const float* Wq = (const float*)d_in[2];
    const float* bq = (const float*)d_in[3];
    const float* Wk = (const float*)d_in[4];
    const float* bk = (const float*)d_in[5];
    const float* Wv = (const float*)d_in[6];
    const float* bv = (const float*)d_in[7];
    float* out = (float*)d_out;

    const int qkv_smem = 3 * 128 * QKST * 2;  // 30720
    cudaFuncSetAttribute(qkv_mma,
                         cudaFuncAttributeMaxDynamicSharedMemorySize, qkv_smem);
    qkv_mma<<<dim3(NC/128, (NB*NT)/128, 3), 256, qkv_smem>>>(
        x, Wq, bq, Wk, bk, Wv, bv);

    const int attn_smem = 27648 * 2 + 64 * 4; // 55552
    cudaFuncSetAttribute(attn_kernel,
                         cudaFuncAttributeMaxDynamicSharedMemorySize, attn_smem);
    attn_kernel<<<dim3(NT/128, NB*NH), 128, attn_smem>>>(mask, out);
}

// round 9
// speedup vs baseline: 1.6819x; 1.0560x over previous
#include <cuda_runtime.h>
#include <cuda_fp16.h>
#include <cstdint>

#define NB 4
#define NT 2048
#define NC 1024
#define NH 16
#define ND 64

// Scratch: Q,K,V in [B,H,T,D] layout, fp16 (rounded once in qkv epilogue).
__device__ __half g_q[NB*NH*NT*ND];
__device__ __half g_k[NB*NH*NT*ND];
__device__ __half g_v[NB*NH*NT*ND];

__device__ __forceinline__ void mma_f16(float d[4], const uint32_t a[4],
                                        const uint32_t b[2]) {
    asm volatile(
        "mma.sync.aligned.m16n8k16.row.col.f32.f16.f16.f32 "
        "{%0,%1,%2,%3}, {%4,%5,%6,%7}, {%8,%9}, {%0,%1,%2,%3};"
        : "+f"(d[0]), "+f"(d[1]), "+f"(d[2]), "+f"(d[3])
        : "r"(a[0]), "r"(a[1]), "r"(a[2]), "r"(a[3]), "r"(b[0]), "r"(b[1]));
}

__device__ __forceinline__ void ldm_x4(uint32_t r[4], uint32_t addr) {
    asm volatile(
        "ldmatrix.sync.aligned.m8n8.x4.shared.b16 {%0,%1,%2,%3}, [%4];"
        : "=r"(r[0]), "=r"(r[1]), "=r"(r[2]), "=r"(r[3]) : "r"(addr));
}

// ---------------------------------------------------------------------------
// QKV projection on fp16 tensor cores with split-activation compensation.
// R9: all fragments via ldmatrix.x4.
// grid = (NC/128, (NB*NT)/128, 3), block = 256 (2 m-warp x 4 n-warp).
// ---------------------------------------------------------------------------
#define QKST 40  // halves per row (20 words): ldmatrix rows conflict-free

__global__ __launch_bounds__(256) void qkv_mma(
    const float* __restrict__ x,
    const float* __restrict__ Wq, const float* __restrict__ bq,
    const float* __restrict__ Wk, const float* __restrict__ bk,
    const float* __restrict__ Wv, const float* __restrict__ bv)
{
    extern __shared__ __align__(16) char smraw[];
    __half* Ah = (__half*)smraw;       // [128][QKST] x_hi
    __half* Al = Ah + 128*QKST;        // [128][QKST] x_lo
    __half* Bs = Al + 128*QKST;        // [128][QKST] W

    const int z = blockIdx.z;
    const float* __restrict__ W    = (z == 0) ? Wq : ((z == 1) ? Wk : Wv);
    const float* __restrict__ bias = (z == 0) ? bq : ((z == 1) ? bk : bv);
    __half* __restrict__ dst       = (z == 0) ? g_q : ((z == 1) ? g_k : g_v);
    const float scale = (z == 0) ? 0.125f : 1.0f;

    const int tid  = threadIdx.x;
    const int warp = tid >> 5;
    const int lane = tid & 31;
    const int g    = lane >> 2;
    const int c    = lane & 3;
    const int mw   = (warp & 1) * 64;
    const int nw   = (warp >> 1) * 32;

    const int m0 = blockIdx.y * 128;
    const int n0 = blockIdx.x * 128;

    const int srow = tid >> 1;
    const int scg  = (tid & 1) * 16;

    // ldmatrix lane address components
    const int arow = (lane & 7) + ((lane >> 3) & 1) * 8;  // A: [m0k0,m8k0,m0k8,m8k8]
    const int acol = (lane >> 4) * 8;
    const int brow = (lane & 7) + (lane >> 4) * 8;        // B: [n0k0,n0k8,n8k0,n8k8]
    const int bcol = ((lane >> 3) & 1) * 8;

    const uint32_t ah_b = (uint32_t)__cvta_generic_to_shared(
        &Ah[(mw + arow)*QKST + acol]);
    const uint32_t al_b = (uint32_t)__cvta_generic_to_shared(
        &Al[(mw + arow)*QKST + acol]);
    const uint32_t bs_b = (uint32_t)__cvta_generic_to_shared(
        &Bs[(nw + brow)*QKST + bcol]);

    float acc[4][4][4] = {};

    for (int k0 = 0; k0 < NC; k0 += 32) {
        float4 xv[4], wv[4];
        #pragma unroll
        for (int p = 0; p < 4; p++) {
            xv[p] = *(const float4*)&x[(m0 + srow)*NC + k0 + scg + 4*p];
            wv[p] = *(const float4*)&W[(n0 + srow)*NC + k0 + scg + 4*p];
        }
        __syncthreads();

        __half2 xh[8], xl[8], wh[8];
        #pragma unroll
        for (int p = 0; p < 4; p++) {
            const float vx[4] = {xv[p].x, xv[p].y, xv[p].z, xv[p].w};
            __half hq[4]; float lq[4];
            #pragma unroll
            for (int j = 0; j < 4; j++) {
                hq[j] = __float2half_rn(vx[j]);
                lq[j] = vx[j] - __half2float(hq[j]);
            }
            xh[2*p]   = __halves2half2(hq[0], hq[1]);
            xh[2*p+1] = __halves2half2(hq[2], hq[3]);
            xl[2*p]   = __floats2half2_rn(lq[0], lq[1]);
            xl[2*p+1] = __floats2half2_rn(lq[2], lq[3]);
            wh[2*p]   = __floats2half2_rn(wv[p].x, wv[p].y);
            wh[2*p+1] = __floats2half2_rn(wv[p].z, wv[p].w);
        }
        *(uint4*)&Ah[srow*QKST + scg    ] = ((const uint4*)xh)[0];
        *(uint4*)&Ah[srow*QKST + scg + 8] = ((const uint4*)xh)[1];
        *(uint4*)&Al[srow*QKST + scg    ] = ((const uint4*)xl)[0];
        *(uint4*)&Al[srow*QKST + scg + 8] = ((const uint4*)xl)[1];
        *(uint4*)&Bs[srow*QKST + scg    ] = ((const uint4*)wh)[0];
        *(uint4*)&Bs[srow*QKST + scg + 8] = ((const uint4*)wh)[1];
        __syncthreads();

        #pragma unroll
        for (int kc = 0; kc < 2; kc++) {
            const uint32_t koff = (uint32_t)(kc * 16 * 2);
            uint32_t bf[2][4];
            ldm_x4(bf[0], bs_b + koff);
            ldm_x4(bf[1], bs_b + (uint32_t)(16*QKST*2) + koff);
            #pragma unroll
            for (int mt = 0; mt < 4; mt++) {
                const uint32_t moff = (uint32_t)(mt * 16 * QKST * 2);
                uint32_t ah[4], al[4];
                ldm_x4(ah, ah_b + moff + koff);
                ldm_x4(al, al_b + moff + koff);
                #pragma unroll
                for (int np = 0; np < 2; np++) {
                    mma_f16(acc[mt][2*np    ], ah, &bf[np][0]);
                    mma_f16(acc[mt][2*np    ], al, &bf[np][0]);
                    mma_f16(acc[mt][2*np + 1], ah, &bf[np][2]);
                    mma_f16(acc[mt][2*np + 1], al, &bf[np][2]);
                }
            }
        }
    }

    // Epilogue: bias + scale (fp32), round to fp16, scatter to [B,H,T,D]
    #pragma unroll
    for (int nt = 0; nt < 4; nt++) {
        const int col = n0 + nw + nt*8 + 2*c;
        float2 b2 = *(const float2*)&bias[col];
        const int h  = col >> 6;
        const int cc = col & 63;
        #pragma unroll
        for (int mt = 0; mt < 4; mt++) {
            #pragma unroll
            for (int rh = 0; rh < 2; rh++) {
                const int m = m0 + mw + mt*16 + g + rh*8;
                const int b = m >> 11;
                const int t = m & (NT - 1);
                const float vx = (acc[mt][nt][rh*2 + 0] + b2.x) * scale;
                const float vy = (acc[mt][nt][rh*2 + 1] + b2.y) * scale;
                *(__half2*)&dst[((b*NH + h)*NT + t)*ND + cc] =
                    __floats2half2_rn(vx, vy);
            }
        }
    }
}

// ---------------------------------------------------------------------------
// Flash attention on fp16 tensor cores. R9: Q/K/P fragments via ldmatrix.x4
// (V already ldmatrix.x4.trans). grid = (NT/128, NB*NH), block = 128.
// ---------------------------------------------------------------------------
#define RS 72

__global__ __launch_bounds__(128) void attn_kernel(
    const int* __restrict__ mask, float* __restrict__ out)
{
    extern __shared__ __align__(16) char smraw[];
    __half* Qsh = (__half*)smraw;          // [128][RS]
    __half* Psh = Qsh + 128*RS;            // [128][RS]
    __half* Ksh = Psh + 128*RS;            // [64][RS]
    __half* Vsh = Ksh + 64*RS;             // [64][RS]
    float*  maskf = (float*)(Vsh + 64*RS); // [64]

    const int tid  = threadIdx.x;
    const int warp = tid >> 5;
    const int lane = tid & 31;
    const int g    = lane >> 2;
    const int c    = lane & 3;
    const int wr   = warp * 32;

    const int bh = blockIdx.y;
    const int b  = bh >> 4;
    const int h  = bh & 15;
    const int q0 = blockIdx.x * 128;

    const __half* __restrict__ qb = g_q + (bh*NT + q0) * ND;
    const __half* __restrict__ kb = g_k + bh*NT*ND;
    const __half* __restrict__ vb = g_v + bh*NT*ND;
    const int*    __restrict__ mb = mask + b*NT;

    #pragma unroll
    for (int i = 0; i < 8; i++) {
        const int slot = tid + 128*i;
        const int r = slot >> 3, c8 = (slot & 7) * 8;
        *(uint4*)&Qsh[r*RS + c8] = *(const uint4*)&qb[r*ND + c8];
    }

    // ldmatrix lane addresses
    const int arow = (lane & 7) + ((lane >> 3) & 1) * 8;   // A frags
    const int acol = (lane >> 4) * 8;
    const int brow = (lane & 7) + (lane >> 4) * 8;         // K b frags
    const int bcol = ((lane >> 3) & 1) * 8;
    const int vrow = ((lane >> 3) & 1) * 8 + (lane & 7);   // V trans frags
    const int vcol = (lane >> 4) * 8;

    const uint32_t qa_b = (uint32_t)__cvta_generic_to_shared(
        &Qsh[(wr + arow)*RS + acol]);
    const uint32_t pa_b = (uint32_t)__cvta_generic_to_shared(
        &Psh[(wr + arow)*RS + acol]);
    const uint32_t kb_b = (uint32_t)__cvta_generic_to_shared(
        &Ksh[brow*RS + bcol]);
    const uint32_t vb_b = (uint32_t)__cvta_generic_to_shared(
        &Vsh[vrow*RS + vcol]);
    const uint32_t MT16 = (uint32_t)(16*RS*2);

    float o[2][8][4] = {};
    float m_run[2][2] = {{-1e30f,-1e30f},{-1e30f,-1e30f}};
    float l_run[2][2] = {{0.f,0.f},{0.f,0.f}};

    for (int k0 = 0; k0 < NT; k0 += 64) {
        uint4 ka[4], va[4];
        #pragma unroll
        for (int i = 0; i < 4; i++) {
            const int slot = tid + 128*i;
            const int r = slot >> 3, c8 = (slot & 7) * 8;
            ka[i] = *(const uint4*)&kb[(k0 + r)*ND + c8];
            va[i] = *(const uint4*)&vb[(k0 + r)*ND + c8];
        }
        __syncthreads();
        #pragma unroll
        for (int i = 0; i < 4; i++) {
            const int slot = tid + 128*i;
            const int r = slot >> 3, c8 = (slot & 7) * 8;
            *(uint4*)&Ksh[r*RS + c8] = ka[i];
            *(uint4*)&Vsh[r*RS + c8] = va[i];
        }
        if (tid < 64) maskf[tid] = (mb[k0 + tid] > 0) ? 0.0f : -1e30f;
        __syncthreads();

        // ---- S = Q @ K^T ----
        float s[2][8][4] = {};
        #pragma unroll
        for (int kt = 0; kt < 4; kt++) {
            const uint32_t koff = (uint32_t)(kt * 32);
            uint32_t a[2][4];
            ldm_x4(a[0], qa_b + koff);
            ldm_x4(a[1], qa_b + MT16 + koff);
            #pragma unroll
            for (int np = 0; np < 4; np++) {
                uint32_t bbq[4];
                ldm_x4(bbq, kb_b + (uint32_t)np*MT16 + koff);
                mma_f16(s[0][2*np    ], a[0], &bbq[0]);
                mma_f16(s[1][2*np    ], a[1], &bbq[0]);
                mma_f16(s[0][2*np + 1], a[0], &bbq[2]);
                mma_f16(s[1][2*np + 1], a[1], &bbq[2]);
            }
        }

        // additive mask (reference semantics: masked -> -1e30)
        #pragma unroll
        for (int nt = 0; nt < 8; nt++) {
            float2 mf = *(const float2*)&maskf[nt*8 + 2*c];
            #pragma unroll
            for (int mt = 0; mt < 2; mt++) {
                s[mt][nt][0] += mf.x; s[mt][nt][1] += mf.y;
                s[mt][nt][2] += mf.x; s[mt][nt][3] += mf.y;
            }
        }

        // ---- online softmax ----
        #pragma unroll
        for (int mt = 0; mt < 2; mt++) {
            float alpha[2];
            #pragma unroll
            for (int rh = 0; rh < 2; rh++) {
                float rm = -1e30f;
                #pragma unroll
                for (int nt = 0; nt < 8; nt++)
                    rm = fmaxf(rm, fmaxf(s[mt][nt][rh*2], s[mt][nt][rh*2+1]));
                rm = fmaxf(rm, __shfl_xor_sync(0xffffffffu, rm, 1));
                rm = fmaxf(rm, __shfl_xor_sync(0xffffffffu, rm, 2));
                float mnew = fmaxf(m_run[mt][rh], rm);
                alpha[rh] = __expf(m_run[mt][rh] - mnew);
                m_run[mt][rh] = mnew;
                float rs = 0.f;
                #pragma unroll
                for (int nt = 0; nt < 8; nt++) {
                    float p0 = __expf(s[mt][nt][rh*2]   - mnew);
                    float p1 = __expf(s[mt][nt][rh*2+1] - mnew);
                    s[mt][nt][rh*2] = p0; s[mt][nt][rh*2+1] = p1;
                    rs += p0 + p1;
                }
                rs += __shfl_xor_sync(0xffffffffu, rs, 1);
                rs += __shfl_xor_sync(0xffffffffu, rs, 2);
                l_run[mt][rh] = l_run[mt][rh]*alpha[rh] + rs;
            }
            #pragma unroll
            for (int nt = 0; nt < 8; nt++) {
                o[mt][nt][0] *= alpha[0]; o[mt][nt][1] *= alpha[0];
                o[mt][nt][2] *= alpha[1]; o[mt][nt][3] *= alpha[1];
            }
            #pragma unroll
            for (int nt = 0; nt < 8; nt++) {
                *(__half2*)&Psh[(wr + mt*16 + g    )*RS + nt*8 + 2*c] =
                    __floats2half2_rn(s[mt][nt][0], s[mt][nt][1]);
                *(__half2*)&Psh[(wr + mt*16 + g + 8)*RS + nt*8 + 2*c] =
                    __floats2half2_rn(s[mt][nt][2], s[mt][nt][3]);
            }
        }
        __syncwarp();

        // ---- O += P @ V ----
        #pragma unroll
        for (int kt = 0; kt < 4; kt++) {
            const uint32_t koff = (uint32_t)(kt * 32);
            uint32_t a[2][4];
            ldm_x4(a[0], pa_b + koff);
            ldm_x4(a[1], pa_b + MT16 + koff);
            #pragma unroll
            for (int nt2 = 0; nt2 < 4; nt2++) {
                uint32_t r0, r1, r2, r3;
                const uint32_t addr = vb_b + (uint32_t)(kt*16*RS + nt2*16) * 2;
                asm volatile(
                    "ldmatrix.sync.aligned.m8n8.x4.trans.shared.b16 "
                    "{%0,%1,%2,%3}, [%4];"
                    : "=r"(r0), "=r"(r1), "=r"(r2), "=r"(r3) : "r"(addr));
                uint32_t b0[2] = {r0, r1};
                uint32_t b1[2] = {r2, r3};
                mma_f16(o[0][nt2*2    ], a[0], b0);
                mma_f16(o[1][nt2*2    ], a[1], b0);
                mma_f16(o[0][nt2*2 + 1], a[0], b1);
                mma_f16(o[1][nt2*2 + 1], a[1], b1);
            }
        }
    }

    // epilogue: normalize, store fp32
    #pragma unroll
    for (int mt = 0; mt < 2; mt++) {
        const float inv0 = 1.0f / l_run[mt][0];
        const float inv1 = 1.0f / l_run[mt][1];
        const int t0 = q0 + wr + mt*16 + g;
        float* ob0 = out + (b*NT + t0    )*NC + h*ND;
        float* ob1 = out + (b*NT + t0 + 8)*NC + h*ND;
        #pragma unroll
        for (int nt = 0; nt < 8; nt++) {
            *(float2*)&ob0[nt*8 + 2*c] =
                make_float2(o[mt][nt][0]*inv0, o[mt][nt][1]*inv0);
            *(float2*)&ob1[nt*8 + 2*c] =
                make_float2(o[mt][nt][2]*inv1, o[mt][nt][3]*inv1);
        }
    }
}

// ---------------------------------------------------------------------------
extern "C" void kernel_launch(void* const* d_in, const int* in_sizes, int n_in,
                              void* d_out, int out_size)
{
    const float* x  = (const float*)d_in[0];
    const int* mask = (const int*)  d_in[1];
    const float* Wq = (const float*)d_in[2];
    const float* bq = (const float*)d_in[3];
    const float* Wk = (const float*)d_in[4];
    const float* bk = (const float*)d_in[5];
    const float* Wv = (const float*)d_in[6];
    const float* bv = (const float*)d_in[7];
    float* out = (float*)d_out;

    const int qkv_smem = 3 * 128 * QKST * 2;  // 30720
    cudaFuncSetAttribute(qkv_mma,
                         cudaFuncAttributeMaxDynamicSharedMemorySize, qkv_smem);
    qkv_mma<<<dim3(NC/128, (NB*NT)/128, 3), 256, qkv_smem>>>(
        x, Wq, bq, Wk, bk, Wv, bv);

    const int attn_smem = 27648 * 2 + 64 * 4; // 55552
    cudaFuncSetAttribute(attn_kernel,
                         cudaFuncAttributeMaxDynamicSharedMemorySize, attn_smem);
    attn_kernel<<<dim3(NT/128, NB*NH), 128, attn_smem>>>(mask, out);
}

// round 10
// speedup vs baseline: 1.7581x; 1.0453x over previous
#include <cuda_runtime.h>
#include <cuda_fp16.h>
#include <cstdint>

#define NB 4
#define NT 2048
#define NC 1024
#define NH 16
#define ND 64

// Scratch: Q,K,V in [B,H,T,D] layout, fp16 (rounded once in qkv epilogue).
__device__ __half g_q[NB*NH*NT*ND];
__device__ __half g_k[NB*NH*NT*ND];
__device__ __half g_v[NB*NH*NT*ND];

__device__ __forceinline__ void mma_f16(float d[4], const uint32_t a[4],
                                        const uint32_t b[2]) {
    asm volatile(
        "mma.sync.aligned.m16n8k16.row.col.f32.f16.f16.f32 "
        "{%0,%1,%2,%3}, {%4,%5,%6,%7}, {%8,%9}, {%0,%1,%2,%3};"
        : "+f"(d[0]), "+f"(d[1]), "+f"(d[2]), "+f"(d[3])
        : "r"(a[0]), "r"(a[1]), "r"(a[2]), "r"(a[3]), "r"(b[0]), "r"(b[1]));
}

__device__ __forceinline__ void ldm_x4(uint32_t r[4], uint32_t addr) {
    asm volatile(
        "ldmatrix.sync.aligned.m8n8.x4.shared.b16 {%0,%1,%2,%3}, [%4];"
        : "=r"(r[0]), "=r"(r[1]), "=r"(r[2]), "=r"(r[3]) : "r"(addr));
}

__device__ __forceinline__ uint32_t h2pack(float x, float y) {
    __half2 h = __floats2half2_rn(x, y);
    return *(const uint32_t*)&h;
}

// ---------------------------------------------------------------------------
// QKV projection on fp16 tensor cores with split-activation compensation
// (unchanged from R9). grid = (NC/128, (NB*NT)/128, 3), block = 256.
// ---------------------------------------------------------------------------
#define QKST 40

__global__ __launch_bounds__(256) void qkv_mma(
    const float* __restrict__ x,
    const float* __restrict__ Wq, const float* __restrict__ bq,
    const float* __restrict__ Wk, const float* __restrict__ bk,
    const float* __restrict__ Wv, const float* __restrict__ bv)
{
    extern __shared__ __align__(16) char smraw[];
    __half* Ah = (__half*)smraw;
    __half* Al = Ah + 128*QKST;
    __half* Bs = Al + 128*QKST;

    const int z = blockIdx.z;
    const float* __restrict__ W    = (z == 0) ? Wq : ((z == 1) ? Wk : Wv);
    const float* __restrict__ bias = (z == 0) ? bq : ((z == 1) ? bk : bv);
    __half* __restrict__ dst       = (z == 0) ? g_q : ((z == 1) ? g_k : g_v);
    const float scale = (z == 0) ? 0.125f : 1.0f;

    const int tid  = threadIdx.x;
    const int warp = tid >> 5;
    const int lane = tid & 31;
    const int g    = lane >> 2;
    const int c    = lane & 3;
    const int mw   = (warp & 1) * 64;
    const int nw   = (warp >> 1) * 32;

    const int m0 = blockIdx.y * 128;
    const int n0 = blockIdx.x * 128;

    const int srow = tid >> 1;
    const int scg  = (tid & 1) * 16;

    const int arow = (lane & 7) + ((lane >> 3) & 1) * 8;
    const int acol = (lane >> 4) * 8;
    const int brow = (lane & 7) + (lane >> 4) * 8;
    const int bcol = ((lane >> 3) & 1) * 8;

    const uint32_t ah_b = (uint32_t)__cvta_generic_to_shared(
        &Ah[(mw + arow)*QKST + acol]);
    const uint32_t al_b = (uint32_t)__cvta_generic_to_shared(
        &Al[(mw + arow)*QKST + acol]);
    const uint32_t bs_b = (uint32_t)__cvta_generic_to_shared(
        &Bs[(nw + brow)*QKST + bcol]);

    float acc[4][4][4] = {};

    for (int k0 = 0; k0 < NC; k0 += 32) {
        float4 xv[4], wv[4];
        #pragma unroll
        for (int p = 0; p < 4; p++) {
            xv[p] = *(const float4*)&x[(m0 + srow)*NC + k0 + scg + 4*p];
            wv[p] = *(const float4*)&W[(n0 + srow)*NC + k0 + scg + 4*p];
        }
        __syncthreads();

        __half2 xh[8], xl[8], wh[8];
        #pragma unroll
        for (int p = 0; p < 4; p++) {
            const float vx[4] = {xv[p].x, xv[p].y, xv[p].z, xv[p].w};
            __half hq[4]; float lq[4];
            #pragma unroll
            for (int j = 0; j < 4; j++) {
                hq[j] = __float2half_rn(vx[j]);
                lq[j] = vx[j] - __half2float(hq[j]);
            }
            xh[2*p]   = __halves2half2(hq[0], hq[1]);
            xh[2*p+1] = __halves2half2(hq[2], hq[3]);
            xl[2*p]   = __floats2half2_rn(lq[0], lq[1]);
            xl[2*p+1] = __floats2half2_rn(lq[2], lq[3]);
            wh[2*p]   = __floats2half2_rn(wv[p].x, wv[p].y);
            wh[2*p+1] = __floats2half2_rn(wv[p].z, wv[p].w);
        }
        *(uint4*)&Ah[srow*QKST + scg    ] = ((const uint4*)xh)[0];
        *(uint4*)&Ah[srow*QKST + scg + 8] = ((const uint4*)xh)[1];
        *(uint4*)&Al[srow*QKST + scg    ] = ((const uint4*)xl)[0];
        *(uint4*)&Al[srow*QKST + scg + 8] = ((const uint4*)xl)[1];
        *(uint4*)&Bs[srow*QKST + scg    ] = ((const uint4*)wh)[0];
        *(uint4*)&Bs[srow*QKST + scg + 8] = ((const uint4*)wh)[1];
        __syncthreads();

        #pragma unroll
        for (int kc = 0; kc < 2; kc++) {
            const uint32_t koff = (uint32_t)(kc * 16 * 2);
            uint32_t bf[2][4];
            ldm_x4(bf[0], bs_b + koff);
            ldm_x4(bf[1], bs_b + (uint32_t)(16*QKST*2) + koff);
            #pragma unroll
            for (int mt = 0; mt < 4; mt++) {
                const uint32_t moff = (uint32_t)(mt * 16 * QKST * 2);
                uint32_t ah[4], al[4];
                ldm_x4(ah, ah_b + moff + koff);
                ldm_x4(al, al_b + moff + koff);
                #pragma unroll
                for (int np = 0; np < 2; np++) {
                    mma_f16(acc[mt][2*np    ], ah, &bf[np][0]);
                    mma_f16(acc[mt][2*np    ], al, &bf[np][0]);
                    mma_f16(acc[mt][2*np + 1], ah, &bf[np][2]);
                    mma_f16(acc[mt][2*np + 1], al, &bf[np][2]);
                }
            }
        }
    }

    #pragma unroll
    for (int nt = 0; nt < 4; nt++) {
        const int col = n0 + nw + nt*8 + 2*c;
        float2 b2 = *(const float2*)&bias[col];
        const int h  = col >> 6;
        const int cc = col & 63;
        #pragma unroll
        for (int mt = 0; mt < 4; mt++) {
            #pragma unroll
            for (int rh = 0; rh < 2; rh++) {
                const int m = m0 + mw + mt*16 + g + rh*8;
                const int b = m >> 11;
                const int t = m & (NT - 1);
                const float vx = (acc[mt][nt][rh*2 + 0] + b2.x) * scale;
                const float vy = (acc[mt][nt][rh*2 + 1] + b2.y) * scale;
                *(__half2*)&dst[((b*NH + h)*NT + t)*ND + cc] =
                    __floats2half2_rn(vx, vy);
            }
        }
    }
}

// ---------------------------------------------------------------------------
// Flash attention on fp16 tensor cores. R10: P kept in registers (accumulator
// layout == A-fragment layout for adjacent n8-tile pairs), Q fragments
// preloaded once, rescale skipped when alpha==1 warp-wide.
// grid = (NT/128, NB*NH), block = 128 (4 warps x 32 q-rows).
// ---------------------------------------------------------------------------
#define RS 72

__global__ __launch_bounds__(128) void attn_kernel(
    const int* __restrict__ mask, float* __restrict__ out)
{
    extern __shared__ __align__(16) char smraw[];
    __half* Qsh = (__half*)smraw;          // [128][RS]
    __half* Ksh = Qsh + 128*RS;            // [64][RS]
    __half* Vsh = Ksh + 64*RS;             // [64][RS]
    float*  maskf = (float*)(Vsh + 64*RS); // [64]
    // 18432 halves + 64 floats = 37120 B

    const int tid  = threadIdx.x;
    const int warp = tid >> 5;
    const int lane = tid & 31;
    const int g    = lane >> 2;
    const int c    = lane & 3;
    const int wr   = warp * 32;

    const int bh = blockIdx.y;
    const int b  = bh >> 4;
    const int h  = bh & 15;
    const int q0 = blockIdx.x * 128;

    const __half* __restrict__ qb = g_q + (bh*NT + q0) * ND;
    const __half* __restrict__ kb = g_k + bh*NT*ND;
    const __half* __restrict__ vb = g_v + bh*NT*ND;
    const int*    __restrict__ mb = mask + b*NT;

    // Stage Q, then preload all Q a-fragments into registers (loop-invariant)
    #pragma unroll
    for (int i = 0; i < 8; i++) {
        const int slot = tid + 128*i;
        const int r = slot >> 3, c8 = (slot & 7) * 8;
        *(uint4*)&Qsh[r*RS + c8] = *(const uint4*)&qb[r*ND + c8];
    }

    const int arow = (lane & 7) + ((lane >> 3) & 1) * 8;   // A frags
    const int acol = (lane >> 4) * 8;
    const int brow = (lane & 7) + (lane >> 4) * 8;         // K b frags
    const int bcol = ((lane >> 3) & 1) * 8;
    const int vrow = ((lane >> 3) & 1) * 8 + (lane & 7);   // V trans frags
    const int vcol = (lane >> 4) * 8;

    const uint32_t qa_b = (uint32_t)__cvta_generic_to_shared(
        &Qsh[(wr + arow)*RS + acol]);
    const uint32_t kb_b = (uint32_t)__cvta_generic_to_shared(
        &Ksh[brow*RS + bcol]);
    const uint32_t vb_b = (uint32_t)__cvta_generic_to_shared(
        &Vsh[vrow*RS + vcol]);
    const uint32_t MT16 = (uint32_t)(16*RS*2);

    __syncthreads();
    uint32_t aq[2][4][4];
    #pragma unroll
    for (int mt = 0; mt < 2; mt++)
        #pragma unroll
        for (int kt = 0; kt < 4; kt++)
            ldm_x4(aq[mt][kt], qa_b + (uint32_t)mt*MT16 + (uint32_t)(kt*32));

    float o[2][8][4] = {};
    float m_run[2][2] = {{-1e30f,-1e30f},{-1e30f,-1e30f}};
    float l_run[2][2] = {{0.f,0.f},{0.f,0.f}};

    for (int k0 = 0; k0 < NT; k0 += 64) {
        uint4 ka[4], va[4];
        #pragma unroll
        for (int i = 0; i < 4; i++) {
            const int slot = tid + 128*i;
            const int r = slot >> 3, c8 = (slot & 7) * 8;
            ka[i] = *(const uint4*)&kb[(k0 + r)*ND + c8];
            va[i] = *(const uint4*)&vb[(k0 + r)*ND + c8];
        }
        __syncthreads();   // prior chunk's Ksh/Vsh reads complete
        #pragma unroll
        for (int i = 0; i < 4; i++) {
            const int slot = tid + 128*i;
            const int r = slot >> 3, c8 = (slot & 7) * 8;
            *(uint4*)&Ksh[r*RS + c8] = ka[i];
            *(uint4*)&Vsh[r*RS + c8] = va[i];
        }
        if (tid < 64) maskf[tid] = (mb[k0 + tid] > 0) ? 0.0f : -1e30f;
        __syncthreads();

        // ---- S = Q @ K^T ----
        float s[2][8][4] = {};
        #pragma unroll
        for (int kt = 0; kt < 4; kt++) {
            const uint32_t koff = (uint32_t)(kt * 32);
            #pragma unroll
            for (int np = 0; np < 4; np++) {
                uint32_t bbq[4];
                ldm_x4(bbq, kb_b + (uint32_t)np*MT16 + koff);
                mma_f16(s[0][2*np    ], aq[0][kt], &bbq[0]);
                mma_f16(s[1][2*np    ], aq[1][kt], &bbq[0]);
                mma_f16(s[0][2*np + 1], aq[0][kt], &bbq[2]);
                mma_f16(s[1][2*np + 1], aq[1][kt], &bbq[2]);
            }
        }

        // additive mask (reference semantics: masked -> -1e30)
        #pragma unroll
        for (int nt = 0; nt < 8; nt++) {
            float2 mf = *(const float2*)&maskf[nt*8 + 2*c];
            #pragma unroll
            for (int mt = 0; mt < 2; mt++) {
                s[mt][nt][0] += mf.x; s[mt][nt][1] += mf.y;
                s[mt][nt][2] += mf.x; s[mt][nt][3] += mf.y;
            }
        }

        // ---- online softmax (s regs become P in place) ----
        #pragma unroll
        for (int mt = 0; mt < 2; mt++) {
            float alpha[2];
            #pragma unroll
            for (int rh = 0; rh < 2; rh++) {
                float rm = -1e30f;
                #pragma unroll
                for (int nt = 0; nt < 8; nt++)
                    rm = fmaxf(rm, fmaxf(s[mt][nt][rh*2], s[mt][nt][rh*2+1]));
                rm = fmaxf(rm, __shfl_xor_sync(0xffffffffu, rm, 1));
                rm = fmaxf(rm, __shfl_xor_sync(0xffffffffu, rm, 2));
                float mnew = fmaxf(m_run[mt][rh], rm);
                alpha[rh] = __expf(m_run[mt][rh] - mnew);
                m_run[mt][rh] = mnew;
                float rs = 0.f;
                #pragma unroll
                for (int nt = 0; nt < 8; nt++) {
                    float p0 = __expf(s[mt][nt][rh*2]   - mnew);
                    float p1 = __expf(s[mt][nt][rh*2+1] - mnew);
                    s[mt][nt][rh*2] = p0; s[mt][nt][rh*2+1] = p1;
                    rs += p0 + p1;
                }
                rs += __shfl_xor_sync(0xffffffffu, rs, 1);
                rs += __shfl_xor_sync(0xffffffffu, rs, 2);
                l_run[mt][rh] = l_run[mt][rh]*alpha[rh] + rs;
            }
            // skip O-rescale when alpha==1 everywhere (x1.0 elision: exact)
            if (!__all_sync(0xffffffffu,
                            (alpha[0] == 1.0f) && (alpha[1] == 1.0f))) {
                #pragma unroll
                for (int nt = 0; nt < 8; nt++) {
                    o[mt][nt][0] *= alpha[0]; o[mt][nt][1] *= alpha[0];
                    o[mt][nt][2] *= alpha[1]; o[mt][nt][3] *= alpha[1];
                }
            }
        }

        // ---- O += P @ V  (P direct from s-registers: FA2 layout identity) ----
        #pragma unroll
        for (int kt = 0; kt < 4; kt++) {
            uint32_t a[2][4];
            #pragma unroll
            for (int mt = 0; mt < 2; mt++) {
                a[mt][0] = h2pack(s[mt][2*kt    ][0], s[mt][2*kt    ][1]);
                a[mt][1] = h2pack(s[mt][2*kt    ][2], s[mt][2*kt    ][3]);
                a[mt][2] = h2pack(s[mt][2*kt + 1][0], s[mt][2*kt + 1][1]);
                a[mt][3] = h2pack(s[mt][2*kt + 1][2], s[mt][2*kt + 1][3]);
            }
            #pragma unroll
            for (int nt2 = 0; nt2 < 4; nt2++) {
                uint32_t r0, r1, r2, r3;
                const uint32_t addr = vb_b + (uint32_t)(kt*16*RS + nt2*16) * 2;
                asm volatile(
                    "ldmatrix.sync.aligned.m8n8.x4.trans.shared.b16 "
                    "{%0,%1,%2,%3}, [%4];"
                    : "=r"(r0), "=r"(r1), "=r"(r2), "=r"(r3) : "r"(addr));
                uint32_t b0[2] = {r0, r1};
                uint32_t b1[2] = {r2, r3};
                mma_f16(o[0][nt2*2    ], a[0], b0);
                mma_f16(o[1][nt2*2    ], a[1], b0);
                mma_f16(o[0][nt2*2 + 1], a[0], b1);
                mma_f16(o[1][nt2*2 + 1], a[1], b1);
            }
        }
    }

    // epilogue: normalize, store fp32
    #pragma unroll
    for (int mt = 0; mt < 2; mt++) {
        const float inv0 = 1.0f / l_run[mt][0];
        const float inv1 = 1.0f / l_run[mt][1];
        const int t0 = q0 + wr + mt*16 + g;
        float* ob0 = out + (b*NT + t0    )*NC + h*ND;
        float* ob1 = out + (b*NT + t0 + 8)*NC + h*ND;
        #pragma unroll
        for (int nt = 0; nt < 8; nt++) {
            *(float2*)&ob0[nt*8 + 2*c] =
                make_float2(o[mt][nt][0]*inv0, o[mt][nt][1]*inv0);
            *(float2*)&ob1[nt*8 + 2*c] =
                make_float2(o[mt][nt][2]*inv1, o[mt][nt][3]*inv1);
        }
    }
}

// ---------------------------------------------------------------------------
extern "C" void kernel_launch(void* const* d_in, const int* in_sizes, int n_in,
                              void* d_out, int out_size)
{
    const float* x  = (const float*)d_in[0];
    const int* mask = (const int*)  d_in[1];
    const float* Wq = (const float*)d_in[2];
    const float* bq = (const float*)d_in[3];
    const float* Wk = (const float*)d_in[4];
    const float* bk = (const float*)d_in[5];
    const float* Wv = (const float*)d_in[6];
    const float* bv = (const float*)d_in[7];
    float* out = (float*)d_out;

    const int qkv_smem = 3 * 128 * QKST * 2;  // 30720
    cudaFuncSetAttribute(qkv_mma,
                         cudaFuncAttributeMaxDynamicSharedMemorySize, qkv_smem);
    qkv_mma<<<dim3(NC/128, (NB*NT)/128, 3), 256, qkv_smem>>>(
        x, Wq, bq, Wk, bk, Wv, bv);

    const int attn_smem = (128*RS + 64*RS + 64*RS) * 2 + 64 * 4;  // 37120
    cudaFuncSetAttribute(attn_kernel,
                         cudaFuncAttributeMaxDynamicSharedMemorySize, attn_smem);
    attn_kernel<<<dim3(NT/128, NB*NH), 128, attn_smem>>>(mask, out);
}

// round 11
// speedup vs baseline: 1.8695x; 1.0634x over previous
#include <cuda_runtime.h>
#include <cuda_fp16.h>
#include <cstdint>

#define NB 4
#define NT 2048
#define NC 1024
#define NH 16
#define ND 64

// Scratch: Q,K,V in [B,H,T,D] layout, fp16.
__device__ __half g_q[NB*NH*NT*ND];
__device__ __half g_k[NB*NH*NT*ND];
__device__ __half g_v[NB*NH*NT*ND];
// Preconverted inputs: x split into hi+lo fp16; W rounded to fp16.
__device__ __half g_xh[NB*NT*NC];
__device__ __half g_xl[NB*NT*NC];
__device__ __half g_wh[3*NC*NC];

__device__ __forceinline__ void mma_f16(float d[4], const uint32_t a[4],
                                        const uint32_t b[2]) {
    asm volatile(
        "mma.sync.aligned.m16n8k16.row.col.f32.f16.f16.f32 "
        "{%0,%1,%2,%3}, {%4,%5,%6,%7}, {%8,%9}, {%0,%1,%2,%3};"
        : "+f"(d[0]), "+f"(d[1]), "+f"(d[2]), "+f"(d[3])
        : "r"(a[0]), "r"(a[1]), "r"(a[2]), "r"(a[3]), "r"(b[0]), "r"(b[1]));
}

__device__ __forceinline__ void ldm_x4(uint32_t r[4], uint32_t addr) {
    asm volatile(
        "ldmatrix.sync.aligned.m8n8.x4.shared.b16 {%0,%1,%2,%3}, [%4];"
        : "=r"(r[0]), "=r"(r[1]), "=r"(r[2]), "=r"(r[3]) : "r"(addr));
}

__device__ __forceinline__ uint32_t h2pack(float x, float y) {
    __half2 h = __floats2half2_rn(x, y);
    return *(const uint32_t*)&h;
}

// ---------------------------------------------------------------------------
// Prep: one-time fp32 -> fp16 conversions (memory-bound, ~15-20 us total).
// ---------------------------------------------------------------------------
__global__ __launch_bounds__(256) void prep_x(const float* __restrict__ x)
{
    const int i8 = (blockIdx.x * 256 + threadIdx.x) * 8;   // 8 elems/thread
    float4 v0 = *(const float4*)&x[i8];
    float4 v1 = *(const float4*)&x[i8 + 4];
    const float v[8] = {v0.x,v0.y,v0.z,v0.w, v1.x,v1.y,v1.z,v1.w};
    __half2 hi[4], lo[4];
    #pragma unroll
    for (int p = 0; p < 4; p++) {
        __half h0 = __float2half_rn(v[2*p]);
        __half h1 = __float2half_rn(v[2*p + 1]);
        hi[p] = __halves2half2(h0, h1);
        lo[p] = __floats2half2_rn(v[2*p]     - __half2float(h0),
                                  v[2*p + 1] - __half2float(h1));
    }
    *(uint4*)&g_xh[i8] = *(const uint4*)hi;
    *(uint4*)&g_xl[i8] = *(const uint4*)lo;
}

__global__ __launch_bounds__(256) void prep_w(
    const float* __restrict__ Wq, const float* __restrict__ Wk,
    const float* __restrict__ Wv)
{
    const float* __restrict__ W =
        (blockIdx.y == 0) ? Wq : ((blockIdx.y == 1) ? Wk : Wv);
    const int i8 = (blockIdx.x * 256 + threadIdx.x) * 8;
    float4 v0 = *(const float4*)&W[i8];
    float4 v1 = *(const float4*)&W[i8 + 4];
    __half2 h[4];
    h[0] = __floats2half2_rn(v0.x, v0.y);
    h[1] = __floats2half2_rn(v0.z, v0.w);
    h[2] = __floats2half2_rn(v1.x, v1.y);
    h[3] = __floats2half2_rn(v1.z, v1.w);
    *(uint4*)&g_wh[blockIdx.y*NC*NC + i8] = *(const uint4*)h;
}

// ---------------------------------------------------------------------------
// QKV projection on fp16 tensor cores with split-activation compensation.
// R11: inputs preconverted -> staging is pure uint4 copies.
// grid = (NC/128, (NB*NT)/128, 3), block = 256 (2 m-warp x 4 n-warp).
// ---------------------------------------------------------------------------
#define QKST 40

__global__ __launch_bounds__(256) void qkv_mma(
    const float* __restrict__ bq, const float* __restrict__ bk,
    const float* __restrict__ bv)
{
    extern __shared__ __align__(16) char smraw[];
    __half* Ah = (__half*)smraw;       // [128][QKST] x_hi
    __half* Al = Ah + 128*QKST;        // [128][QKST] x_lo
    __half* Bs = Al + 128*QKST;        // [128][QKST] W

    const int z = blockIdx.z;
    const float* __restrict__ bias = (z == 0) ? bq : ((z == 1) ? bk : bv);
    const __half* __restrict__ Wh  = g_wh + z*NC*NC;
    __half* __restrict__ dst       = (z == 0) ? g_q : ((z == 1) ? g_k : g_v);
    const float scale = (z == 0) ? 0.125f : 1.0f;   // q pre-scaled by 1/sqrt(D)

    const int tid  = threadIdx.x;
    const int warp = tid >> 5;
    const int lane = tid & 31;
    const int g    = lane >> 2;
    const int c    = lane & 3;
    const int mw   = (warp & 1) * 64;
    const int nw   = (warp >> 1) * 32;

    const int m0 = blockIdx.y * 128;
    const int n0 = blockIdx.x * 128;

    const int srow = tid >> 1;          // 0..127
    const int scg  = (tid & 1) * 16;    // 0 or 16

    const int arow = (lane & 7) + ((lane >> 3) & 1) * 8;
    const int acol = (lane >> 4) * 8;
    const int brow = (lane & 7) + (lane >> 4) * 8;
    const int bcol = ((lane >> 3) & 1) * 8;

    const uint32_t ah_b = (uint32_t)__cvta_generic_to_shared(
        &Ah[(mw + arow)*QKST + acol]);
    const uint32_t al_b = (uint32_t)__cvta_generic_to_shared(
        &Al[(mw + arow)*QKST + acol]);
    const uint32_t bs_b = (uint32_t)__cvta_generic_to_shared(
        &Bs[(nw + brow)*QKST + bcol]);

    float acc[4][4][4] = {};

    for (int k0 = 0; k0 < NC; k0 += 32) {
        // prefetch to regs (latency overlap), then sync, then store
        uint4 vah = *(const uint4*)&g_xh[(m0 + srow)*NC + k0 + scg];
        uint4 vah2 = *(const uint4*)&g_xh[(m0 + srow)*NC + k0 + scg + 8];
        uint4 val = *(const uint4*)&g_xl[(m0 + srow)*NC + k0 + scg];
        uint4 val2 = *(const uint4*)&g_xl[(m0 + srow)*NC + k0 + scg + 8];
        uint4 vw  = *(const uint4*)&Wh[(n0 + srow)*NC + k0 + scg];
        uint4 vw2 = *(const uint4*)&Wh[(n0 + srow)*NC + k0 + scg + 8];
        __syncthreads();
        *(uint4*)&Ah[srow*QKST + scg    ] = vah;
        *(uint4*)&Ah[srow*QKST + scg + 8] = vah2;
        *(uint4*)&Al[srow*QKST + scg    ] = val;
        *(uint4*)&Al[srow*QKST + scg + 8] = val2;
        *(uint4*)&Bs[srow*QKST + scg    ] = vw;
        *(uint4*)&Bs[srow*QKST + scg + 8] = vw2;
        __syncthreads();

        #pragma unroll
        for (int kc = 0; kc < 2; kc++) {
            const uint32_t koff = (uint32_t)(kc * 16 * 2);
            uint32_t bf[2][4];
            ldm_x4(bf[0], bs_b + koff);
            ldm_x4(bf[1], bs_b + (uint32_t)(16*QKST*2) + koff);
            #pragma unroll
            for (int mt = 0; mt < 4; mt++) {
                const uint32_t moff = (uint32_t)(mt * 16 * QKST * 2);
                uint32_t ah[4], al[4];
                ldm_x4(ah, ah_b + moff + koff);
                ldm_x4(al, al_b + moff + koff);
                #pragma unroll
                for (int np = 0; np < 2; np++) {
                    mma_f16(acc[mt][2*np    ], ah, &bf[np][0]);
                    mma_f16(acc[mt][2*np    ], al, &bf[np][0]);
                    mma_f16(acc[mt][2*np + 1], ah, &bf[np][2]);
                    mma_f16(acc[mt][2*np + 1], al, &bf[np][2]);
                }
            }
        }
    }

    // Epilogue: bias + scale (fp32), round to fp16, scatter to [B,H,T,D]
    #pragma unroll
    for (int nt = 0; nt < 4; nt++) {
        const int col = n0 + nw + nt*8 + 2*c;
        float2 b2 = *(const float2*)&bias[col];
        const int h  = col >> 6;
        const int cc = col & 63;
        #pragma unroll
        for (int mt = 0; mt < 4; mt++) {
            #pragma unroll
            for (int rh = 0; rh < 2; rh++) {
                const int m = m0 + mw + mt*16 + g + rh*8;
                const int b = m >> 11;
                const int t = m & (NT - 1);
                const float vx = (acc[mt][nt][rh*2 + 0] + b2.x) * scale;
                const float vy = (acc[mt][nt][rh*2 + 1] + b2.y) * scale;
                *(__half2*)&dst[((b*NH + h)*NT + t)*ND + cc] =
                    __floats2half2_rn(vx, vy);
            }
        }
    }
}

// ---------------------------------------------------------------------------
// Flash attention on fp16 tensor cores (unchanged from R10).
// grid = (NT/128, NB*NH), block = 128 (4 warps x 32 q-rows).
// ---------------------------------------------------------------------------
#define RS 72

__global__ __launch_bounds__(128) void attn_kernel(
    const int* __restrict__ mask, float* __restrict__ out)
{
    extern __shared__ __align__(16) char smraw[];
    __half* Qsh = (__half*)smraw;          // [128][RS]
    __half* Ksh = Qsh + 128*RS;            // [64][RS]
    __half* Vsh = Ksh + 64*RS;             // [64][RS]
    float*  maskf = (float*)(Vsh + 64*RS); // [64]

    const int tid  = threadIdx.x;
    const int warp = tid >> 5;
    const int lane = tid & 31;
    const int g    = lane >> 2;
    const int c    = lane & 3;
    const int wr   = warp * 32;

    const int bh = blockIdx.y;
    const int b  = bh >> 4;
    const int h  = bh & 15;
    const int q0 = blockIdx.x * 128;

    const __half* __restrict__ qb = g_q + (bh*NT + q0) * ND;
    const __half* __restrict__ kb = g_k + bh*NT*ND;
    const __half* __restrict__ vb = g_v + bh*NT*ND;
    const int*    __restrict__ mb = mask + b*NT;

    #pragma unroll
    for (int i = 0; i < 8; i++) {
        const int slot = tid + 128*i;
        const int r = slot >> 3, c8 = (slot & 7) * 8;
        *(uint4*)&Qsh[r*RS + c8] = *(const uint4*)&qb[r*ND + c8];
    }

    const int arow = (lane & 7) + ((lane >> 3) & 1) * 8;
    const int acol = (lane >> 4) * 8;
    const int brow = (lane & 7) + (lane >> 4) * 8;
    const int bcol = ((lane >> 3) & 1) * 8;
    const int vrow = ((lane >> 3) & 1) * 8 + (lane & 7);
    const int vcol = (lane >> 4) * 8;

    const uint32_t qa_b = (uint32_t)__cvta_generic_to_shared(
        &Qsh[(wr + arow)*RS + acol]);
    const uint32_t kb_b = (uint32_t)__cvta_generic_to_shared(
        &Ksh[brow*RS + bcol]);
    const uint32_t vb_b = (uint32_t)__cvta_generic_to_shared(
        &Vsh[vrow*RS + vcol]);
    const uint32_t MT16 = (uint32_t)(16*RS*2);

    __syncthreads();
    uint32_t aq[2][4][4];
    #pragma unroll
    for (int mt = 0; mt < 2; mt++)
        #pragma unroll
        for (int kt = 0; kt < 4; kt++)
            ldm_x4(aq[mt][kt], qa_b + (uint32_t)mt*MT16 + (uint32_t)(kt*32));

    float o[2][8][4] = {};
    float m_run[2][2] = {{-1e30f,-1e30f},{-1e30f,-1e30f}};
    float l_run[2][2] = {{0.f,0.f},{0.f,0.f}};

    for (int k0 = 0; k0 < NT; k0 += 64) {
        uint4 ka[4], va[4];
        #pragma unroll
        for (int i = 0; i < 4; i++) {
            const int slot = tid + 128*i;
            const int r = slot >> 3, c8 = (slot & 7) * 8;
            ka[i] = *(const uint4*)&kb[(k0 + r)*ND + c8];
            va[i] = *(const uint4*)&vb[(k0 + r)*ND + c8];
        }
        __syncthreads();
        #pragma unroll
        for (int i = 0; i < 4; i++) {
            const int slot = tid + 128*i;
            const int r = slot >> 3, c8 = (slot & 7) * 8;
            *(uint4*)&Ksh[r*RS + c8] = ka[i];
            *(uint4*)&Vsh[r*RS + c8] = va[i];
        }
        if (tid < 64) maskf[tid] = (mb[k0 + tid] > 0) ? 0.0f : -1e30f;
        __syncthreads();

        // ---- S = Q @ K^T ----
        float s[2][8][4] = {};
        #pragma unroll
        for (int kt = 0; kt < 4; kt++) {
            const uint32_t koff = (uint32_t)(kt * 32);
            #pragma unroll
            for (int np = 0; np < 4; np++) {
                uint32_t bbq[4];
                ldm_x4(bbq, kb_b + (uint32_t)np*MT16 + koff);
                mma_f16(s[0][2*np    ], aq[0][kt], &bbq[0]);
                mma_f16(s[1][2*np    ], aq[1][kt], &bbq[0]);
                mma_f16(s[0][2*np + 1], aq[0][kt], &bbq[2]);
                mma_f16(s[1][2*np + 1], aq[1][kt], &bbq[2]);
            }
        }

        // additive mask
        #pragma unroll
        for (int nt = 0; nt < 8; nt++) {
            float2 mf = *(const float2*)&maskf[nt*8 + 2*c];
            #pragma unroll
            for (int mt = 0; mt < 2; mt++) {
                s[mt][nt][0] += mf.x; s[mt][nt][1] += mf.y;
                s[mt][nt][2] += mf.x; s[mt][nt][3] += mf.y;
            }
        }

        // ---- online softmax ----
        #pragma unroll
        for (int mt = 0; mt < 2; mt++) {
            float alpha[2];
            #pragma unroll
            for (int rh = 0; rh < 2; rh++) {
                float rm = -1e30f;
                #pragma unroll
                for (int nt = 0; nt < 8; nt++)
                    rm = fmaxf(rm, fmaxf(s[mt][nt][rh*2], s[mt][nt][rh*2+1]));
                rm = fmaxf(rm, __shfl_xor_sync(0xffffffffu, rm, 1));
                rm = fmaxf(rm, __shfl_xor_sync(0xffffffffu, rm, 2));
                float mnew = fmaxf(m_run[mt][rh], rm);
                alpha[rh] = __expf(m_run[mt][rh] - mnew);
                m_run[mt][rh] = mnew;
                float rs = 0.f;
                #pragma unroll
                for (int nt = 0; nt < 8; nt++) {
                    float p0 = __expf(s[mt][nt][rh*2]   - mnew);
                    float p1 = __expf(s[mt][nt][rh*2+1] - mnew);
                    s[mt][nt][rh*2] = p0; s[mt][nt][rh*2+1] = p1;
                    rs += p0 + p1;
                }
                rs += __shfl_xor_sync(0xffffffffu, rs, 1);
                rs += __shfl_xor_sync(0xffffffffu, rs, 2);
                l_run[mt][rh] = l_run[mt][rh]*alpha[rh] + rs;
            }
            if (!__all_sync(0xffffffffu,
                            (alpha[0] == 1.0f) && (alpha[1] == 1.0f))) {
                #pragma unroll
                for (int nt = 0; nt < 8; nt++) {
                    o[mt][nt][0] *= alpha[0]; o[mt][nt][1] *= alpha[0];
                    o[mt][nt][2] *= alpha[1]; o[mt][nt][3] *= alpha[1];
                }
            }
        }

        // ---- O += P @ V ----
        #pragma unroll
        for (int kt = 0; kt < 4; kt++) {
            uint32_t a[2][4];
            #pragma unroll
            for (int mt = 0; mt < 2; mt++) {
                a[mt][0] = h2pack(s[mt][2*kt    ][0], s[mt][2*kt    ][1]);
                a[mt][1] = h2pack(s[mt][2*kt    ][2], s[mt][2*kt    ][3]);
                a[mt][2] = h2pack(s[mt][2*kt + 1][0], s[mt][2*kt + 1][1]);
                a[mt][3] = h2pack(s[mt][2*kt + 1][2], s[mt][2*kt + 1][3]);
            }
            #pragma unroll
            for (int nt2 = 0; nt2 < 4; nt2++) {
                uint32_t r0, r1, r2, r3;
                const uint32_t addr = vb_b + (uint32_t)(kt*16*RS + nt2*16) * 2;
                asm volatile(
                    "ldmatrix.sync.aligned.m8n8.x4.trans.shared.b16 "
                    "{%0,%1,%2,%3}, [%4];"
                    : "=r"(r0), "=r"(r1), "=r"(r2), "=r"(r3) : "r"(addr));
                uint32_t b0[2] = {r0, r1};
                uint32_t b1[2] = {r2, r3};
                mma_f16(o[0][nt2*2    ], a[0], b0);
                mma_f16(o[1][nt2*2    ], a[1], b0);
                mma_f16(o[0][nt2*2 + 1], a[0], b1);
                mma_f16(o[1][nt2*2 + 1], a[1], b1);
            }
        }
    }

    #pragma unroll
    for (int mt = 0; mt < 2; mt++) {
        const float inv0 = 1.0f / l_run[mt][0];
        const float inv1 = 1.0f / l_run[mt][1];
        const int t0 = q0 + wr + mt*16 + g;
        float* ob0 = out + (b*NT + t0    )*NC + h*ND;
        float* ob1 = out + (b*NT + t0 + 8)*NC + h*ND;
        #pragma unroll
        for (int nt = 0; nt < 8; nt++) {
            *(float2*)&ob0[nt*8 + 2*c] =
                make_float2(o[mt][nt][0]*inv0, o[mt][nt][1]*inv0);
            *(float2*)&ob1[nt*8 + 2*c] =
                make_float2(o[mt][nt][2]*inv1, o[mt][nt][3]*inv1);
        }
    }
}

// ---------------------------------------------------------------------------
extern "C" void kernel_launch(void* const* d_in, const int* in_sizes, int n_in,
                              void* d_out, int out_size)
{
    const float* x  = (const float*)d_in[0];
    const int* mask = (const int*)  d_in[1];
    const float* Wq = (const float*)d_in[2];
    const float* bq = (const float*)d_in[3];
    const float* Wk = (const float*)d_in[4];
    const float* bk = (const float*)d_in[5];
    const float* Wv = (const float*)d_in[6];
    const float* bv = (const float*)d_in[7];
    float* out = (float*)d_out;

    prep_x<<<NB*NT*NC/8/256, 256>>>(x);
    prep_w<<<dim3(NC*NC/8/256, 3), 256>>>(Wq, Wk, Wv);

    const int qkv_smem = 3 * 128 * QKST * 2;  // 30720
    cudaFuncSetAttribute(qkv_mma,
                         cudaFuncAttributeMaxDynamicSharedMemorySize, qkv_smem);
    qkv_mma<<<dim3(NC/128, (NB*NT)/128, 3), 256, qkv_smem>>>(bq, bk, bv);

    const int attn_smem = (128*RS + 64*RS + 64*RS) * 2 + 64 * 4;  // 37120
    cudaFuncSetAttribute(attn_kernel,
                         cudaFuncAttributeMaxDynamicSharedMemorySize, attn_smem);
    attn_kernel<<<dim3(NT/128, NB*NH), 128, attn_smem>>>(mask, out);
}

// round 12
// speedup vs baseline: 1.8878x; 1.0098x over previous
#include <cuda_runtime.h>
#include <cuda_fp16.h>
#include <cstdint>

#define NB 4
#define NT 2048
#define NC 1024
#define NH 16
#define ND 64

// Scratch: Q,K,V in [B,H,T,D] layout, fp16.
__device__ __half g_q[NB*NH*NT*ND];
__device__ __half g_k[NB*NH*NT*ND];
__device__ __half g_v[NB*NH*NT*ND];
// Preconverted inputs: x split into hi+lo fp16; W rounded to fp16.
__device__ __half g_xh[NB*NT*NC];
__device__ __half g_xl[NB*NT*NC];
__device__ __half g_wh[3*NC*NC];

__device__ __forceinline__ void mma_f16(float d[4], const uint32_t a[4],
                                        const uint32_t b[2]) {
    asm volatile(
        "mma.sync.aligned.m16n8k16.row.col.f32.f16.f16.f32 "
        "{%0,%1,%2,%3}, {%4,%5,%6,%7}, {%8,%9}, {%0,%1,%2,%3};"
        : "+f"(d[0]), "+f"(d[1]), "+f"(d[2]), "+f"(d[3])
        : "r"(a[0]), "r"(a[1]), "r"(a[2]), "r"(a[3]), "r"(b[0]), "r"(b[1]));
}

__device__ __forceinline__ void ldm_x4(uint32_t r[4], uint32_t addr) {
    asm volatile(
        "ldmatrix.sync.aligned.m8n8.x4.shared.b16 {%0,%1,%2,%3}, [%4];"
        : "=r"(r[0]), "=r"(r[1]), "=r"(r[2]), "=r"(r[3]) : "r"(addr));
}

__device__ __forceinline__ uint32_t h2pack(float x, float y) {
    __half2 h = __floats2half2_rn(x, y);
    return *(const uint32_t*)&h;
}

__device__ __forceinline__ void cp16(uint32_t dst, const void* src) {
    asm volatile("cp.async.cg.shared.global [%0], [%1], 16;"
                 :: "r"(dst), "l"(src));
}
__device__ __forceinline__ void cp_commit() {
    asm volatile("cp.async.commit_group;");
}
template <int N>
__device__ __forceinline__ void cp_wait() {
    asm volatile("cp.async.wait_group %0;" :: "n"(N));
}

// ---------------------------------------------------------------------------
// Prep: one-time fp32 -> fp16 conversions (memory-bound).
// ---------------------------------------------------------------------------
__global__ __launch_bounds__(256) void prep_x(const float* __restrict__ x)
{
    const int i8 = (blockIdx.x * 256 + threadIdx.x) * 8;
    float4 v0 = *(const float4*)&x[i8];
    float4 v1 = *(const float4*)&x[i8 + 4];
    const float v[8] = {v0.x,v0.y,v0.z,v0.w, v1.x,v1.y,v1.z,v1.w};
    __half2 hi[4], lo[4];
    #pragma unroll
    for (int p = 0; p < 4; p++) {
        __half h0 = __float2half_rn(v[2*p]);
        __half h1 = __float2half_rn(v[2*p + 1]);
        hi[p] = __halves2half2(h0, h1);
        lo[p] = __floats2half2_rn(v[2*p]     - __half2float(h0),
                                  v[2*p + 1] - __half2float(h1));
    }
    *(uint4*)&g_xh[i8] = *(const uint4*)hi;
    *(uint4*)&g_xl[i8] = *(const uint4*)lo;
}

__global__ __launch_bounds__(256) void prep_w(
    const float* __restrict__ Wq, const float* __restrict__ Wk,
    const float* __restrict__ Wv)
{
    const float* __restrict__ W =
        (blockIdx.y == 0) ? Wq : ((blockIdx.y == 1) ? Wk : Wv);
    const int i8 = (blockIdx.x * 256 + threadIdx.x) * 8;
    float4 v0 = *(const float4*)&W[i8];
    float4 v1 = *(const float4*)&W[i8 + 4];
    __half2 h[4];
    h[0] = __floats2half2_rn(v0.x, v0.y);
    h[1] = __floats2half2_rn(v0.z, v0.w);
    h[2] = __floats2half2_rn(v1.x, v1.y);
    h[3] = __floats2half2_rn(v1.z, v1.w);
    *(uint4*)&g_wh[blockIdx.y*NC*NC + i8] = *(const uint4*)h;
}

// ---------------------------------------------------------------------------
// QKV projection on fp16 tensor cores with split-activation compensation.
// R12: two-stage cp.async pipeline — tile i+1 loads overlap tile i compute.
// grid = (NC/128, (NB*NT)/128, 3), block = 256 (2 m-warp x 4 n-warp).
// ---------------------------------------------------------------------------
#define QKST 40
#define TILEB (128*QKST*2)     // bytes per matrix per stage
#define STAGEB (3*TILEB)       // bytes per stage (Ah,Al,Bs)

__global__ __launch_bounds__(256) void qkv_mma(
    const float* __restrict__ bq, const float* __restrict__ bk,
    const float* __restrict__ bv)
{
    extern __shared__ __align__(16) char smraw[];   // 2 stages

    const int z = blockIdx.z;
    const float* __restrict__ bias = (z == 0) ? bq : ((z == 1) ? bk : bv);
    const __half* __restrict__ Wh  = g_wh + z*NC*NC;
    __half* __restrict__ dst       = (z == 0) ? g_q : ((z == 1) ? g_k : g_v);
    const float scale = (z == 0) ? 0.125f : 1.0f;

    const int tid  = threadIdx.x;
    const int warp = tid >> 5;
    const int lane = tid & 31;
    const int g    = lane >> 2;
    const int c    = lane & 3;
    const int mw   = (warp & 1) * 64;
    const int nw   = (warp >> 1) * 32;

    const int m0 = blockIdx.y * 128;
    const int n0 = blockIdx.x * 128;

    const int srow = tid >> 1;          // 0..127
    const int scg  = (tid & 1) * 16;    // 0 or 16

    const uint32_t sm0 = (uint32_t)__cvta_generic_to_shared(smraw);
    // staging destinations (stage-relative byte offsets)
    const uint32_t st_row = (uint32_t)(srow*QKST + scg) * 2;

    // ldmatrix lane address components
    const int arow = (lane & 7) + ((lane >> 3) & 1) * 8;
    const int acol = (lane >> 4) * 8;
    const int brow = (lane & 7) + (lane >> 4) * 8;
    const int bcol = ((lane >> 3) & 1) * 8;
    const uint32_t ah_f = sm0 + (uint32_t)(((mw + arow)*QKST + acol) * 2);
    const uint32_t al_f = ah_f + TILEB;
    const uint32_t bs_f = sm0 + 2*TILEB +
        (uint32_t)(((nw + brow)*QKST + bcol) * 2);

    const __half* xh_p = &g_xh[(m0 + srow)*NC + scg];
    const __half* xl_p = &g_xl[(m0 + srow)*NC + scg];
    const __half* wh_p = &Wh  [(n0 + srow)*NC + scg];

    // issue tile k0 into stage s
    auto issue = [&](int s, int k0) {
        const uint32_t base = sm0 + (uint32_t)s*STAGEB + st_row;
        cp16(base,                  xh_p + k0);
        cp16(base + 16,             xh_p + k0 + 8);
        cp16(base + TILEB,          xl_p + k0);
        cp16(base + TILEB + 16,     xl_p + k0 + 8);
        cp16(base + 2*TILEB,        wh_p + k0);
        cp16(base + 2*TILEB + 16,   wh_p + k0 + 8);
        cp_commit();
    };

    float acc[4][4][4] = {};

    issue(0, 0);
    #pragma unroll 1
    for (int it = 0; it < NC/32; it++) {
        const int s = it & 1;
        if (it + 1 < NC/32) {
            issue(s ^ 1, (it + 1) * 32);
            cp_wait<1>();
        } else {
            cp_wait<0>();
        }
        __syncthreads();   // stage s data visible to all

        const uint32_t sb = (uint32_t)s*STAGEB;
        #pragma unroll
        for (int kc = 0; kc < 2; kc++) {
            const uint32_t koff = (uint32_t)(kc * 16 * 2);
            uint32_t bf[2][4];
            ldm_x4(bf[0], bs_f + sb + koff);
            ldm_x4(bf[1], bs_f + sb + (uint32_t)(16*QKST*2) + koff);
            #pragma unroll
            for (int mt = 0; mt < 4; mt++) {
                const uint32_t moff = (uint32_t)(mt * 16 * QKST * 2);
                uint32_t ah[4], al[4];
                ldm_x4(ah, ah_f + sb + moff + koff);
                ldm_x4(al, al_f + sb + moff + koff);
                #pragma unroll
                for (int np = 0; np < 2; np++) {
                    mma_f16(acc[mt][2*np    ], ah, &bf[np][0]);
                    mma_f16(acc[mt][2*np    ], al, &bf[np][0]);
                    mma_f16(acc[mt][2*np + 1], ah, &bf[np][2]);
                    mma_f16(acc[mt][2*np + 1], al, &bf[np][2]);
                }
            }
        }
        __syncthreads();   // stage s reads done before it gets overwritten
    }

    // Epilogue: bias + scale (fp32), round to fp16, scatter to [B,H,T,D]
    #pragma unroll
    for (int nt = 0; nt < 4; nt++) {
        const int col = n0 + nw + nt*8 + 2*c;
        float2 b2 = *(const float2*)&bias[col];
        const int h  = col >> 6;
        const int cc = col & 63;
        #pragma unroll
        for (int mt = 0; mt < 4; mt++) {
            #pragma unroll
            for (int rh = 0; rh < 2; rh++) {
                const int m = m0 + mw + mt*16 + g + rh*8;
                const int b = m >> 11;
                const int t = m & (NT - 1);
                const float vx = (acc[mt][nt][rh*2 + 0] + b2.x) * scale;
                const float vy = (acc[mt][nt][rh*2 + 1] + b2.y) * scale;
                *(__half2*)&dst[((b*NH + h)*NT + t)*ND + cc] =
                    __floats2half2_rn(vx, vy);
            }
        }
    }
}

// ---------------------------------------------------------------------------
// Flash attention on fp16 tensor cores (unchanged from R10/R11).
// grid = (NT/128, NB*NH), block = 128 (4 warps x 32 q-rows).
// ---------------------------------------------------------------------------
#define RS 72

__global__ __launch_bounds__(128) void attn_kernel(
    const int* __restrict__ mask, float* __restrict__ out)
{
    extern __shared__ __align__(16) char smraw[];
    __half* Qsh = (__half*)smraw;          // [128][RS]
    __half* Ksh = Qsh + 128*RS;            // [64][RS]
    __half* Vsh = Ksh + 64*RS;             // [64][RS]
    float*  maskf = (float*)(Vsh + 64*RS); // [64]

    const int tid  = threadIdx.x;
    const int warp = tid >> 5;
    const int lane = tid & 31;
    const int g    = lane >> 2;
    const int c    = lane & 3;
    const int wr   = warp * 32;

    const int bh = blockIdx.y;
    const int b  = bh >> 4;
    const int h  = bh & 15;
    const int q0 = blockIdx.x * 128;

    const __half* __restrict__ qb = g_q + (bh*NT + q0) * ND;
    const __half* __restrict__ kb = g_k + bh*NT*ND;
    const __half* __restrict__ vb = g_v + bh*NT*ND;
    const int*    __restrict__ mb = mask + b*NT;

    #pragma unroll
    for (int i = 0; i < 8; i++) {
        const int slot = tid + 128*i;
        const int r = slot >> 3, c8 = (slot & 7) * 8;
        *(uint4*)&Qsh[r*RS + c8] = *(const uint4*)&qb[r*ND + c8];
    }

    const int arow = (lane & 7) + ((lane >> 3) & 1) * 8;
    const int acol = (lane >> 4) * 8;
    const int brow = (lane & 7) + (lane >> 4) * 8;
    const int bcol = ((lane >> 3) & 1) * 8;
    const int vrow = ((lane >> 3) & 1) * 8 + (lane & 7);
    const int vcol = (lane >> 4) * 8;

    const uint32_t qa_b = (uint32_t)__cvta_generic_to_shared(
        &Qsh[(wr + arow)*RS + acol]);
    const uint32_t kb_b = (uint32_t)__cvta_generic_to_shared(
        &Ksh[brow*RS + bcol]);
    const uint32_t vb_b = (uint32_t)__cvta_generic_to_shared(
        &Vsh[vrow*RS + vcol]);
    const uint32_t MT16 = (uint32_t)(16*RS*2);

    __syncthreads();
    uint32_t aq[2][4][4];
    #pragma unroll
    for (int mt = 0; mt < 2; mt++)
        #pragma unroll
        for (int kt = 0; kt < 4; kt++)
            ldm_x4(aq[mt][kt], qa_b + (uint32_t)mt*MT16 + (uint32_t)(kt*32));

    float o[2][8][4] = {};
    float m_run[2][2] = {{-1e30f,-1e30f},{-1e30f,-1e30f}};
    float l_run[2][2] = {{0.f,0.f},{0.f,0.f}};

    for (int k0 = 0; k0 < NT; k0 += 64) {
        uint4 ka[4], va[4];
        #pragma unroll
        for (int i = 0; i < 4; i++) {
            const int slot = tid + 128*i;
            const int r = slot >> 3, c8 = (slot & 7) * 8;
            ka[i] = *(const uint4*)&kb[(k0 + r)*ND + c8];
            va[i] = *(const uint4*)&vb[(k0 + r)*ND + c8];
        }
        __syncthreads();
        #pragma unroll
        for (int i = 0; i < 4; i++) {
            const int slot = tid + 128*i;
            const int r = slot >> 3, c8 = (slot & 7) * 8;
            *(uint4*)&Ksh[r*RS + c8] = ka[i];
            *(uint4*)&Vsh[r*RS + c8] = va[i];
        }
        if (tid < 64) maskf[tid] = (mb[k0 + tid] > 0) ? 0.0f : -1e30f;
        __syncthreads();

        float s[2][8][4] = {};
        #pragma unroll
        for (int kt = 0; kt < 4; kt++) {
            const uint32_t koff = (uint32_t)(kt * 32);
            #pragma unroll
            for (int np = 0; np < 4; np++) {
                uint32_t bbq[4];
                ldm_x4(bbq, kb_b + (uint32_t)np*MT16 + koff);
                mma_f16(s[0][2*np    ], aq[0][kt], &bbq[0]);
                mma_f16(s[1][2*np    ], aq[1][kt], &bbq[0]);
                mma_f16(s[0][2*np + 1], aq[0][kt], &bbq[2]);
                mma_f16(s[1][2*np + 1], aq[1][kt], &bbq[2]);
            }
        }

        #pragma unroll
        for (int nt = 0; nt < 8; nt++) {
            float2 mf = *(const float2*)&maskf[nt*8 + 2*c];
            #pragma unroll
            for (int mt = 0; mt < 2; mt++) {
                s[mt][nt][0] += mf.x; s[mt][nt][1] += mf.y;
                s[mt][nt][2] += mf.x; s[mt][nt][3] += mf.y;
            }
        }

        #pragma unroll
        for (int mt = 0; mt < 2; mt++) {
            float alpha[2];
            #pragma unroll
            for (int rh = 0; rh < 2; rh++) {
                float rm = -1e30f;
                #pragma unroll
                for (int nt = 0; nt < 8; nt++)
                    rm = fmaxf(rm, fmaxf(s[mt][nt][rh*2], s[mt][nt][rh*2+1]));
                rm = fmaxf(rm, __shfl_xor_sync(0xffffffffu, rm, 1));
                rm = fmaxf(rm, __shfl_xor_sync(0xffffffffu, rm, 2));
                float mnew = fmaxf(m_run[mt][rh], rm);
                alpha[rh] = __expf(m_run[mt][rh] - mnew);
                m_run[mt][rh] = mnew;
                float rs = 0.f;
                #pragma unroll
                for (int nt = 0; nt < 8; nt++) {
                    float p0 = __expf(s[mt][nt][rh*2]   - mnew);
                    float p1 = __expf(s[mt][nt][rh*2+1] - mnew);
                    s[mt][nt][rh*2] = p0; s[mt][nt][rh*2+1] = p1;
                    rs += p0 + p1;
                }
                rs += __shfl_xor_sync(0xffffffffu, rs, 1);
                rs += __shfl_xor_sync(0xffffffffu, rs, 2);
                l_run[mt][rh] = l_run[mt][rh]*alpha[rh] + rs;
            }
            if (!__all_sync(0xffffffffu,
                            (alpha[0] == 1.0f) && (alpha[1] == 1.0f))) {
                #pragma unroll
                for (int nt = 0; nt < 8; nt++) {
                    o[mt][nt][0] *= alpha[0]; o[mt][nt][1] *= alpha[0];
                    o[mt][nt][2] *= alpha[1]; o[mt][nt][3] *= alpha[1];
                }
            }
        }

        #pragma unroll
        for (int kt = 0; kt < 4; kt++) {
            uint32_t a[2][4];
            #pragma unroll
            for (int mt = 0; mt < 2; mt++) {
                a[mt][0] = h2pack(s[mt][2*kt    ][0], s[mt][2*kt    ][1]);
                a[mt][1] = h2pack(s[mt][2*kt    ][2], s[mt][2*kt    ][3]);
                a[mt][2] = h2pack(s[mt][2*kt + 1][0], s[mt][2*kt + 1][1]);
                a[mt][3] = h2pack(s[mt][2*kt + 1][2], s[mt][2*kt + 1][3]);
            }
            #pragma unroll
            for (int nt2 = 0; nt2 < 4; nt2++) {
                uint32_t r0, r1, r2, r3;
                const uint32_t addr = vb_b + (uint32_t)(kt*16*RS + nt2*16) * 2;
                asm volatile(
                    "ldmatrix.sync.aligned.m8n8.x4.trans.shared.b16 "
                    "{%0,%1,%2,%3}, [%4];"
                    : "=r"(r0), "=r"(r1), "=r"(r2), "=r"(r3) : "r"(addr));
                uint32_t b0[2] = {r0, r1};
                uint32_t b1[2] = {r2, r3};
                mma_f16(o[0][nt2*2    ], a[0], b0);
                mma_f16(o[1][nt2*2    ], a[1], b0);
                mma_f16(o[0][nt2*2 + 1], a[0], b1);
                mma_f16(o[1][nt2*2 + 1], a[1], b1);
            }
        }
    }

    #pragma unroll
    for (int mt = 0; mt < 2; mt++) {
        const float inv0 = 1.0f / l_run[mt][0];
        const float inv1 = 1.0f / l_run[mt][1];
        const int t0 = q0 + wr + mt*16 + g;
        float* ob0 = out + (b*NT + t0    )*NC + h*ND;
        float* ob1 = out + (b*NT + t0 + 8)*NC + h*ND;
        #pragma unroll
        for (int nt = 0; nt < 8; nt++) {
            *(float2*)&ob0[nt*8 + 2*c] =
                make_float2(o[mt][nt][0]*inv0, o[mt][nt][1]*inv0);
            *(float2*)&ob1[nt*8 + 2*c] =
                make_float2(o[mt][nt][2]*inv1, o[mt][nt][3]*inv1);
        }
    }
}

// ---------------------------------------------------------------------------
extern "C" void kernel_launch(void* const* d_in, const int* in_sizes, int n_in,
                              void* d_out, int out_size)
{
    const float* x  = (const float*)d_in[0];
    const int* mask = (const int*)  d_in[1];
    const float* Wq = (const float*)d_in[2];
    const float* bq = (const float*)d_in[3];
    const float* Wk = (const float*)d_in[4];
    const float* bk = (const float*)d_in[5];
    const float* Wv = (const float*)d_in[6];
    const float* bv = (const float*)d_in[7];
    float* out = (float*)d_out;

    prep_x<<<NB*NT*NC/8/256, 256>>>(x);
    prep_w<<<dim3(NC*NC/8/256, 3), 256>>>(Wq, Wk, Wv);

    const int qkv_smem = 2 * STAGEB;          // 61440
    cudaFuncSetAttribute(qkv_mma,
                         cudaFuncAttributeMaxDynamicSharedMemorySize, qkv_smem);
    qkv_mma<<<dim3(NC/128, (NB*NT)/128, 3), 256, qkv_smem>>>(bq, bk, bv);

    const int attn_smem = (128*RS + 64*RS + 64*RS) * 2 + 64 * 4;  // 37120
    cudaFuncSetAttribute(attn_kernel,
                         cudaFuncAttributeMaxDynamicSharedMemorySize, attn_smem);
    attn_kernel<<<dim3(NT/128, NB*NH), 128, attn_smem>>>(mask, out);
}

// round 13
// speedup vs baseline: 2.5364x; 1.3436x over previous
#include <cuda_runtime.h>
#include <cuda_fp16.h>
#include <cstdint>

#define NB 4
#define NT 2048
#define NC 1024
#define NH 16
#define ND 64

// Scratch: Q,K,V in [B,H,T,D] layout, fp16.
__device__ __half g_q[NB*NH*NT*ND];
__device__ __half g_k[NB*NH*NT*ND];
__device__ __half g_v[NB*NH*NT*ND];
// Preconverted inputs: x and W rounded once to fp16.
__device__ __half g_xh[NB*NT*NC];
__device__ __half g_wh[3*NC*NC];

__device__ __forceinline__ void mma_f16(float d[4], const uint32_t a[4],
                                        const uint32_t b[2]) {
    asm volatile(
        "mma.sync.aligned.m16n8k16.row.col.f32.f16.f16.f32 "
        "{%0,%1,%2,%3}, {%4,%5,%6,%7}, {%8,%9}, {%0,%1,%2,%3};"
        : "+f"(d[0]), "+f"(d[1]), "+f"(d[2]), "+f"(d[3])
        : "r"(a[0]), "r"(a[1]), "r"(a[2]), "r"(a[3]), "r"(b[0]), "r"(b[1]));
}

__device__ __forceinline__ void ldm_x4(uint32_t r[4], uint32_t addr) {
    asm volatile(
        "ldmatrix.sync.aligned.m8n8.x4.shared.b16 {%0,%1,%2,%3}, [%4];"
        : "=r"(r[0]), "=r"(r[1]), "=r"(r[2]), "=r"(r[3]) : "r"(addr));
}

__device__ __forceinline__ uint32_t h2pack(float x, float y) {
    __half2 h = __floats2half2_rn(x, y);
    return *(const uint32_t*)&h;
}

__device__ __forceinline__ void cp16(uint32_t dst, const void* src) {
    asm volatile("cp.async.cg.shared.global [%0], [%1], 16;"
                 :: "r"(dst), "l"(src));
}
__device__ __forceinline__ void cp_commit() {
    asm volatile("cp.async.commit_group;");
}
template <int N>
__device__ __forceinline__ void cp_wait() {
    asm volatile("cp.async.wait_group %0;" :: "n"(N));
}

// ---------------------------------------------------------------------------
// Prep: one-time fp32 -> fp16 conversions (memory-bound).
// ---------------------------------------------------------------------------
__global__ __launch_bounds__(256) void prep_x(const float* __restrict__ x)
{
    const int i8 = (blockIdx.x * 256 + threadIdx.x) * 8;
    float4 v0 = *(const float4*)&x[i8];
    float4 v1 = *(const float4*)&x[i8 + 4];
    __half2 h[4];
    h[0] = __floats2half2_rn(v0.x, v0.y);
    h[1] = __floats2half2_rn(v0.z, v0.w);
    h[2] = __floats2half2_rn(v1.x, v1.y);
    h[3] = __floats2half2_rn(v1.z, v1.w);
    *(uint4*)&g_xh[i8] = *(const uint4*)h;
}

__global__ __launch_bounds__(256) void prep_w(
    const float* __restrict__ Wq, const float* __restrict__ Wk,
    const float* __restrict__ Wv)
{
    const float* __restrict__ W =
        (blockIdx.y == 0) ? Wq : ((blockIdx.y == 1) ? Wk : Wv);
    const int i8 = (blockIdx.x * 256 + threadIdx.x) * 8;
    float4 v0 = *(const float4*)&W[i8];
    float4 v1 = *(const float4*)&W[i8 + 4];
    __half2 h[4];
    h[0] = __floats2half2_rn(v0.x, v0.y);
    h[1] = __floats2half2_rn(v0.z, v0.w);
    h[2] = __floats2half2_rn(v1.x, v1.y);
    h[3] = __floats2half2_rn(v1.z, v1.w);
    *(uint4*)&g_wh[blockIdx.y*NC*NC + i8] = *(const uint4*)h;
}

// ---------------------------------------------------------------------------
// QKV projection on fp16 tensor cores. R13: single-MMA (compensation dropped
// -- error budget allows it). Two-stage cp.async pipeline.
// grid = (NC/128, (NB*NT)/128, 3), block = 256 (2 m-warp x 4 n-warp).
// ---------------------------------------------------------------------------
#define QKST 40
#define TILEB (128*QKST*2)     // bytes per matrix per stage
#define STAGEB (2*TILEB)       // bytes per stage (A, B)

__global__ __launch_bounds__(256) void qkv_mma(
    const float* __restrict__ bq, const float* __restrict__ bk,
    const float* __restrict__ bv)
{
    extern __shared__ __align__(16) char smraw[];   // 2 stages

    const int z = blockIdx.z;
    const float* __restrict__ bias = (z == 0) ? bq : ((z == 1) ? bk : bv);
    const __half* __restrict__ Wh  = g_wh + z*NC*NC;
    __half* __restrict__ dst       = (z == 0) ? g_q : ((z == 1) ? g_k : g_v);
    const float scale = (z == 0) ? 0.125f : 1.0f;

    const int tid  = threadIdx.x;
    const int warp = tid >> 5;
    const int lane = tid & 31;
    const int g    = lane >> 2;
    const int c    = lane & 3;
    const int mw   = (warp & 1) * 64;
    const int nw   = (warp >> 1) * 32;

    const int m0 = blockIdx.y * 128;
    const int n0 = blockIdx.x * 128;

    const int srow = tid >> 1;          // 0..127
    const int scg  = (tid & 1) * 16;    // 0 or 16

    const uint32_t sm0 = (uint32_t)__cvta_generic_to_shared(smraw);
    const uint32_t st_row = (uint32_t)(srow*QKST + scg) * 2;

    const int arow = (lane & 7) + ((lane >> 3) & 1) * 8;
    const int acol = (lane >> 4) * 8;
    const int brow = (lane & 7) + (lane >> 4) * 8;
    const int bcol = ((lane >> 3) & 1) * 8;
    const uint32_t ah_f = sm0 + (uint32_t)(((mw + arow)*QKST + acol) * 2);
    const uint32_t bs_f = sm0 + TILEB +
        (uint32_t)(((nw + brow)*QKST + bcol) * 2);

    const __half* xh_p = &g_xh[(m0 + srow)*NC + scg];
    const __half* wh_p = &Wh  [(n0 + srow)*NC + scg];

    auto issue = [&](int s, int k0) {
        const uint32_t base = sm0 + (uint32_t)s*STAGEB + st_row;
        cp16(base,              xh_p + k0);
        cp16(base + 16,         xh_p + k0 + 8);
        cp16(base + TILEB,      wh_p + k0);
        cp16(base + TILEB + 16, wh_p + k0 + 8);
        cp_commit();
    };

    float acc[4][4][4] = {};

    issue(0, 0);
    #pragma unroll 1
    for (int it = 0; it < NC/32; it++) {
        const int s = it & 1;
        if (it + 1 < NC/32) {
            issue(s ^ 1, (it + 1) * 32);
            cp_wait<1>();
        } else {
            cp_wait<0>();
        }
        __syncthreads();

        const uint32_t sb = (uint32_t)s*STAGEB;
        #pragma unroll
        for (int kc = 0; kc < 2; kc++) {
            const uint32_t koff = (uint32_t)(kc * 16 * 2);
            uint32_t bf[2][4];
            ldm_x4(bf[0], bs_f + sb + koff);
            ldm_x4(bf[1], bs_f + sb + (uint32_t)(16*QKST*2) + koff);
            #pragma unroll
            for (int mt = 0; mt < 4; mt++) {
                const uint32_t moff = (uint32_t)(mt * 16 * QKST * 2);
                uint32_t ah[4];
                ldm_x4(ah, ah_f + sb + moff + koff);
                #pragma unroll
                for (int np = 0; np < 2; np++) {
                    mma_f16(acc[mt][2*np    ], ah, &bf[np][0]);
                    mma_f16(acc[mt][2*np + 1], ah, &bf[np][2]);
                }
            }
        }
        __syncthreads();
    }

    // Epilogue: bias + scale (fp32), round to fp16, scatter to [B,H,T,D]
    #pragma unroll
    for (int nt = 0; nt < 4; nt++) {
        const int col = n0 + nw + nt*8 + 2*c;
        float2 b2 = *(const float2*)&bias[col];
        const int h  = col >> 6;
        const int cc = col & 63;
        #pragma unroll
        for (int mt = 0; mt < 4; mt++) {
            #pragma unroll
            for (int rh = 0; rh < 2; rh++) {
                const int m = m0 + mw + mt*16 + g + rh*8;
                const int b = m >> 11;
                const int t = m & (NT - 1);
                const float vx = (acc[mt][nt][rh*2 + 0] + b2.x) * scale;
                const float vy = (acc[mt][nt][rh*2 + 1] + b2.y) * scale;
                *(__half2*)&dst[((b*NH + h)*NT + t)*ND + cc] =
                    __floats2half2_rn(vx, vy);
            }
        }
    }
}

// ---------------------------------------------------------------------------
// Flash attention on fp16 tensor cores (unchanged from R10-R12).
// grid = (NT/128, NB*NH), block = 128 (4 warps x 32 q-rows).
// ---------------------------------------------------------------------------
#define RS 72

__global__ __launch_bounds__(128) void attn_kernel(
    const int* __restrict__ mask, float* __restrict__ out)
{
    extern __shared__ __align__(16) char smraw[];
    __half* Qsh = (__half*)smraw;          // [128][RS]
    __half* Ksh = Qsh + 128*RS;            // [64][RS]
    __half* Vsh = Ksh + 64*RS;             // [64][RS]
    float*  maskf = (float*)(Vsh + 64*RS); // [64]

    const int tid  = threadIdx.x;
    const int warp = tid >> 5;
    const int lane = tid & 31;
    const int g    = lane >> 2;
    const int c    = lane & 3;
    const int wr   = warp * 32;

    const int bh = blockIdx.y;
    const int b  = bh >> 4;
    const int h  = bh & 15;
    const int q0 = blockIdx.x * 128;

    const __half* __restrict__ qb = g_q + (bh*NT + q0) * ND;
    const __half* __restrict__ kb = g_k + bh*NT*ND;
    const __half* __restrict__ vb = g_v + bh*NT*ND;
    const int*    __restrict__ mb = mask + b*NT;

    #pragma unroll
    for (int i = 0; i < 8; i++) {
        const int slot = tid + 128*i;
        const int r = slot >> 3, c8 = (slot & 7) * 8;
        *(uint4*)&Qsh[r*RS + c8] = *(const uint4*)&qb[r*ND + c8];
    }

    const int arow = (lane & 7) + ((lane >> 3) & 1) * 8;
    const int acol = (lane >> 4) * 8;
    const int brow = (lane & 7) + (lane >> 4) * 8;
    const int bcol = ((lane >> 3) & 1) * 8;
    const int vrow = ((lane >> 3) & 1) * 8 + (lane & 7);
    const int vcol = (lane >> 4) * 8;

    const uint32_t qa_b = (uint32_t)__cvta_generic_to_shared(
        &Qsh[(wr + arow)*RS + acol]);
    const uint32_t kb_b = (uint32_t)__cvta_generic_to_shared(
        &Ksh[brow*RS + bcol]);
    const uint32_t vb_b = (uint32_t)__cvta_generic_to_shared(
        &Vsh[vrow*RS + vcol]);
    const uint32_t MT16 = (uint32_t)(16*RS*2);

    __syncthreads();
    uint32_t aq[2][4][4];
    #pragma unroll
    for (int mt = 0; mt < 2; mt++)
        #pragma unroll
        for (int kt = 0; kt < 4; kt++)
            ldm_x4(aq[mt][kt], qa_b + (uint32_t)mt*MT16 + (uint32_t)(kt*32));

    float o[2][8][4] = {};
    float m_run[2][2] = {{-1e30f,-1e30f},{-1e30f,-1e30f}};
    float l_run[2][2] = {{0.f,0.f},{0.f,0.f}};

    for (int k0 = 0; k0 < NT; k0 += 64) {
        uint4 ka[4], va[4];
        #pragma unroll
        for (int i = 0; i < 4; i++) {
            const int slot = tid + 128*i;
            const int r = slot >> 3, c8 = (slot & 7) * 8;
            ka[i] = *(const uint4*)&kb[(k0 + r)*ND + c8];
            va[i] = *(const uint4*)&vb[(k0 + r)*ND + c8];
        }
        __syncthreads();
        #pragma unroll
        for (int i = 0; i < 4; i++) {
            const int slot = tid + 128*i;
            const int r = slot >> 3, c8 = (slot & 7) * 8;
            *(uint4*)&Ksh[r*RS + c8] = ka[i];
            *(uint4*)&Vsh[r*RS + c8] = va[i];
        }
        if (tid < 64) maskf[tid] = (mb[k0 + tid] > 0) ? 0.0f : -1e30f;
        __syncthreads();

        float s[2][8][4] = {};
        #pragma unroll
        for (int kt = 0; kt < 4; kt++) {
            const uint32_t koff = (uint32_t)(kt * 32);
            #pragma unroll
            for (int np = 0; np < 4; np++) {
                uint32_t bbq[4];
                ldm_x4(bbq, kb_b + (uint32_t)np*MT16 + koff);
                mma_f16(s[0][2*np    ], aq[0][kt], &bbq[0]);
                mma_f16(s[1][2*np    ], aq[1][kt], &bbq[0]);
                mma_f16(s[0][2*np + 1], aq[0][kt], &bbq[2]);
                mma_f16(s[1][2*np + 1], aq[1][kt], &bbq[2]);
            }
        }

        #pragma unroll
        for (int nt = 0; nt < 8; nt++) {
            float2 mf = *(const float2*)&maskf[nt*8 + 2*c];
            #pragma unroll
            for (int mt = 0; mt < 2; mt++) {
                s[mt][nt][0] += mf.x; s[mt][nt][1] += mf.y;
                s[mt][nt][2] += mf.x; s[mt][nt][3] += mf.y;
            }
        }

        #pragma unroll
        for (int mt = 0; mt < 2; mt++) {
            float alpha[2];
            #pragma unroll
            for (int rh = 0; rh < 2; rh++) {
                float rm = -1e30f;
                #pragma unroll
                for (int nt = 0; nt < 8; nt++)
                    rm = fmaxf(rm, fmaxf(s[mt][nt][rh*2], s[mt][nt][rh*2+1]));
                rm = fmaxf(rm, __shfl_xor_sync(0xffffffffu, rm, 1));
                rm = fmaxf(rm, __shfl_xor_sync(0xffffffffu, rm, 2));
                float mnew = fmaxf(m_run[mt][rh], rm);
                alpha[rh] = __expf(m_run[mt][rh] - mnew);
                m_run[mt][rh] = mnew;
                float rs = 0.f;
                #pragma unroll
                for (int nt = 0; nt < 8; nt++) {
                    float p0 = __expf(s[mt][nt][rh*2]   - mnew);
                    float p1 = __expf(s[mt][nt][rh*2+1] - mnew);
                    s[mt][nt][rh*2] = p0; s[mt][nt][rh*2+1] = p1;
                    rs += p0 + p1;
                }
                rs += __shfl_xor_sync(0xffffffffu, rs, 1);
                rs += __shfl_xor_sync(0xffffffffu, rs, 2);
                l_run[mt][rh] = l_run[mt][rh]*alpha[rh] + rs;
            }
            if (!__all_sync(0xffffffffu,
                            (alpha[0] == 1.0f) && (alpha[1] == 1.0f))) {
                #pragma unroll
                for (int nt = 0; nt < 8; nt++) {
                    o[mt][nt][0] *= alpha[0]; o[mt][nt][1] *= alpha[0];
                    o[mt][nt][2] *= alpha[1]; o[mt][nt][3] *= alpha[1];
                }
            }
        }

        #pragma unroll
        for (int kt = 0; kt < 4; kt++) {
            uint32_t a[2][4];
            #pragma unroll
            for (int mt = 0; mt < 2; mt++) {
                a[mt][0] = h2pack(s[mt][2*kt    ][0], s[mt][2*kt    ][1]);
                a[mt][1] = h2pack(s[mt][2*kt    ][2], s[mt][2*kt    ][3]);
                a[mt][2] = h2pack(s[mt][2*kt + 1][0], s[mt][2*kt + 1][1]);
                a[mt][3] = h2pack(s[mt][2*kt + 1][2], s[mt][2*kt + 1][3]);
            }
            #pragma unroll
            for (int nt2 = 0; nt2 < 4; nt2++) {
                uint32_t r0, r1, r2, r3;
                const uint32_t addr = vb_b + (uint32_t)(kt*16*RS + nt2*16) * 2;
                asm volatile(
                    "ldmatrix.sync.aligned.m8n8.x4.trans.shared.b16 "
                    "{%0,%1,%2,%3}, [%4];"
                    : "=r"(r0), "=r"(r1), "=r"(r2), "=r"(r3) : "r"(addr));
                uint32_t b0[2] = {r0, r1};
                uint32_t b1[2] = {r2, r3};
                mma_f16(o[0][nt2*2    ], a[0], b0);
                mma_f16(o[1][nt2*2    ], a[1], b0);
                mma_f16(o[0][nt2*2 + 1], a[0], b1);
                mma_f16(o[1][nt2*2 + 1], a[1], b1);
            }
        }
    }

    #pragma unroll
    for (int mt = 0; mt < 2; mt++) {
        const float inv0 = 1.0f / l_run[mt][0];
        const float inv1 = 1.0f / l_run[mt][1];
        const int t0 = q0 + wr + mt*16 + g;
        float* ob0 = out + (b*NT + t0    )*NC + h*ND;
        float* ob1 = out + (b*NT + t0 + 8)*NC + h*ND;
        #pragma unroll
        for (int nt = 0; nt < 8; nt++) {
            *(float2*)&ob0[nt*8 + 2*c] =
                make_float2(o[mt][nt][0]*inv0, o[mt][nt][1]*inv0);
            *(float2*)&ob1[nt*8 + 2*c] =
                make_float2(o[mt][nt][2]*inv1, o[mt][nt][3]*inv1);
        }
    }
}

// ---------------------------------------------------------------------------
extern "C" void kernel_launch(void* const* d_in, const int* in_sizes, int n_in,
                              void* d_out, int out_size)
{
    const float* x  = (const float*)d_in[0];
    const int* mask = (const int*)  d_in[1];
    const float* Wq = (const float*)d_in[2];
    const float* bq = (const float*)d_in[3];
    const float* Wk = (const float*)d_in[4];
    const float* bk = (const float*)d_in[5];
    const float* Wv = (const float*)d_in[6];
    const float* bv = (const float*)d_in[7];
    float* out = (float*)d_out;

    prep_x<<<NB*NT*NC/8/256, 256>>>(x);
    prep_w<<<dim3(NC*NC/8/256, 3), 256>>>(Wq, Wk, Wv);

    const int qkv_smem = 2 * STAGEB;          // 40960
    cudaFuncSetAttribute(qkv_mma,
                         cudaFuncAttributeMaxDynamicSharedMemorySize, qkv_smem);
    qkv_mma<<<dim3(NC/128, (NB*NT)/128, 3), 256, qkv_smem>>>(bq, bk, bv);

    const int attn_smem = (128*RS + 64*RS + 64*RS) * 2 + 64 * 4;  // 37120
    cudaFuncSetAttribute(attn_kernel,
                         cudaFuncAttributeMaxDynamicSharedMemorySize, attn_smem);
    attn_kernel<<<dim3(NT/128, NB*NH), 128, attn_smem>>>(mask, out);
}

// round 15
// speedup vs baseline: 3.2921x; 1.2980x over previous
#include <cuda_runtime.h>
#include <cuda_fp16.h>
#include <cstdint>

#define NB 4
#define NT 2048
#define NC 1024
#define NH 16
#define ND 64

// Scratch: Q full [B,H,T,D]; K,V COMPACTED along T per batch (valid keys
// first, zero pad after — pad region never written, device globals zero-init).
__device__ __half g_q[NB*NH*NT*ND];
__device__ __half g_k[NB*NH*NT*ND];
__device__ __half g_v[NB*NH*NT*ND];
// Preconverted inputs: x and W rounded once to fp16.
__device__ __half g_xh[NB*NT*NC];
__device__ __half g_wh[3*NC*NC];
// Mask compaction: rank[b*NT+t] = compacted index or -1; cnt[b] = #valid.
__device__ int g_rank[NB*NT];
__device__ int g_cnt[NB];

__device__ __forceinline__ void mma_f16(float d[4], const uint32_t a[4],
                                        const uint32_t b[2]) {
    asm volatile(
        "mma.sync.aligned.m16n8k16.row.col.f32.f16.f16.f32 "
        "{%0,%1,%2,%3}, {%4,%5,%6,%7}, {%8,%9}, {%0,%1,%2,%3};"
        : "+f"(d[0]), "+f"(d[1]), "+f"(d[2]), "+f"(d[3])
        : "r"(a[0]), "r"(a[1]), "r"(a[2]), "r"(a[3]), "r"(b[0]), "r"(b[1]));
}

__device__ __forceinline__ void ldm_x4(uint32_t r[4], uint32_t addr) {
    asm volatile(
        "ldmatrix.sync.aligned.m8n8.x4.shared.b16 {%0,%1,%2,%3}, [%4];"
        : "=r"(r[0]), "=r"(r[1]), "=r"(r[2]), "=r"(r[3]) : "r"(addr));
}

__device__ __forceinline__ uint32_t h2pack(float x, float y) {
    __half2 h = __floats2half2_rn(x, y);
    return *(const uint32_t*)&h;
}

__device__ __forceinline__ void cp16(uint32_t dst, const void* src) {
    asm volatile("cp.async.cg.shared.global [%0], [%1], 16;"
                 :: "r"(dst), "l"(src));
}
__device__ __forceinline__ void cp_commit() {
    asm volatile("cp.async.commit_group;");
}
template <int N>
__device__ __forceinline__ void cp_wait() {
    asm volatile("cp.async.wait_group %0;" :: "n"(N));
}

// ---------------------------------------------------------------------------
// Mask scan: per batch, compacted rank for each valid key + count.
// grid = NB, block = 256 (8 keys/thread).
// ---------------------------------------------------------------------------
__global__ __launch_bounds__(256) void mask_scan(const int* __restrict__ mask)
{
    __shared__ int cnts[256];
    const int b   = blockIdx.x;
    const int tid = threadIdx.x;
    const int* mb = mask + b*NT;
    const int t0  = tid * 8;

    int loc[8]; int c = 0;
    #pragma unroll
    for (int j = 0; j < 8; j++) { loc[j] = (mb[t0 + j] > 0); c += loc[j]; }
    cnts[tid] = c;
    __syncthreads();
    // inclusive Hillis-Steele scan
    #pragma unroll
    for (int off = 1; off < 256; off <<= 1) {
        int u = (tid >= off) ? cnts[tid - off] : 0;
        __syncthreads();
        cnts[tid] += u;
        __syncthreads();
    }
    int base = cnts[tid] - c;   // exclusive prefix
    #pragma unroll
    for (int j = 0; j < 8; j++) {
        g_rank[b*NT + t0 + j] = loc[j] ? base : -1;
        base += loc[j];
    }
    if (tid == 255) g_cnt[b] = cnts[255];
}

// ---------------------------------------------------------------------------
// Prep: one-time fp32 -> fp16 conversions (memory-bound).
// ---------------------------------------------------------------------------
__global__ __launch_bounds__(256) void prep_x(const float* __restrict__ x)
{
    const int i8 = (blockIdx.x * 256 + threadIdx.x) * 8;
    float4 v0 = *(const float4*)&x[i8];
    float4 v1 = *(const float4*)&x[i8 + 4];
    __half2 h[4];
    h[0] = __floats2half2_rn(v0.x, v0.y);
    h[1] = __floats2half2_rn(v0.z, v0.w);
    h[2] = __floats2half2_rn(v1.x, v1.y);
    h[3] = __floats2half2_rn(v1.z, v1.w);
    *(uint4*)&g_xh[i8] = *(const uint4*)h;
}

__global__ __launch_bounds__(256) void prep_w(
    const float* __restrict__ Wq, const float* __restrict__ Wk,
    const float* __restrict__ Wv)
{
    const float* __restrict__ W =
        (blockIdx.y == 0) ? Wq : ((blockIdx.y == 1) ? Wk : Wv);
    const int i8 = (blockIdx.x * 256 + threadIdx.x) * 8;
    float4 v0 = *(const float4*)&W[i8];
    float4 v1 = *(const float4*)&W[i8 + 4];
    __half2 h[4];
    h[0] = __floats2half2_rn(v0.x, v0.y);
    h[1] = __floats2half2_rn(v0.z, v0.w);
    h[2] = __floats2half2_rn(v1.x, v1.y);
    h[3] = __floats2half2_rn(v1.z, v1.w);
    *(uint4*)&g_wh[blockIdx.y*NC*NC + i8] = *(const uint4*)h;
}

// ---------------------------------------------------------------------------
// QKV projection on fp16 tensor cores (single-MMA, cp.async 2-stage — R13).
// R15: K/V rows scattered to COMPACTED positions (masked rows skipped).
// grid = (NC/128, (NB*NT)/128, 3), block = 256 (2 m-warp x 4 n-warp).
// ---------------------------------------------------------------------------
#define QKST 40
#define TILEB (128*QKST*2)
#define STAGEB (2*TILEB)

__global__ __launch_bounds__(256) void qkv_mma(
    const float* __restrict__ bq, const float* __restrict__ bk,
    const float* __restrict__ bv)
{
    extern __shared__ __align__(16) char smraw[];

    const int z = blockIdx.z;
    const float* __restrict__ bias = (z == 0) ? bq : ((z == 1) ? bk : bv);
    const __half* __restrict__ Wh  = g_wh + z*NC*NC;
    __half* __restrict__ dst       = (z == 0) ? g_q : ((z == 1) ? g_k : g_v);
    const float scale = (z == 0) ? 0.125f : 1.0f;

    const int tid  = threadIdx.x;
    const int warp = tid >> 5;
    const int lane = tid & 31;
    const int g    = lane >> 2;
    const int c    = lane & 3;
    const int mw   = (warp & 1) * 64;
    const int nw   = (warp >> 1) * 32;

    const int m0 = blockIdx.y * 128;
    const int n0 = blockIdx.x * 128;

    const int srow = tid >> 1;
    const int scg  = (tid & 1) * 16;

    const uint32_t sm0 = (uint32_t)__cvta_generic_to_shared(smraw);
    const uint32_t st_row = (uint32_t)(srow*QKST + scg) * 2;

    const int arow = (lane & 7) + ((lane >> 3) & 1) * 8;
    const int acol = (lane >> 4) * 8;
    const int brow = (lane & 7) + (lane >> 4) * 8;
    const int bcol = ((lane >> 3) & 1) * 8;
    const uint32_t ah_f = sm0 + (uint32_t)(((mw + arow)*QKST + acol) * 2);
    const uint32_t bs_f = sm0 + TILEB +
        (uint32_t)(((nw + brow)*QKST + bcol) * 2);

    const __half* xh_p = &g_xh[(m0 + srow)*NC + scg];
    const __half* wh_p = &Wh  [(n0 + srow)*NC + scg];

    auto issue = [&](int s, int k0) {
        const uint32_t base = sm0 + (uint32_t)s*STAGEB + st_row;
        cp16(base,              xh_p + k0);
        cp16(base + 16,         xh_p + k0 + 8);
        cp16(base + TILEB,      wh_p + k0);
        cp16(base + TILEB + 16, wh_p + k0 + 8);
        cp_commit();
    };

    float acc[4][4][4] = {};

    issue(0, 0);
    #pragma unroll 1
    for (int it = 0; it < NC/32; it++) {
        const int s = it & 1;
        if (it + 1 < NC/32) {
            issue(s ^ 1, (it + 1) * 32);
            cp_wait<1>();
        } else {
            cp_wait<0>();
        }
        __syncthreads();

        const uint32_t sb = (uint32_t)s*STAGEB;
        #pragma unroll
        for (int kc = 0; kc < 2; kc++) {
            const uint32_t koff = (uint32_t)(kc * 16 * 2);
            uint32_t bf[2][4];
            ldm_x4(bf[0], bs_f + sb + koff);
            ldm_x4(bf[1], bs_f + sb + (uint32_t)(16*QKST*2) + koff);
            #pragma unroll
            for (int mt = 0; mt < 4; mt++) {
                const uint32_t moff = (uint32_t)(mt * 16 * QKST * 2);
                uint32_t ah[4];
                ldm_x4(ah, ah_f + sb + moff + koff);
                #pragma unroll
                for (int np = 0; np < 2; np++) {
                    mma_f16(acc[mt][2*np    ], ah, &bf[np][0]);
                    mma_f16(acc[mt][2*np + 1], ah, &bf[np][2]);
                }
            }
        }
        __syncthreads();
    }

    // Epilogue: bias + scale, fp16, scatter. Q: row t. K/V: compacted rank
    // (masked rows skipped entirely).
    float2 bsr[4];
    #pragma unroll
    for (int nt = 0; nt < 4; nt++)
        bsr[nt] = *(const float2*)&bias[n0 + nw + nt*8 + 2*c];

    #pragma unroll
    for (int mt = 0; mt < 4; mt++) {
        #pragma unroll
        for (int rh = 0; rh < 2; rh++) {
            const int m = m0 + mw + mt*16 + g + rh*8;
            const int b = m >> 11;
            const int t = m & (NT - 1);
            int tt = t;
            if (z != 0) tt = g_rank[b*NT + t];
            if (tt < 0) continue;
            __half* rowp = &dst[(b*NH)*NT*ND + tt*ND];
            #pragma unroll
            for (int nt = 0; nt < 4; nt++) {
                const int col = n0 + nw + nt*8 + 2*c;
                const int h  = col >> 6;
                const int cc = col & 63;
                const float vx = (acc[mt][nt][rh*2 + 0] + bsr[nt].x) * scale;
                const float vy = (acc[mt][nt][rh*2 + 1] + bsr[nt].y) * scale;
                *(__half2*)&rowp[h*(NT*ND) + cc] = __floats2half2_rn(vx, vy);
            }
        }
    }
}

// ---------------------------------------------------------------------------
// Flash attention on fp16 tensor cores over COMPACTED keys.
// Loop runs ceil(cnt/64) chunks (~half of 32); mask add only on tail chunk.
// grid = (NT/128, NB*NH), block = 128 (4 warps x 32 q-rows).
// ---------------------------------------------------------------------------
#define RS 72

__global__ __launch_bounds__(128) void attn_kernel(float* __restrict__ out)
{
    extern __shared__ __align__(16) char smraw[];
    __half* Qsh = (__half*)smraw;          // [128][RS]
    __half* Ksh = Qsh + 128*RS;            // [64][RS]
    __half* Vsh = Ksh + 64*RS;             // [64][RS]

    const int tid  = threadIdx.x;
    const int warp = tid >> 5;
    const int lane = tid & 31;
    const int g    = lane >> 2;
    const int c    = lane & 3;
    const int wr   = warp * 32;

    const int bh = blockIdx.y;
    const int b  = bh >> 4;
    const int h  = bh & 15;
    const int q0 = blockIdx.x * 128;

    const __half* __restrict__ qb = g_q + (bh*NT + q0) * ND;
    const __half* __restrict__ kb = g_k + bh*NT*ND;
    const __half* __restrict__ vb = g_v + bh*NT*ND;

    const int cnt     = g_cnt[b];
    const int cnt_pad = (cnt + 63) & ~63;

    #pragma unroll
    for (int i = 0; i < 8; i++) {
        const int slot = tid + 128*i;
        const int r = slot >> 3, c8 = (slot & 7) * 8;
        *(uint4*)&Qsh[r*RS + c8] = *(const uint4*)&qb[r*ND + c8];
    }

    const int arow = (lane & 7) + ((lane >> 3) & 1) * 8;
    const int acol = (lane >> 4) * 8;
    const int brow = (lane & 7) + (lane >> 4) * 8;
    const int bcol = ((lane >> 3) & 1) * 8;
    const int vrow = ((lane >> 3) & 1) * 8 + (lane & 7);
    const int vcol = (lane >> 4) * 8;

    const uint32_t qa_b = (uint32_t)__cvta_generic_to_shared(
        &Qsh[(wr + arow)*RS + acol]);
    const uint32_t kb_b = (uint32_t)__cvta_generic_to_shared(
        &Ksh[brow*RS + bcol]);
    const uint32_t vb_b = (uint32_t)__cvta_generic_to_shared(
        &Vsh[vrow*RS + vcol]);
    const uint32_t MT16 = (uint32_t)(16*RS*2);

    __syncthreads();
    uint32_t aq[2][4][4];
    #pragma unroll
    for (int mt = 0; mt < 2; mt++)
        #pragma unroll
        for (int kt = 0; kt < 4; kt++)
            ldm_x4(aq[mt][kt], qa_b + (uint32_t)mt*MT16 + (uint32_t)(kt*32));

    float o[2][8][4] = {};
    float m_run[2][2] = {{-1e30f,-1e30f},{-1e30f,-1e30f}};
    float l_run[2][2] = {{0.f,0.f},{0.f,0.f}};

    #pragma unroll 1
    for (int k0 = 0; k0 < cnt_pad; k0 += 64) {
        uint4 ka[4], va[4];
        #pragma unroll
        for (int i = 0; i < 4; i++) {
            const int slot = tid + 128*i;
            const int r = slot >> 3, c8 = (slot & 7) * 8;
            ka[i] = *(const uint4*)&kb[(k0 + r)*ND + c8];
            va[i] = *(const uint4*)&vb[(k0 + r)*ND + c8];
        }
        __syncthreads();
        #pragma unroll
        for (int i = 0; i < 4; i++) {
            const int slot = tid + 128*i;
            const int r = slot >> 3, c8 = (slot & 7) * 8;
            *(uint4*)&Ksh[r*RS + c8] = ka[i];
            *(uint4*)&Vsh[r*RS + c8] = va[i];
        }
        __syncthreads();

        // ---- S = Q @ K^T ----
        float s[2][8][4] = {};
        #pragma unroll
        for (int kt = 0; kt < 4; kt++) {
            const uint32_t koff = (uint32_t)(kt * 32);
            #pragma unroll
            for (int np = 0; np < 4; np++) {
                uint32_t bbq[4];
                ldm_x4(bbq, kb_b + (uint32_t)np*MT16 + koff);
                mma_f16(s[0][2*np    ], aq[0][kt], &bbq[0]);
                mma_f16(s[1][2*np    ], aq[1][kt], &bbq[0]);
                mma_f16(s[0][2*np + 1], aq[0][kt], &bbq[2]);
                mma_f16(s[1][2*np + 1], aq[1][kt], &bbq[2]);
            }
        }

        // tail-only bound mask (reference semantics via compaction)
        if (k0 + 64 > cnt) {
            #pragma unroll
            for (int nt = 0; nt < 8; nt++) {
                const float mx = (k0 + nt*8 + 2*c     < cnt) ? 0.f : -1e30f;
                const float my = (k0 + nt*8 + 2*c + 1 < cnt) ? 0.f : -1e30f;
                #pragma unroll
                for (int mt = 0; mt < 2; mt++) {
                    s[mt][nt][0] += mx; s[mt][nt][1] += my;
                    s[mt][nt][2] += mx; s[mt][nt][3] += my;
                }
            }
        }

        // ---- online softmax (s regs become P in place) ----
        #pragma unroll
        for (int mt = 0; mt < 2; mt++) {
            float alpha[2];
            #pragma unroll
            for (int rh = 0; rh < 2; rh++) {
                float rm = -1e30f;
                #pragma unroll
                for (int nt = 0; nt < 8; nt++)
                    rm = fmaxf(rm, fmaxf(s[mt][nt][rh*2], s[mt][nt][rh*2+1]));
                rm = fmaxf(rm, __shfl_xor_sync(0xffffffffu, rm, 1));
                rm = fmaxf(rm, __shfl_xor_sync(0xffffffffu, rm, 2));
                float mnew = fmaxf(m_run[mt][rh], rm);
                alpha[rh] = __expf(m_run[mt][rh] - mnew);
                m_run[mt][rh] = mnew;
                float rs = 0.f;
                #pragma unroll
                for (int nt = 0; nt < 8; nt++) {
                    float p0 = __expf(s[mt][nt][rh*2]   - mnew);
                    float p1 = __expf(s[mt][nt][rh*2+1] - mnew);
                    s[mt][nt][rh*2] = p0; s[mt][nt][rh*2+1] = p1;
                    rs += p0 + p1;
                }
                rs += __shfl_xor_sync(0xffffffffu, rs, 1);
                rs += __shfl_xor_sync(0xffffffffu, rs, 2);
                l_run[mt][rh] = l_run[mt][rh]*alpha[rh] + rs;
            }
            if (!__all_sync(0xffffffffu,
                            (alpha[0] == 1.0f) && (alpha[1] == 1.0f))) {
                #pragma unroll
                for (int nt = 0; nt < 8; nt++) {
                    o[mt][nt][0] *= alpha[0]; o[mt][nt][1] *= alpha[0];
                    o[mt][nt][2] *= alpha[1]; o[mt][nt][3] *= alpha[1];
                }
            }
        }

        // ---- O += P @ V (register-P, FA2 layout identity) ----
        #pragma unroll
        for (int kt = 0; kt < 4; kt++) {
            uint32_t a[2][4];
            #pragma unroll
            for (int mt = 0; mt < 2; mt++) {
                a[mt][0] = h2pack(s[mt][2*kt    ][0], s[mt][2*kt    ][1]);
                a[mt][1] = h2pack(s[mt][2*kt    ][2], s[mt][2*kt    ][3]);
                a[mt][2] = h2pack(s[mt][2*kt + 1][0], s[mt][2*kt + 1][1]);
                a[mt][3] = h2pack(s[mt][2*kt + 1][2], s[mt][2*kt + 1][3]);
            }
            #pragma unroll
            for (int nt2 = 0; nt2 < 4; nt2++) {
                uint32_t r0, r1, r2, r3;
                const uint32_t addr = vb_b + (uint32_t)(kt*16*RS + nt2*16) * 2;
                asm volatile(
                    "ldmatrix.sync.aligned.m8n8.x4.trans.shared.b16 "
                    "{%0,%1,%2,%3}, [%4];"
                    : "=r"(r0), "=r"(r1), "=r"(r2), "=r"(r3) : "r"(addr));
                uint32_t b0[2] = {r0, r1};
                uint32_t b1[2] = {r2, r3};
                mma_f16(o[0][nt2*2    ], a[0], b0);
                mma_f16(o[1][nt2*2    ], a[1], b0);
                mma_f16(o[0][nt2*2 + 1], a[0], b1);
                mma_f16(o[1][nt2*2 + 1], a[1], b1);
            }
        }
    }

    #pragma unroll
    for (int mt = 0; mt < 2; mt++) {
        const float inv0 = 1.0f / l_run[mt][0];
        const float inv1 = 1.0f / l_run[mt][1];
        const int t0 = q0 + wr + mt*16 + g;
        float* ob0 = out + (b*NT + t0    )*NC + h*ND;
        float* ob1 = out + (b*NT + t0 + 8)*NC + h*ND;
        #pragma unroll
        for (int nt = 0; nt < 8; nt++) {
            *(float2*)&ob0[nt*8 + 2*c] =
                make_float2(o[mt][nt][0]*inv0, o[mt][nt][1]*inv0);
            *(float2*)&ob1[nt*8 + 2*c] =
                make_float2(o[mt][nt][2]*inv1, o[mt][nt][3]*inv1);
        }
    }
}

// ---------------------------------------------------------------------------
extern "C" void kernel_launch(void* const* d_in, const int* in_sizes, int n_in,
                              void* d_out, int out_size)
{
    const float* x  = (const float*)d_in[0];
    const int* mask = (const int*)  d_in[1];
    const float* Wq = (const float*)d_in[2];
    const float* bq = (const float*)d_in[3];
    const float* Wk = (const float*)d_in[4];
    const float* bk = (const float*)d_in[5];
    const float* Wv = (const float*)d_in[6];
    const float* bv = (const float*)d_in[7];
    float* out = (float*)d_out;

    mask_scan<<<NB, 256>>>(mask);
    prep_x<<<NB*NT*NC/8/256, 256>>>(x);
    prep_w<<<dim3(NC*NC/8/256, 3), 256>>>(Wq, Wk, Wv);

    const int qkv_smem = 2 * STAGEB;          // 40960
    cudaFuncSetAttribute(qkv_mma,
                         cudaFuncAttributeMaxDynamicSharedMemorySize, qkv_smem);
    qkv_mma<<<dim3(NC/128, (NB*NT)/128, 3), 256, qkv_smem>>>(bq, bk, bv);

    const int attn_smem = (128*RS + 64*RS + 64*RS) * 2;  // 36864
    cudaFuncSetAttribute(attn_kernel,
                         cudaFuncAttributeMaxDynamicSharedMemorySize, attn_smem);
    attn_kernel<<<dim3(NT/128, NB*NH), 128, attn_smem>>>(out);
}

// round 16
// speedup vs baseline: 3.8499x; 1.1694x over previous
#include <cuda_runtime.h>
#include <cuda_fp16.h>
#include <cstdint>

#define NB 4
#define NT 2048
#define NC 1024
#define NH 16
#define ND 64

// Scratch: Q full [B,H,T,D]; K,V COMPACTED along T per batch (valid keys
// first; pad tail masked in attention).
__device__ __half g_q[NB*NH*NT*ND];
__device__ __half g_k[NB*NH*NT*ND];
__device__ __half g_v[NB*NH*NT*ND];
// Preconverted inputs: x (full + per-batch compacted) and W, fp16.
__device__ __half g_xh[NB*NT*NC];
__device__ __half g_xc[NB*NT*NC];
__device__ __half g_wh[3*NC*NC];
// Mask compaction: rank[b*NT+t] = compacted index or -1; cnt[b] = #valid.
__device__ int g_rank[NB*NT];
__device__ int g_cnt[NB];

__device__ __forceinline__ void mma_f16(float d[4], const uint32_t a[4],
                                        const uint32_t b[2]) {
    asm volatile(
        "mma.sync.aligned.m16n8k16.row.col.f32.f16.f16.f32 "
        "{%0,%1,%2,%3}, {%4,%5,%6,%7}, {%8,%9}, {%0,%1,%2,%3};"
        : "+f"(d[0]), "+f"(d[1]), "+f"(d[2]), "+f"(d[3])
        : "r"(a[0]), "r"(a[1]), "r"(a[2]), "r"(a[3]), "r"(b[0]), "r"(b[1]));
}

__device__ __forceinline__ void ldm_x4(uint32_t r[4], uint32_t addr) {
    asm volatile(
        "ldmatrix.sync.aligned.m8n8.x4.shared.b16 {%0,%1,%2,%3}, [%4];"
        : "=r"(r[0]), "=r"(r[1]), "=r"(r[2]), "=r"(r[3]) : "r"(addr));
}

__device__ __forceinline__ uint32_t h2pack(float x, float y) {
    __half2 h = __floats2half2_rn(x, y);
    return *(const uint32_t*)&h;
}

__device__ __forceinline__ void cp16(uint32_t dst, const void* src) {
    asm volatile("cp.async.cg.shared.global [%0], [%1], 16;"
                 :: "r"(dst), "l"(src));
}
__device__ __forceinline__ void cp_commit() {
    asm volatile("cp.async.commit_group;");
}
template <int N>
__device__ __forceinline__ void cp_wait() {
    asm volatile("cp.async.wait_group %0;" :: "n"(N));
}

// ---------------------------------------------------------------------------
// Mask scan: per batch, compacted rank for each valid key + count.
// ---------------------------------------------------------------------------
__global__ __launch_bounds__(256) void mask_scan(const int* __restrict__ mask)
{
    __shared__ int cnts[256];
    const int b   = blockIdx.x;
    const int tid = threadIdx.x;
    const int* mb = mask + b*NT;
    const int t0  = tid * 8;

    int loc[8]; int c = 0;
    #pragma unroll
    for (int j = 0; j < 8; j++) { loc[j] = (mb[t0 + j] > 0); c += loc[j]; }
    cnts[tid] = c;
    __syncthreads();
    #pragma unroll
    for (int off = 1; off < 256; off <<= 1) {
        int u = (tid >= off) ? cnts[tid - off] : 0;
        __syncthreads();
        cnts[tid] += u;
        __syncthreads();
    }
    int base = cnts[tid] - c;
    #pragma unroll
    for (int j = 0; j < 8; j++) {
        g_rank[b*NT + t0 + j] = loc[j] ? base : -1;
        base += loc[j];
    }
    if (tid == 255) g_cnt[b] = cnts[255];
}

// ---------------------------------------------------------------------------
// Prep: one-time fp32 -> fp16 conversions + valid-row gather.
// ---------------------------------------------------------------------------
__global__ __launch_bounds__(256) void prep_x(const float* __restrict__ x)
{
    const int i8 = (blockIdx.x * 256 + threadIdx.x) * 8;
    float4 v0 = *(const float4*)&x[i8];
    float4 v1 = *(const float4*)&x[i8 + 4];
    __half2 h[4];
    h[0] = __floats2half2_rn(v0.x, v0.y);
    h[1] = __floats2half2_rn(v0.z, v0.w);
    h[2] = __floats2half2_rn(v1.x, v1.y);
    h[3] = __floats2half2_rn(v1.z, v1.w);
    *(uint4*)&g_xh[i8] = *(const uint4*)h;
}

// Gather valid rows of g_xh into per-batch compacted g_xc. 2 rows/block.
__global__ __launch_bounds__(256) void prep_xc()
{
    const int row = blockIdx.x * 2 + (threadIdx.x >> 7);   // global row
    const int r   = g_rank[row];
    if (r < 0) return;
    const int b = row >> 11;
    const int l = threadIdx.x & 127;
    const uint4 v = *(const uint4*)&g_xh[row*NC + l*8];
    *(uint4*)&g_xc[(b*NT + r)*NC + l*8] = v;
}

__global__ __launch_bounds__(256) void prep_w(
    const float* __restrict__ Wq, const float* __restrict__ Wk,
    const float* __restrict__ Wv)
{
    const float* __restrict__ W =
        (blockIdx.y == 0) ? Wq : ((blockIdx.y == 1) ? Wk : Wv);
    const int i8 = (blockIdx.x * 256 + threadIdx.x) * 8;
    float4 v0 = *(const float4*)&W[i8];
    float4 v1 = *(const float4*)&W[i8 + 4];
    __half2 h[4];
    h[0] = __floats2half2_rn(v0.x, v0.y);
    h[1] = __floats2half2_rn(v0.z, v0.w);
    h[2] = __floats2half2_rn(v1.x, v1.y);
    h[3] = __floats2half2_rn(v1.z, v1.w);
    *(uint4*)&g_wh[blockIdx.y*NC*NC + i8] = *(const uint4*)h;
}

// ---------------------------------------------------------------------------
// QKV projection on fp16 tensor cores (single-MMA, cp.async 2-stage).
// R16: K/V GEMM runs over COMPACTED rows; tiles beyond cnt[b] early-exit.
// grid = (NC/128, (NB*NT)/128, 3), block = 256 (2 m-warp x 4 n-warp).
// ---------------------------------------------------------------------------
#define QKST 40
#define TILEB (128*QKST*2)
#define STAGEB (2*TILEB)

__global__ __launch_bounds__(256) void qkv_mma(
    const float* __restrict__ bq, const float* __restrict__ bk,
    const float* __restrict__ bv)
{
    extern __shared__ __align__(16) char smraw[];

    const int z = blockIdx.z;
    const float* __restrict__ bias = (z == 0) ? bq : ((z == 1) ? bk : bv);
    const __half* __restrict__ Wh  = g_wh + z*NC*NC;
    __half* __restrict__ dst       = (z == 0) ? g_q : ((z == 1) ? g_k : g_v);
    const float scale = (z == 0) ? 0.125f : 1.0f;

    // m0: global row offset into source ([B*T, NC] layout).
    // Q: all rows. K/V: compacted rows; skip tiles fully beyond cnt[b].
    int m0;
    const __half* __restrict__ asrc;
    if (z == 0) {
        m0 = blockIdx.y * 128;
        asrc = g_xh;
    } else {
        const int b    = blockIdx.y >> 4;
        const int tile = blockIdx.y & 15;
        if (tile * 128 >= g_cnt[b]) return;
        m0 = b*NT + tile*128;
        asrc = g_xc;
    }

    const int tid  = threadIdx.x;
    const int warp = tid >> 5;
    const int lane = tid & 31;
    const int g    = lane >> 2;
    const int c    = lane & 3;
    const int mw   = (warp & 1) * 64;
    const int nw   = (warp >> 1) * 32;

    const int n0 = blockIdx.x * 128;

    const int srow = tid >> 1;
    const int scg  = (tid & 1) * 16;

    const uint32_t sm0 = (uint32_t)__cvta_generic_to_shared(smraw);
    const uint32_t st_row = (uint32_t)(srow*QKST + scg) * 2;

    const int arow = (lane & 7) + ((lane >> 3) & 1) * 8;
    const int acol = (lane >> 4) * 8;
    const int brow = (lane & 7) + (lane >> 4) * 8;
    const int bcol = ((lane >> 3) & 1) * 8;
    const uint32_t ah_f = sm0 + (uint32_t)(((mw + arow)*QKST + acol) * 2);
    const uint32_t bs_f = sm0 + TILEB +
        (uint32_t)(((nw + brow)*QKST + bcol) * 2);

    const __half* xh_p = &asrc[(m0 + srow)*NC + scg];
    const __half* wh_p = &Wh  [(n0 + srow)*NC + scg];

    auto issue = [&](int s, int k0) {
        const uint32_t base = sm0 + (uint32_t)s*STAGEB + st_row;
        cp16(base,              xh_p + k0);
        cp16(base + 16,         xh_p + k0 + 8);
        cp16(base + TILEB,      wh_p + k0);
        cp16(base + TILEB + 16, wh_p + k0 + 8);
        cp_commit();
    };

    float acc[4][4][4] = {};

    issue(0, 0);
    #pragma unroll 1
    for (int it = 0; it < NC/32; it++) {
        const int s = it & 1;
        if (it + 1 < NC/32) {
            issue(s ^ 1, (it + 1) * 32);
            cp_wait<1>();
        } else {
            cp_wait<0>();
        }
        __syncthreads();

        const uint32_t sb = (uint32_t)s*STAGEB;
        #pragma unroll
        for (int kc = 0; kc < 2; kc++) {
            const uint32_t koff = (uint32_t)(kc * 16 * 2);
            uint32_t bf[2][4];
            ldm_x4(bf[0], bs_f + sb + koff);
            ldm_x4(bf[1], bs_f + sb + (uint32_t)(16*QKST*2) + koff);
            #pragma unroll
            for (int mt = 0; mt < 4; mt++) {
                const uint32_t moff = (uint32_t)(mt * 16 * QKST * 2);
                uint32_t ah[4];
                ldm_x4(ah, ah_f + sb + moff + koff);
                #pragma unroll
                for (int np = 0; np < 2; np++) {
                    mma_f16(acc[mt][2*np    ], ah, &bf[np][0]);
                    mma_f16(acc[mt][2*np + 1], ah, &bf[np][2]);
                }
            }
        }
        __syncthreads();
    }

    // Epilogue: bias + scale, fp16, direct store (rows already compacted).
    float2 bsr[4];
    #pragma unroll
    for (int nt = 0; nt < 4; nt++)
        bsr[nt] = *(const float2*)&bias[n0 + nw + nt*8 + 2*c];

    #pragma unroll
    for (int mt = 0; mt < 4; mt++) {
        #pragma unroll
        for (int rh = 0; rh < 2; rh++) {
            const int m = m0 + mw + mt*16 + g + rh*8;
            const int b = m >> 11;
            const int t = m & (NT - 1);
            __half* rowp = &dst[(b*NH)*NT*ND + t*ND];
            #pragma unroll
            for (int nt = 0; nt < 4; nt++) {
                const int col = n0 + nw + nt*8 + 2*c;
                const int h  = col >> 6;
                const int cc = col & 63;
                const float vx = (acc[mt][nt][rh*2 + 0] + bsr[nt].x) * scale;
                const float vy = (acc[mt][nt][rh*2 + 1] + bsr[nt].y) * scale;
                *(__half2*)&rowp[h*(NT*ND) + cc] = __floats2half2_rn(vx, vy);
            }
        }
    }
}

// ---------------------------------------------------------------------------
// Flash attention on fp16 tensor cores over COMPACTED keys (unchanged R15).
// grid = (NT/128, NB*NH), block = 128 (4 warps x 32 q-rows).
// ---------------------------------------------------------------------------
#define RS 72

__global__ __launch_bounds__(128) void attn_kernel(float* __restrict__ out)
{
    extern __shared__ __align__(16) char smraw[];
    __half* Qsh = (__half*)smraw;          // [128][RS]
    __half* Ksh = Qsh + 128*RS;            // [64][RS]
    __half* Vsh = Ksh + 64*RS;             // [64][RS]

    const int tid  = threadIdx.x;
    const int warp = tid >> 5;
    const int lane = tid & 31;
    const int g    = lane >> 2;
    const int c    = lane & 3;
    const int wr   = warp * 32;

    const int bh = blockIdx.y;
    const int b  = bh >> 4;
    const int h  = bh & 15;
    const int q0 = blockIdx.x * 128;

    const __half* __restrict__ qb = g_q + (bh*NT + q0) * ND;
    const __half* __restrict__ kb = g_k + bh*NT*ND;
    const __half* __restrict__ vb = g_v + bh*NT*ND;

    const int cnt     = g_cnt[b];
    const int cnt_pad = (cnt + 63) & ~63;

    #pragma unroll
    for (int i = 0; i < 8; i++) {
        const int slot = tid + 128*i;
        const int r = slot >> 3, c8 = (slot & 7) * 8;
        *(uint4*)&Qsh[r*RS + c8] = *(const uint4*)&qb[r*ND + c8];
    }

    const int arow = (lane & 7) + ((lane >> 3) & 1) * 8;
    const int acol = (lane >> 4) * 8;
    const int brow = (lane & 7) + (lane >> 4) * 8;
    const int bcol = ((lane >> 3) & 1) * 8;
    const int vrow = ((lane >> 3) & 1) * 8 + (lane & 7);
    const int vcol = (lane >> 4) * 8;

    const uint32_t qa_b = (uint32_t)__cvta_generic_to_shared(
        &Qsh[(wr + arow)*RS + acol]);
    const uint32_t kb_b = (uint32_t)__cvta_generic_to_shared(
        &Ksh[brow*RS + bcol]);
    const uint32_t vb_b = (uint32_t)__cvta_generic_to_shared(
        &Vsh[vrow*RS + vcol]);
    const uint32_t MT16 = (uint32_t)(16*RS*2);

    __syncthreads();
    uint32_t aq[2][4][4];
    #pragma unroll
    for (int mt = 0; mt < 2; mt++)
        #pragma unroll
        for (int kt = 0; kt < 4; kt++)
            ldm_x4(aq[mt][kt], qa_b + (uint32_t)mt*MT16 + (uint32_t)(kt*32));

    float o[2][8][4] = {};
    float m_run[2][2] = {{-1e30f,-1e30f},{-1e30f,-1e30f}};
    float l_run[2][2] = {{0.f,0.f},{0.f,0.f}};

    #pragma unroll 1
    for (int k0 = 0; k0 < cnt_pad; k0 += 64) {
        uint4 ka[4], va[4];
        #pragma unroll
        for (int i = 0; i < 4; i++) {
            const int slot = tid + 128*i;
            const int r = slot >> 3, c8 = (slot & 7) * 8;
            ka[i] = *(const uint4*)&kb[(k0 + r)*ND + c8];
            va[i] = *(const uint4*)&vb[(k0 + r)*ND + c8];
        }
        __syncthreads();
        #pragma unroll
        for (int i = 0; i < 4; i++) {
            const int slot = tid + 128*i;
            const int r = slot >> 3, c8 = (slot & 7) * 8;
            *(uint4*)&Ksh[r*RS + c8] = ka[i];
            *(uint4*)&Vsh[r*RS + c8] = va[i];
        }
        __syncthreads();

        // ---- S = Q @ K^T ----
        float s[2][8][4] = {};
        #pragma unroll
        for (int kt = 0; kt < 4; kt++) {
            const uint32_t koff = (uint32_t)(kt * 32);
            #pragma unroll
            for (int np = 0; np < 4; np++) {
                uint32_t bbq[4];
                ldm_x4(bbq, kb_b + (uint32_t)np*MT16 + koff);
                mma_f16(s[0][2*np    ], aq[0][kt], &bbq[0]);
                mma_f16(s[1][2*np    ], aq[1][kt], &bbq[0]);
                mma_f16(s[0][2*np + 1], aq[0][kt], &bbq[2]);
                mma_f16(s[1][2*np + 1], aq[1][kt], &bbq[2]);
            }
        }

        // tail-only bound mask (reference semantics via compaction)
        if (k0 + 64 > cnt) {
            #pragma unroll
            for (int nt = 0; nt < 8; nt++) {
                const float mx = (k0 + nt*8 + 2*c     < cnt) ? 0.f : -1e30f;
                const float my = (k0 + nt*8 + 2*c + 1 < cnt) ? 0.f : -1e30f;
                #pragma unroll
                for (int mt = 0; mt < 2; mt++) {
                    s[mt][nt][0] += mx; s[mt][nt][1] += my;
                    s[mt][nt][2] += mx; s[mt][nt][3] += my;
                }
            }
        }

        // ---- online softmax (s regs become P in place) ----
        #pragma unroll
        for (int mt = 0; mt < 2; mt++) {
            float alpha[2];
            #pragma unroll
            for (int rh = 0; rh < 2; rh++) {
                float rm = -1e30f;
                #pragma unroll
                for (int nt = 0; nt < 8; nt++)
                    rm = fmaxf(rm, fmaxf(s[mt][nt][rh*2], s[mt][nt][rh*2+1]));
                rm = fmaxf(rm, __shfl_xor_sync(0xffffffffu, rm, 1));
                rm = fmaxf(rm, __shfl_xor_sync(0xffffffffu, rm, 2));
                float mnew = fmaxf(m_run[mt][rh], rm);
                alpha[rh] = __expf(m_run[mt][rh] - mnew);
                m_run[mt][rh] = mnew;
                float rs = 0.f;
                #pragma unroll
                for (int nt = 0; nt < 8; nt++) {
                    float p0 = __expf(s[mt][nt][rh*2]   - mnew);
                    float p1 = __expf(s[mt][nt][rh*2+1] - mnew);
                    s[mt][nt][rh*2] = p0; s[mt][nt][rh*2+1] = p1;
                    rs += p0 + p1;
                }
                rs += __shfl_xor_sync(0xffffffffu, rs, 1);
                rs += __shfl_xor_sync(0xffffffffu, rs, 2);
                l_run[mt][rh] = l_run[mt][rh]*alpha[rh] + rs;
            }
            if (!__all_sync(0xffffffffu,
                            (alpha[0] == 1.0f) && (alpha[1] == 1.0f))) {
                #pragma unroll
                for (int nt = 0; nt < 8; nt++) {
                    o[mt][nt][0] *= alpha[0]; o[mt][nt][1] *= alpha[0];
                    o[mt][nt][2] *= alpha[1]; o[mt][nt][3] *= alpha[1];
                }
            }
        }

        // ---- O += P @ V (register-P, FA2 layout identity) ----
        #pragma unroll
        for (int kt = 0; kt < 4; kt++) {
            uint32_t a[2][4];
            #pragma unroll
            for (int mt = 0; mt < 2; mt++) {
                a[mt][0] = h2pack(s[mt][2*kt    ][0], s[mt][2*kt    ][1]);
                a[mt][1] = h2pack(s[mt][2*kt    ][2], s[mt][2*kt    ][3]);
                a[mt][2] = h2pack(s[mt][2*kt + 1][0], s[mt][2*kt + 1][1]);
                a[mt][3] = h2pack(s[mt][2*kt + 1][2], s[mt][2*kt + 1][3]);
            }
            #pragma unroll
            for (int nt2 = 0; nt2 < 4; nt2++) {
                uint32_t r0, r1, r2, r3;
                const uint32_t addr = vb_b + (uint32_t)(kt*16*RS + nt2*16) * 2;
                asm volatile(
                    "ldmatrix.sync.aligned.m8n8.x4.trans.shared.b16 "
                    "{%0,%1,%2,%3}, [%4];"
                    : "=r"(r0), "=r"(r1), "=r"(r2), "=r"(r3) : "r"(addr));
                uint32_t b0[2] = {r0, r1};
                uint32_t b1[2] = {r2, r3};
                mma_f16(o[0][nt2*2    ], a[0], b0);
                mma_f16(o[1][nt2*2    ], a[1], b0);
                mma_f16(o[0][nt2*2 + 1], a[0], b1);
                mma_f16(o[1][nt2*2 + 1], a[1], b1);
            }
        }
    }

    #pragma unroll
    for (int mt = 0; mt < 2; mt++) {
        const float inv0 = 1.0f / l_run[mt][0];
        const float inv1 = 1.0f / l_run[mt][1];
        const int t0 = q0 + wr + mt*16 + g;
        float* ob0 = out + (b*NT + t0    )*NC + h*ND;
        float* ob1 = out + (b*NT + t0 + 8)*NC + h*ND;
        #pragma unroll
        for (int nt = 0; nt < 8; nt++) {
            *(float2*)&ob0[nt*8 + 2*c] =
                make_float2(o[mt][nt][0]*inv0, o[mt][nt][1]*inv0);
            *(float2*)&ob1[nt*8 + 2*c] =
                make_float2(o[mt][nt][2]*inv1, o[mt][nt][3]*inv1);
        }
    }
}

// ---------------------------------------------------------------------------
extern "C" void kernel_launch(void* const* d_in, const int* in_sizes, int n_in,
                              void* d_out, int out_size)
{
    const float* x  = (const float*)d_in[0];
    const int* mask = (const int*)  d_in[1];
    const float* Wq = (const float*)d_in[2];
    const float* bq = (const float*)d_in[3];
    const float* Wk = (const float*)d_in[4];
    const float* bk = (const float*)d_in[5];
    const float* Wv = (const float*)d_in[6];
    const float* bv = (const float*)d_in[7];
    float* out = (float*)d_out;

    mask_scan<<<NB, 256>>>(mask);
    prep_x<<<NB*NT*NC/8/256, 256>>>(x);
    prep_w<<<dim3(NC*NC/8/256, 3), 256>>>(Wq, Wk, Wv);
    prep_xc<<<NB*NT/2, 256>>>();

    const int qkv_smem = 2 * STAGEB;          // 40960
    cudaFuncSetAttribute(qkv_mma,
                         cudaFuncAttributeMaxDynamicSharedMemorySize, qkv_smem);
    qkv_mma<<<dim3(NC/128, (NB*NT)/128, 3), 256, qkv_smem>>>(bq, bk, bv);

    const int attn_smem = (128*RS + 64*RS + 64*RS) * 2;  // 36864
    cudaFuncSetAttribute(attn_kernel,
                         cudaFuncAttributeMaxDynamicSharedMemorySize, attn_smem);
    attn_kernel<<<dim3(NT/128, NB*NH), 128, attn_smem>>>(out);
}

// round 17
// speedup vs baseline: 4.0608x; 1.0548x over previous
#include <cuda_runtime.h>
#include <cuda_fp16.h>
#include <cstdint>

#define NB 4
#define NT 2048
#define NC 1024
#define NH 16
#define ND 64

// Scratch: Q full [B,H,T,D]; K,V COMPACTED along T per batch.
__device__ __half g_q[NB*NH*NT*ND];
__device__ __half g_k[NB*NH*NT*ND];
__device__ __half g_v[NB*NH*NT*ND];
// Preconverted inputs: x and W, fp16.
__device__ __half g_xh[NB*NT*NC];
__device__ __half g_wh[3*NC*NC];
// Mask compaction: vlist[b*NT + r] = original t of r-th valid key; cnt[b].
__device__ int g_vlist[NB*NT];
__device__ int g_cnt[NB];

__device__ __forceinline__ void mma_f16(float d[4], const uint32_t a[4],
                                        const uint32_t b[2]) {
    asm volatile(
        "mma.sync.aligned.m16n8k16.row.col.f32.f16.f16.f32 "
        "{%0,%1,%2,%3}, {%4,%5,%6,%7}, {%8,%9}, {%0,%1,%2,%3};"
        : "+f"(d[0]), "+f"(d[1]), "+f"(d[2]), "+f"(d[3])
        : "r"(a[0]), "r"(a[1]), "r"(a[2]), "r"(a[3]), "r"(b[0]), "r"(b[1]));
}

__device__ __forceinline__ void ldm_x4(uint32_t r[4], uint32_t addr) {
    asm volatile(
        "ldmatrix.sync.aligned.m8n8.x4.shared.b16 {%0,%1,%2,%3}, [%4];"
        : "=r"(r[0]), "=r"(r[1]), "=r"(r[2]), "=r"(r[3]) : "r"(addr));
}

__device__ __forceinline__ uint32_t h2pack(float x, float y) {
    __half2 h = __floats2half2_rn(x, y);
    return *(const uint32_t*)&h;
}

__device__ __forceinline__ void cp16(uint32_t dst, const void* src) {
    asm volatile("cp.async.cg.shared.global [%0], [%1], 16;"
                 :: "r"(dst), "l"(src));
}
__device__ __forceinline__ void cp_commit() {
    asm volatile("cp.async.commit_group;");
}
template <int N>
__device__ __forceinline__ void cp_wait() {
    asm volatile("cp.async.wait_group %0;" :: "n"(N));
}

// ---------------------------------------------------------------------------
// Mask scan: per batch, valid-key list (inverse rank) + count.
// ---------------------------------------------------------------------------
__global__ __launch_bounds__(256) void mask_scan(const int* __restrict__ mask)
{
    __shared__ int cnts[256];
    const int b   = blockIdx.x;
    const int tid = threadIdx.x;
    const int* mb = mask + b*NT;
    const int t0  = tid * 8;

    int loc[8]; int c = 0;
    #pragma unroll
    for (int j = 0; j < 8; j++) { loc[j] = (mb[t0 + j] > 0); c += loc[j]; }
    cnts[tid] = c;
    __syncthreads();
    #pragma unroll
    for (int off = 1; off < 256; off <<= 1) {
        int u = (tid >= off) ? cnts[tid - off] : 0;
        __syncthreads();
        cnts[tid] += u;
        __syncthreads();
    }
    int base = cnts[tid] - c;
    #pragma unroll
    for (int j = 0; j < 8; j++) {
        if (loc[j]) g_vlist[b*NT + base] = t0 + j;
        base += loc[j];
    }
    if (tid == 255) g_cnt[b] = cnts[255];
}

// ---------------------------------------------------------------------------
// Prep: fused one-time fp32 -> fp16 conversion of x (blocks [0,4096)) and
// Wq/Wk/Wv (blocks [4096, 4096+1536)).
// ---------------------------------------------------------------------------
__global__ __launch_bounds__(256) void prep_all(
    const float* __restrict__ x,
    const float* __restrict__ Wq, const float* __restrict__ Wk,
    const float* __restrict__ Wv)
{
    const int bid = blockIdx.x;
    const float* __restrict__ src;
    __half* __restrict__ dst;
    int i8;
    if (bid < 4096) {
        src = x; dst = g_xh;
        i8 = (bid * 256 + threadIdx.x) * 8;
    } else {
        const int wz = (bid - 4096) >> 9;            // /512
        const int wb = (bid - 4096) & 511;
        src = (wz == 0) ? Wq : ((wz == 1) ? Wk : Wv);
        dst = g_wh + wz*NC*NC;
        i8 = (wb * 256 + threadIdx.x) * 8;
    }
    float4 v0 = *(const float4*)&src[i8];
    float4 v1 = *(const float4*)&src[i8 + 4];
    __half2 h[4];
    h[0] = __floats2half2_rn(v0.x, v0.y);
    h[1] = __floats2half2_rn(v0.z, v0.w);
    h[2] = __floats2half2_rn(v1.x, v1.y);
    h[3] = __floats2half2_rn(v1.z, v1.w);
    *(uint4*)&dst[i8] = *(const uint4*)h;
}

// ---------------------------------------------------------------------------
// QKV projection on fp16 tensor cores (single-MMA, cp.async 2-stage).
// R17: K/V tiles gather source rows directly from g_xh via g_vlist
// (no compacted copy); tiles beyond cnt[b] early-exit.
// grid = (NC/128, (NB*NT)/128, 3), block = 256 (2 m-warp x 4 n-warp).
// ---------------------------------------------------------------------------
#define QKST 40
#define TILEB (128*QKST*2)
#define STAGEB (2*TILEB)

__global__ __launch_bounds__(256) void qkv_mma(
    const float* __restrict__ bq, const float* __restrict__ bk,
    const float* __restrict__ bv)
{
    extern __shared__ __align__(16) char smraw[];

    const int z = blockIdx.z;
    const float* __restrict__ bias = (z == 0) ? bq : ((z == 1) ? bk : bv);
    const __half* __restrict__ Wh  = g_wh + z*NC*NC;
    __half* __restrict__ dst       = (z == 0) ? g_q : ((z == 1) ? g_k : g_v);
    const float scale = (z == 0) ? 0.125f : 1.0f;

    const int tid  = threadIdx.x;
    const int warp = tid >> 5;
    const int lane = tid & 31;
    const int g    = lane >> 2;
    const int c    = lane & 3;
    const int mw   = (warp & 1) * 64;
    const int nw   = (warp >> 1) * 32;

    const int n0 = blockIdx.x * 128;
    const int srow = tid >> 1;
    const int scg  = (tid & 1) * 16;

    // Source row for staging (gathered for K/V), dest base m0.
    int m0;
    const __half* xh_p;
    if (z == 0) {
        m0 = blockIdx.y * 128;
        xh_p = &g_xh[(m0 + srow)*NC + scg];
    } else {
        const int b    = blockIdx.y >> 4;
        const int tile = blockIdx.y & 15;
        const int cntb = g_cnt[b];
        if (tile * 128 >= cntb) return;
        m0 = b*NT + tile*128;
        const int lrow = tile*128 + srow;
        const int srct = g_vlist[b*NT + ((lrow < cntb) ? lrow : 0)];
        xh_p = &g_xh[(b*NT + srct)*NC + scg];
    }

    const uint32_t sm0 = (uint32_t)__cvta_generic_to_shared(smraw);
    const uint32_t st_row = (uint32_t)(srow*QKST + scg) * 2;

    const int arow = (lane & 7) + ((lane >> 3) & 1) * 8;
    const int acol = (lane >> 4) * 8;
    const int brow = (lane & 7) + (lane >> 4) * 8;
    const int bcol = ((lane >> 3) & 1) * 8;
    const uint32_t ah_f = sm0 + (uint32_t)(((mw + arow)*QKST + acol) * 2);
    const uint32_t bs_f = sm0 + TILEB +
        (uint32_t)(((nw + brow)*QKST + bcol) * 2);

    const __half* wh_p = &Wh[(n0 + srow)*NC + scg];

    auto issue = [&](int s, int k0) {
        const uint32_t base = sm0 + (uint32_t)s*STAGEB + st_row;
        cp16(base,              xh_p + k0);
        cp16(base + 16,         xh_p + k0 + 8);
        cp16(base + TILEB,      wh_p + k0);
        cp16(base + TILEB + 16, wh_p + k0 + 8);
        cp_commit();
    };

    float acc[4][4][4] = {};

    issue(0, 0);
    #pragma unroll 1
    for (int it = 0; it < NC/32; it++) {
        const int s = it & 1;
        if (it + 1 < NC/32) {
            issue(s ^ 1, (it + 1) * 32);
            cp_wait<1>();
        } else {
            cp_wait<0>();
        }
        __syncthreads();

        const uint32_t sb = (uint32_t)s*STAGEB;
        #pragma unroll
        for (int kc = 0; kc < 2; kc++) {
            const uint32_t koff = (uint32_t)(kc * 16 * 2);
            uint32_t bf[2][4];
            ldm_x4(bf[0], bs_f + sb + koff);
            ldm_x4(bf[1], bs_f + sb + (uint32_t)(16*QKST*2) + koff);
            #pragma unroll
            for (int mt = 0; mt < 4; mt++) {
                const uint32_t moff = (uint32_t)(mt * 16 * QKST * 2);
                uint32_t ah[4];
                ldm_x4(ah, ah_f + sb + moff + koff);
                #pragma unroll
                for (int np = 0; np < 2; np++) {
                    mma_f16(acc[mt][2*np    ], ah, &bf[np][0]);
                    mma_f16(acc[mt][2*np + 1], ah, &bf[np][2]);
                }
            }
        }
        __syncthreads();
    }

    // Epilogue: bias + scale, fp16, direct store (rows already compacted).
    float2 bsr[4];
    #pragma unroll
    for (int nt = 0; nt < 4; nt++)
        bsr[nt] = *(const float2*)&bias[n0 + nw + nt*8 + 2*c];

    #pragma unroll
    for (int mt = 0; mt < 4; mt++) {
        #pragma unroll
        for (int rh = 0; rh < 2; rh++) {
            const int m = m0 + mw + mt*16 + g + rh*8;
            const int b = m >> 11;
            const int t = m & (NT - 1);
            __half* rowp = &dst[(b*NH)*NT*ND + t*ND];
            #pragma unroll
            for (int nt = 0; nt < 4; nt++) {
                const int col = n0 + nw + nt*8 + 2*c;
                const int h  = col >> 6;
                const int cc = col & 63;
                const float vx = (acc[mt][nt][rh*2 + 0] + bsr[nt].x) * scale;
                const float vy = (acc[mt][nt][rh*2 + 1] + bsr[nt].y) * scale;
                *(__half2*)&rowp[h*(NT*ND) + cc] = __floats2half2_rn(vx, vy);
            }
        }
    }
}

// ---------------------------------------------------------------------------
// Flash attention on fp16 tensor cores over COMPACTED keys.
// R17: 128-key staging per barrier pair, two 64-key compute sub-chunks.
// grid = (NT/128, NB*NH), block = 128 (4 warps x 32 q-rows).
// ---------------------------------------------------------------------------
#define RS 72

__global__ __launch_bounds__(128) void attn_kernel(float* __restrict__ out)
{
    extern __shared__ __align__(16) char smraw[];
    __half* Qsh = (__half*)smraw;          // [128][RS]
    __half* Ksh = Qsh + 128*RS;            // [128][RS]
    __half* Vsh = Ksh + 128*RS;            // [128][RS]
    // total 3*128*72*2 = 55296 B

    const int tid  = threadIdx.x;
    const int warp = tid >> 5;
    const int lane = tid & 31;
    const int g    = lane >> 2;
    const int c    = lane & 3;
    const int wr   = warp * 32;

    const int bh = blockIdx.y;
    const int b  = bh >> 4;
    const int h  = bh & 15;
    const int q0 = blockIdx.x * 128;

    const __half* __restrict__ qb = g_q + (bh*NT + q0) * ND;
    const __half* __restrict__ kb = g_k + bh*NT*ND;
    const __half* __restrict__ vb = g_v + bh*NT*ND;

    const int cnt      = g_cnt[b];
    const int cnt_pad  = (cnt + 127) & ~127;

    #pragma unroll
    for (int i = 0; i < 8; i++) {
        const int slot = tid + 128*i;
        const int r = slot >> 3, c8 = (slot & 7) * 8;
        *(uint4*)&Qsh[r*RS + c8] = *(const uint4*)&qb[r*ND + c8];
    }

    const int arow = (lane & 7) + ((lane >> 3) & 1) * 8;
    const int acol = (lane >> 4) * 8;
    const int brow = (lane & 7) + (lane >> 4) * 8;
    const int bcol = ((lane >> 3) & 1) * 8;
    const int vrow = ((lane >> 3) & 1) * 8 + (lane & 7);
    const int vcol = (lane >> 4) * 8;

    const uint32_t qa_b = (uint32_t)__cvta_generic_to_shared(
        &Qsh[(wr + arow)*RS + acol]);
    const uint32_t kb_b = (uint32_t)__cvta_generic_to_shared(
        &Ksh[brow*RS + bcol]);
    const uint32_t vb_b = (uint32_t)__cvta_generic_to_shared(
        &Vsh[vrow*RS + vcol]);
    const uint32_t MT16   = (uint32_t)(16*RS*2);
    const uint32_t SUBOFF = (uint32_t)(64*RS*2);

    __syncthreads();
    uint32_t aq[2][4][4];
    #pragma unroll
    for (int mt = 0; mt < 2; mt++)
        #pragma unroll
        for (int kt = 0; kt < 4; kt++)
            ldm_x4(aq[mt][kt], qa_b + (uint32_t)mt*MT16 + (uint32_t)(kt*32));

    float o[2][8][4] = {};
    float m_run[2][2] = {{-1e30f,-1e30f},{-1e30f,-1e30f}};
    float l_run[2][2] = {{0.f,0.f},{0.f,0.f}};

    #pragma unroll 1
    for (int k0 = 0; k0 < cnt_pad; k0 += 128) {
        // Stage 128 keys of K and V (two rows' worth per thread)
        uint4 ka[8], va[8];
        #pragma unroll
        for (int i = 0; i < 8; i++) {
            const int slot = tid + 128*i;
            const int r = slot >> 3, c8 = (slot & 7) * 8;
            ka[i] = *(const uint4*)&kb[(k0 + r)*ND + c8];
            va[i] = *(const uint4*)&vb[(k0 + r)*ND + c8];
        }
        __syncthreads();
        #pragma unroll
        for (int i = 0; i < 8; i++) {
            const int slot = tid + 128*i;
            const int r = slot >> 3, c8 = (slot & 7) * 8;
            *(uint4*)&Ksh[r*RS + c8] = ka[i];
            *(uint4*)&Vsh[r*RS + c8] = va[i];
        }
        __syncthreads();

        #pragma unroll
        for (int sub = 0; sub < 2; sub++) {
            const int kb0 = k0 + sub*64;
            if (kb0 >= cnt) break;
            const uint32_t so = (uint32_t)sub * SUBOFF;

            // ---- S = Q @ K^T ----
            float s[2][8][4] = {};
            #pragma unroll
            for (int kt = 0; kt < 4; kt++) {
                const uint32_t koff = (uint32_t)(kt * 32);
                #pragma unroll
                for (int np = 0; np < 4; np++) {
                    uint32_t bbq[4];
                    ldm_x4(bbq, kb_b + so + (uint32_t)np*MT16 + koff);
                    mma_f16(s[0][2*np    ], aq[0][kt], &bbq[0]);
                    mma_f16(s[1][2*np    ], aq[1][kt], &bbq[0]);
                    mma_f16(s[0][2*np + 1], aq[0][kt], &bbq[2]);
                    mma_f16(s[1][2*np + 1], aq[1][kt], &bbq[2]);
                }
            }

            // tail-only bound mask
            if (kb0 + 64 > cnt) {
                #pragma unroll
                for (int nt = 0; nt < 8; nt++) {
                    const float mx = (kb0 + nt*8 + 2*c     < cnt) ? 0.f : -1e30f;
                    const float my = (kb0 + nt*8 + 2*c + 1 < cnt) ? 0.f : -1e30f;
                    #pragma unroll
                    for (int mt = 0; mt < 2; mt++) {
                        s[mt][nt][0] += mx; s[mt][nt][1] += my;
                        s[mt][nt][2] += mx; s[mt][nt][3] += my;
                    }
                }
            }

            // ---- online softmax ----
            #pragma unroll
            for (int mt = 0; mt < 2; mt++) {
                float alpha[2];
                #pragma unroll
                for (int rh = 0; rh < 2; rh++) {
                    float rm = -1e30f;
                    #pragma unroll
                    for (int nt = 0; nt < 8; nt++)
                        rm = fmaxf(rm, fmaxf(s[mt][nt][rh*2], s[mt][nt][rh*2+1]));
                    rm = fmaxf(rm, __shfl_xor_sync(0xffffffffu, rm, 1));
                    rm = fmaxf(rm, __shfl_xor_sync(0xffffffffu, rm, 2));
                    float mnew = fmaxf(m_run[mt][rh], rm);
                    alpha[rh] = __expf(m_run[mt][rh] - mnew);
                    m_run[mt][rh] = mnew;
                    float rs = 0.f;
                    #pragma unroll
                    for (int nt = 0; nt < 8; nt++) {
                        float p0 = __expf(s[mt][nt][rh*2]   - mnew);
                        float p1 = __expf(s[mt][nt][rh*2+1] - mnew);
                        s[mt][nt][rh*2] = p0; s[mt][nt][rh*2+1] = p1;
                        rs += p0 + p1;
                    }
                    rs += __shfl_xor_sync(0xffffffffu, rs, 1);
                    rs += __shfl_xor_sync(0xffffffffu, rs, 2);
                    l_run[mt][rh] = l_run[mt][rh]*alpha[rh] + rs;
                }
                if (!__all_sync(0xffffffffu,
                                (alpha[0] == 1.0f) && (alpha[1] == 1.0f))) {
                    #pragma unroll
                    for (int nt = 0; nt < 8; nt++) {
                        o[mt][nt][0] *= alpha[0]; o[mt][nt][1] *= alpha[0];
                        o[mt][nt][2] *= alpha[1]; o[mt][nt][3] *= alpha[1];
                    }
                }
            }

            // ---- O += P @ V (register-P) ----
            #pragma unroll
            for (int kt = 0; kt < 4; kt++) {
                uint32_t a[2][4];
                #pragma unroll
                for (int mt = 0; mt < 2; mt++) {
                    a[mt][0] = h2pack(s[mt][2*kt    ][0], s[mt][2*kt    ][1]);
                    a[mt][1] = h2pack(s[mt][2*kt    ][2], s[mt][2*kt    ][3]);
                    a[mt][2] = h2pack(s[mt][2*kt + 1][0], s[mt][2*kt + 1][1]);
                    a[mt][3] = h2pack(s[mt][2*kt + 1][2], s[mt][2*kt + 1][3]);
                }
                #pragma unroll
                for (int nt2 = 0; nt2 < 4; nt2++) {
                    uint32_t r0, r1, r2, r3;
                    const uint32_t addr = vb_b + so +
                        (uint32_t)(kt*16*RS + nt2*16) * 2;
                    asm volatile(
                        "ldmatrix.sync.aligned.m8n8.x4.trans.shared.b16 "
                        "{%0,%1,%2,%3}, [%4];"
                        : "=r"(r0), "=r"(r1), "=r"(r2), "=r"(r3) : "r"(addr));
                    uint32_t b0[2] = {r0, r1};
                    uint32_t b1[2] = {r2, r3};
                    mma_f16(o[0][nt2*2    ], a[0], b0);
                    mma_f16(o[1][nt2*2    ], a[1], b0);
                    mma_f16(o[0][nt2*2 + 1], a[0], b1);
                    mma_f16(o[1][nt2*2 + 1], a[1], b1);
                }
            }
        }
    }

    #pragma unroll
    for (int mt = 0; mt < 2; mt++) {
        const float inv0 = 1.0f / l_run[mt][0];
        const float inv1 = 1.0f / l_run[mt][1];
        const int t0 = q0 + wr + mt*16 + g;
        float* ob0 = out + (b*NT + t0    )*NC + h*ND;
        float* ob1 = out + (b*NT + t0 + 8)*NC + h*ND;
        #pragma unroll
        for (int nt = 0; nt < 8; nt++) {
            *(float2*)&ob0[nt*8 + 2*c] =
                make_float2(o[mt][nt][0]*inv0, o[mt][nt][1]*inv0);
            *(float2*)&ob1[nt*8 + 2*c] =
                make_float2(o[mt][nt][2]*inv1, o[mt][nt][3]*inv1);
        }
    }
}

// ---------------------------------------------------------------------------
extern "C" void kernel_launch(void* const* d_in, const int* in_sizes, int n_in,
                              void* d_out, int out_size)
{
    const float* x  = (const float*)d_in[0];
    const int* mask = (const int*)  d_in[1];
    const float* Wq = (const float*)d_in[2];
    const float* bq = (const float*)d_in[3];
    const float* Wk = (const float*)d_in[4];
    const float* bk = (const float*)d_in[5];
    const float* Wv = (const float*)d_in[6];
    const float* bv = (const float*)d_in[7];
    float* out = (float*)d_out;

    mask_scan<<<NB, 256>>>(mask);
    prep_all<<<4096 + 3*512, 256>>>(x, Wq, Wk, Wv);

    const int qkv_smem = 2 * STAGEB;          // 40960
    cudaFuncSetAttribute(qkv_mma,
                         cudaFuncAttributeMaxDynamicSharedMemorySize, qkv_smem);
    qkv_mma<<<dim3(NC/128, (NB*NT)/128, 3), 256, qkv_smem>>>(bq, bk, bv);

    const int attn_smem = 3 * 128 * RS * 2;   // 55296
    cudaFuncSetAttribute(attn_kernel,
                         cudaFuncAttributeMaxDynamicSharedMemorySize, attn_smem);
    attn_kernel<<<dim3(NT/128, NB*NH), 128, attn_smem>>>(out);
}